// round 13
// baseline (speedup 1.0000x reference)
#include <cuda_runtime.h>
#include <cuda_bf16.h>
#include <math.h>
#include <stdint.h>

// ---------------- constants ----------------
constexpr int T = 2048, D = 2048, H = 16, DN = 128, DR = 64, DV = 128;
constexpr int QL = 768, KL = 512, FF = 8192, E = 32, EF = 1024;
constexpr int QD = DN + DR;          // 192
constexpr int KVD = KL + DR;         // 576
constexpr int NQKV = QL + KVD;       // 1344
constexpr int KVBD = H * (DN + DV);  // 4096
constexpr int QTOT = H * QD;         // 3072
constexpr int HDV = H * DV;          // 2048

constexpr int BM = 128, BN = 128, BK = 32;
constexpr int PAD = 40;                       // smem leading dim (80B rows, 16B-aligned)
constexpr int TILE_ELEMS = 128 * PAD;         // 5120 elems = 10240 B
constexpr int GSMEM = 2 * 4 * TILE_ELEMS * 2; // 81920 B
constexpr int GPERS = 304;                    // 2 CTAs x 152 SMs

typedef __nv_bfloat16 bf16;

// ---------------- PTX helpers ----------------
__device__ __forceinline__ uint32_t smem_to_u32(const void* p) {
    uint32_t a;
    asm("{ .reg .u64 t; cvta.to.shared.u64 t, %1; cvt.u32.u64 %0, t; }" : "=r"(a) : "l"(p));
    return a;
}
__device__ __forceinline__ void cp16(uint32_t smem_dst, const void* gsrc, bool valid) {
    int sz = valid ? 16 : 0;
    asm volatile("cp.async.cg.shared.global [%0], [%1], 16, %2;\n"
                 :: "r"(smem_dst), "l"(gsrc), "r"(sz));
}
#define CP_COMMIT() asm volatile("cp.async.commit_group;\n" ::: "memory")
#define CP_WAIT0()  asm volatile("cp.async.wait_group 0;\n" ::: "memory")

__device__ __forceinline__ void ldsm_x4(uint32_t* r, uint32_t addr) {
    asm volatile("ldmatrix.sync.aligned.m8n8.x4.shared.b16 {%0,%1,%2,%3}, [%4];\n"
                 : "=r"(r[0]), "=r"(r[1]), "=r"(r[2]), "=r"(r[3]) : "r"(addr));
}
__device__ __forceinline__ void mma_bf(float* c, const uint32_t* a, uint32_t b0, uint32_t b1) {
    asm volatile(
        "mma.sync.aligned.m16n8k16.row.col.f32.bf16.bf16.f32 "
        "{%0,%1,%2,%3}, {%4,%5,%6,%7}, {%8,%9}, {%0,%1,%2,%3};\n"
        : "+f"(c[0]), "+f"(c[1]), "+f"(c[2]), "+f"(c[3])
        : "r"(a[0]), "r"(a[1]), "r"(a[2]), "r"(a[3]), "r"(b0), "r"(b1));
}

// ---------------- scratch (device globals) ----------------
__device__ float g_res[(size_t)T * D];
__device__ float g_h[(size_t)T * D];
__device__ float g_moe[(size_t)T * D];
__device__ float g_qkv[(size_t)T * NQKV];
__device__ float g_q[(size_t)T * QTOT];
__device__ float g_kvb[(size_t)T * KVBD];
__device__ float g_attno[(size_t)T * HDV];
__device__ float g_scores[(size_t)H * T * T];
__device__ float g_gu[(size_t)T * 2 * FF];
__device__ float g_mgu[(size_t)2 * T * 2 * EF];
__device__ float g_my[(size_t)2 * T * D];
__device__ float g_logits[(size_t)T * E];
// bf16 hi/lo activations
__device__ bf16 x_h[(size_t)T * D], x_l[(size_t)T * D];
__device__ bf16 qln_h[(size_t)T * QL], qln_l[(size_t)T * QL];
__device__ bf16 qq_h[(size_t)T * QTOT], qq_l[(size_t)T * QTOT];
__device__ bf16 kvcn_h[(size_t)T * KL], kvcn_l[(size_t)T * KL];
__device__ bf16 kh_h[(size_t)T * QTOT], kh_l[(size_t)T * QTOT];
__device__ bf16 vt_h[(size_t)H * DV * T], vt_l[(size_t)H * DV * T];
__device__ bf16 P_h[(size_t)H * T * T], P_l[(size_t)H * T * T];
__device__ bf16 ao_h[(size_t)T * HDV], ao_l[(size_t)T * HDV];
__device__ bf16 ff_h[(size_t)T * FF], ff_l[(size_t)T * FF];
__device__ bf16 mx_h[(size_t)2 * T * D], mx_l[(size_t)2 * T * D];
__device__ bf16 mh_h[(size_t)2 * T * EF], mh_l[(size_t)2 * T * EF];
// bf16 hi/lo weights transposed to [N][K]
__device__ bf16 wqkvT_h[(size_t)2 * NQKV * D], wqkvT_l[(size_t)2 * NQKV * D];
__device__ bf16 wqbT_h[(size_t)2 * QTOT * QL], wqbT_l[(size_t)2 * QTOT * QL];
__device__ bf16 wkvbT_h[(size_t)2 * KVBD * KL], wkvbT_l[(size_t)2 * KVBD * KL];
__device__ bf16 woT_h[(size_t)2 * D * D], woT_l[(size_t)2 * D * D];
__device__ bf16 wguT_h[(size_t)2 * 2 * FF * D], wguT_l[(size_t)2 * 2 * FF * D];
__device__ bf16 wdT_h[(size_t)2 * D * FF], wdT_l[(size_t)2 * D * FF];
__device__ bf16 rwT_h[(size_t)E * D], rwT_l[(size_t)E * D];
__device__ bf16 mwguT_h[(size_t)E * 2 * EF * D], mwguT_l[(size_t)E * 2 * EF * D];
__device__ bf16 mwdT_h[(size_t)E * D * EF], mwdT_l[(size_t)E * D * EF];
// routing
__device__ int g_expid[2 * T];
__device__ int g_slot[2 * T];
__device__ int g_rowOf[2 * T];
__device__ float g_gate[2 * T];
__device__ int g_cnt[E];
__device__ int g_off[E];

// ---------------- small helpers ----------------
__device__ __forceinline__ void wr_hl(bf16* h, bf16* l, size_t i, float x) {
    bf16 hi = __float2bfloat16(x);
    h[i] = hi;
    l[i] = __float2bfloat16(x - __bfloat162float(hi));
}
__device__ __forceinline__ float blockReduceSum(float v) {
    __shared__ float sh[32];
    int lane = threadIdx.x & 31, wid = threadIdx.x >> 5;
    #pragma unroll
    for (int o = 16; o; o >>= 1) v += __shfl_down_sync(0xffffffffu, v, o);
    if (lane == 0) sh[wid] = v;
    __syncthreads();
    int nw = (blockDim.x + 31) >> 5;
    v = (threadIdx.x < nw) ? sh[threadIdx.x] : 0.f;
    if (wid == 0) {
        #pragma unroll
        for (int o = 16; o; o >>= 1) v += __shfl_down_sync(0xffffffffu, v, o);
        if (lane == 0) sh[0] = v;
    }
    __syncthreads();
    float r = sh[0];
    __syncthreads();
    return r;
}
__device__ __forceinline__ float blockReduceMax(float v) {
    __shared__ float sh[32];
    int lane = threadIdx.x & 31, wid = threadIdx.x >> 5;
    #pragma unroll
    for (int o = 16; o; o >>= 1) v = fmaxf(v, __shfl_down_sync(0xffffffffu, v, o));
    if (lane == 0) sh[wid] = v;
    __syncthreads();
    int nw = (blockDim.x + 31) >> 5;
    v = (threadIdx.x < nw) ? sh[threadIdx.x] : -1e30f;
    if (wid == 0) {
        #pragma unroll
        for (int o = 16; o; o >>= 1) v = fmaxf(v, __shfl_down_sync(0xffffffffu, v, o));
        if (lane == 0) sh[0] = v;
    }
    __syncthreads();
    float r = sh[0];
    __syncthreads();
    return r;
}

// ---- shared GEMM inner body (macro-free via inline fn on raw params) ----
struct GemmCtx {
    uint32_t smb, aoff, boff;
    int tid, lane, wid, warp_m, warp_n, srow0, sch, rrow, rcol;
};
__device__ __forceinline__ GemmCtx make_ctx(const void* sm) {
    GemmCtx c;
    c.smb = smem_to_u32(sm);
    c.tid = threadIdx.x;
    c.lane = c.tid & 31;
    c.wid = c.tid >> 5;
    c.warp_m = c.wid >> 2;
    c.warp_n = c.wid & 3;
    c.srow0 = c.tid >> 2;
    c.sch = c.tid & 3;
    c.aoff = ((uint32_t)((c.lane & 15) * PAD) + ((c.lane >> 4) << 3)) * 2;
    c.boff = ((uint32_t)(((c.lane & 7) + ((c.lane >> 1) & 8)) * PAD) + (c.lane & 8)) * 2;
    c.rrow = c.lane >> 2;
    c.rcol = (c.lane & 3) * 2;
    return c;
}
__device__ __forceinline__ void stage_chunk(const GemmCtx& g, const bf16* Ah, const bf16* Al,
                                            const bf16* Bh, const bf16* Bl,
                                            int lda, int ldb, int bm, int bn,
                                            int rcA, int rcB, int k0, int buf) {
    uint32_t base = g.smb + (uint32_t)buf * 4 * TILE_ELEMS * 2;
    #pragma unroll
    for (int it = 0; it < 2; it++) {
        int row = g.srow0 + it * 64;
        uint32_t soff = (uint32_t)(row * PAD + g.sch * 8) * 2;
        bool vA = row < rcA;
        bool vB = row < rcB;
        long ga = (long)(bm + (vA ? row : 0)) * lda + k0 + g.sch * 8;
        long gb = (long)(bn + (vB ? row : 0)) * ldb + k0 + g.sch * 8;
        cp16(base + 0 * TILE_ELEMS * 2 + soff, Ah + ga, vA);
        cp16(base + 1 * TILE_ELEMS * 2 + soff, Al + ga, vA);
        cp16(base + 2 * TILE_ELEMS * 2 + soff, Bh + gb, vB);
        cp16(base + 3 * TILE_ELEMS * 2 + soff, Bl + gb, vB);
    }
}
__device__ __forceinline__ void compute_chunk(const GemmCtx& g, int buf, float acc[4][4][4]) {
    uint32_t base = g.smb + (uint32_t)buf * 4 * TILE_ELEMS * 2;
    uint32_t tAh = base, tAl = base + TILE_ELEMS * 2;
    uint32_t tBh = base + 2 * TILE_ELEMS * 2, tBl = base + 3 * TILE_ELEMS * 2;
    #pragma unroll
    for (int ks = 0; ks < 2; ks++) {
        uint32_t bh[2][4], bl[2][4];
        #pragma unroll
        for (int nf2 = 0; nf2 < 2; nf2++) {
            uint32_t o = (uint32_t)((g.warp_n * 32 + nf2 * 16) * PAD) * 2 + (uint32_t)(ks * 32) + g.boff;
            ldsm_x4(bh[nf2], tBh + o);
            ldsm_x4(bl[nf2], tBl + o);
        }
        #pragma unroll
        for (int mf = 0; mf < 4; mf++) {
            uint32_t ah[4], al[4];
            uint32_t o = (uint32_t)((g.warp_m * 64 + mf * 16) * PAD) * 2 + (uint32_t)(ks * 32) + g.aoff;
            ldsm_x4(ah, tAh + o);
            ldsm_x4(al, tAl + o);
            #pragma unroll
            for (int nf = 0; nf < 4; nf++) {
                int n2 = nf >> 1, pb = (nf & 1) * 2;
                float* cc = acc[mf][nf];
                mma_bf(cc, ah, bh[n2][pb], bh[n2][pb + 1]);
                mma_bf(cc, ah, bl[n2][pb], bl[n2][pb + 1]);
                mma_bf(cc, al, bh[n2][pb], bh[n2][pb + 1]);
            }
        }
    }
}

// =======================================================================
// bf16x3 GEMM (2-stage, 2 CTA/SM) — scores (cskip)
// =======================================================================
__global__ void __launch_bounds__(256, 2)
bgemm_k(const bf16* __restrict__ Ah, const bf16* __restrict__ Al,
        const bf16* __restrict__ Bh, const bf16* __restrict__ Bl,
        float* __restrict__ C, int M, int N, int K,
        int lda, int ldb, int ldc, long sA, long sB, long sC, int cskip) {
    int z = blockIdx.z;
    Ah += (long)z * sA; Al += (long)z * sA;
    Bh += (long)z * sB; Bl += (long)z * sB;
    C += (long)z * sC;
    int bid = blockIdx.y * gridDim.x + blockIdx.x;
    int mt = gridDim.y;
    int bm = (bid % mt) * BM;
    int bn = (bid / mt) * BN;
    if (bm >= M) return;
    if (cskip && bn > bm + 127) return;
    int nch = K / BK;

    extern __shared__ bf16 sm[];
    GemmCtx g = make_ctx(sm);
    float acc[4][4][4];
    #pragma unroll
    for (int i = 0; i < 4; i++)
        #pragma unroll
        for (int j = 0; j < 4; j++)
            #pragma unroll
            for (int q = 0; q < 4; q++) acc[i][j][q] = 0.f;

    int rcA = (M - bm) < BM ? (M - bm) : BM;
    int rcB = (N - bn) < BN ? (N - bn) : BN;

    stage_chunk(g, Ah, Al, Bh, Bl, lda, ldb, bm, bn, rcA, rcB, 0, 0);
    CP_COMMIT();
    for (int c = 0; c < nch; c++) {
        CP_WAIT0();
        __syncthreads();
        if (c + 1 < nch) {
            stage_chunk(g, Ah, Al, Bh, Bl, lda, ldb, bm, bn, rcA, rcB, (c + 1) * BK, (c + 1) & 1);
            CP_COMMIT();
        }
        compute_chunk(g, c & 1, acc);
        __syncthreads();
    }

    #pragma unroll
    for (int mf = 0; mf < 4; mf++)
        #pragma unroll
        for (int nf = 0; nf < 4; nf++) {
            int m0 = bm + g.warp_m * 64 + mf * 16 + g.rrow;
            int n0 = bn + g.warp_n * 32 + nf * 8 + g.rcol;
            float* cc = acc[mf][nf];
            #pragma unroll
            for (int half = 0; half < 2; half++) {
                int mm = m0 + half * 8;
                if (mm >= M) continue;
                #pragma unroll
                for (int jj = 0; jj < 2; jj++) {
                    int nn = n0 + jj;
                    if (nn < N) C[(long)mm * ldc + nn] = cc[half * 2 + jj];
                }
            }
        }
}

// =======================================================================
// Balanced-range split GEMM (plain GEMMs)
// =======================================================================
__global__ void __launch_bounds__(256, 2)
sgemm_split_k(const bf16* __restrict__ Ah, const bf16* __restrict__ Al,
              const bf16* __restrict__ Bh, const bf16* __restrict__ Bl,
              float* __restrict__ C, int M, int N, int K,
              int lda, int ldb, int ldc, int mt, int nt) {
    int nch = K / BK;
    long U = (long)mt * nt * nch;
    int G = gridDim.x;
    long u0 = (long)blockIdx.x * U / G;
    long u1 = ((long)blockIdx.x + 1) * U / G;

    extern __shared__ bf16 sm[];
    GemmCtx g = make_ctx(sm);

    while (u0 < u1) {
        int tile = (int)(u0 / nch);
        int c0 = (int)(u0 % nch);
        long rem = u1 - (long)tile * nch;
        int c1 = rem < (long)nch ? (int)rem : nch;

        int bm = (tile % mt) * BM;
        int bn = (tile / mt) * BN;
        int rcA = (M - bm) < BM ? (M - bm) : BM;
        int rcB = (N - bn) < BN ? (N - bn) : BN;
        bool full = (c0 == 0) && (c1 == nch);

        float acc[4][4][4];
        #pragma unroll
        for (int i = 0; i < 4; i++)
            #pragma unroll
            for (int j = 0; j < 4; j++)
                #pragma unroll
                for (int q = 0; q < 4; q++) acc[i][j][q] = 0.f;

        stage_chunk(g, Ah, Al, Bh, Bl, lda, ldb, bm, bn, rcA, rcB, c0 * BK, 0);
        CP_COMMIT();
        for (int c = c0; c < c1; c++) {
            CP_WAIT0();
            __syncthreads();
            if (c + 1 < c1) {
                stage_chunk(g, Ah, Al, Bh, Bl, lda, ldb, bm, bn, rcA, rcB, (c + 1) * BK,
                            (c - c0 + 1) & 1);
                CP_COMMIT();
            }
            compute_chunk(g, (c - c0) & 1, acc);
            __syncthreads();
        }

        #pragma unroll
        for (int mf = 0; mf < 4; mf++)
            #pragma unroll
            for (int nf = 0; nf < 4; nf++) {
                int m0 = bm + g.warp_m * 64 + mf * 16 + g.rrow;
                int n0 = bn + g.warp_n * 32 + nf * 8 + g.rcol;
                float* cc = acc[mf][nf];
                #pragma unroll
                for (int half = 0; half < 2; half++) {
                    int mm = m0 + half * 8;
                    if (mm >= M) continue;
                    #pragma unroll
                    for (int jj = 0; jj < 2; jj++) {
                        int nn = n0 + jj;
                        if (nn >= N) continue;
                        float v = cc[half * 2 + jj];
                        if (full) C[(long)mm * ldc + nn] = v;
                        else atomicAdd(&C[(long)mm * ldc + nn], v);
                    }
                }
            }
        __syncthreads();
        u0 = (long)tile * nch + c1;
    }
}

// =======================================================================
// Balanced MoE segmented GEMM: per-expert row segments, unit-balanced.
// =======================================================================
__global__ void __launch_bounds__(256, 2)
mgemm_split_k(const bf16* __restrict__ Ah, const bf16* __restrict__ Al,
              const bf16* __restrict__ Bh, const bf16* __restrict__ Bl, long sB,
              float* __restrict__ C, int N, int K, int lda, int ldc) {
    int nch = K / BK;
    int ntN = (N + BN - 1) / BN;
    long U = 0;
    #pragma unroll
    for (int e = 0; e < E; e++)
        U += (long)((g_cnt[e] + 127) >> 7) * ntN * nch;
    int G = gridDim.x;
    long u0 = (long)blockIdx.x * U / G;
    long u1 = ((long)blockIdx.x + 1) * U / G;

    extern __shared__ bf16 sm[];
    GemmCtx g = make_ctx(sm);

    while (u0 < u1) {
        // locate expert
        long pre = 0;
        int e = 0, M = 0;
        for (; e < E; e++) {
            M = g_cnt[e];
            long ue = (long)((M + 127) >> 7) * ntN * nch;
            if (u0 < pre + ue) break;
            pre += ue;
        }
        int rs = g_off[e];
        long lu = u0 - pre;
        int tile = (int)(lu / nch);
        int c0 = (int)(lu % nch);
        long luend = u1 - pre;
        long tend = (long)(tile + 1) * nch;
        if (luend > tend) luend = tend;
        int c1 = (int)(luend - (long)tile * nch);
        bool full = (c0 == 0) && (c1 == nch);

        int mtiles = (M + 127) >> 7;
        int bm = (tile % mtiles) * BM;
        int bn = (tile / mtiles) * BN;
        int rcA = (M - bm) < BM ? (M - bm) : BM;
        int rcB = (N - bn) < BN ? (N - bn) : BN;

        const bf16* eAh = Ah + (long)rs * lda;
        const bf16* eAl = Al + (long)rs * lda;
        const bf16* eBh = Bh + (long)e * sB;
        const bf16* eBl = Bl + (long)e * sB;
        float* eC = C + (long)rs * ldc;

        float acc[4][4][4];
        #pragma unroll
        for (int i = 0; i < 4; i++)
            #pragma unroll
            for (int j = 0; j < 4; j++)
                #pragma unroll
                for (int q = 0; q < 4; q++) acc[i][j][q] = 0.f;

        stage_chunk(g, eAh, eAl, eBh, eBl, lda, K, bm, bn, rcA, rcB, c0 * BK, 0);
        CP_COMMIT();
        for (int c = c0; c < c1; c++) {
            CP_WAIT0();
            __syncthreads();
            if (c + 1 < c1) {
                stage_chunk(g, eAh, eAl, eBh, eBl, lda, K, bm, bn, rcA, rcB, (c + 1) * BK,
                            (c - c0 + 1) & 1);
                CP_COMMIT();
            }
            compute_chunk(g, (c - c0) & 1, acc);
            __syncthreads();
        }

        #pragma unroll
        for (int mf = 0; mf < 4; mf++)
            #pragma unroll
            for (int nf = 0; nf < 4; nf++) {
                int m0 = bm + g.warp_m * 64 + mf * 16 + g.rrow;
                int n0 = bn + g.warp_n * 32 + nf * 8 + g.rcol;
                float* cc = acc[mf][nf];
                #pragma unroll
                for (int half = 0; half < 2; half++) {
                    int mm = m0 + half * 8;
                    if (mm >= M) continue;
                    #pragma unroll
                    for (int jj = 0; jj < 2; jj++) {
                        int nn = n0 + jj;
                        if (nn >= N) continue;
                        float v = cc[half * 2 + jj];
                        if (full) eC[(long)mm * ldc + nn] = v;
                        else atomicAdd(&eC[(long)mm * ldc + nn], v);
                    }
                }
            }
        __syncthreads();
        u0 = pre + (long)tile * nch + c1;
    }
}

// =======================================================================
// Balanced AV GEMM (R12): chunks(m)=4(m+1); U=8704
// =======================================================================
__global__ void __launch_bounds__(256, 2)
av_split_k(const bf16* __restrict__ Ph, const bf16* __restrict__ Pl,
           const bf16* __restrict__ Vh, const bf16* __restrict__ Vl,
           float* __restrict__ C) {
    const long U = 8704;
    int G = gridDim.x;
    long u0 = (long)blockIdx.x * U / G;
    long u1 = ((long)blockIdx.x + 1) * U / G;

    extern __shared__ bf16 sm[];
    GemmCtx g = make_ctx(sm);

    while (u0 < u1) {
        int h = (int)(u0 / 544);
        int rem = (int)(u0 - (long)h * 544);
        int m = 0;
        while (rem >= 2 * (m + 1) * (m + 2)) m++;
        int c0 = rem - 2 * m * (m + 1);
        int nchT = 4 * (m + 1);
        long avail = u1 - u0;
        int c1 = (c0 + avail < (long)nchT) ? (int)(c0 + avail) : nchT;
        bool full = (c0 == 0) && (c1 == nchT);
        int bm = m * 128;

        const bf16* Ah = Ph + (size_t)h * T * T;
        const bf16* Al = Pl + (size_t)h * T * T;
        const bf16* Bh = Vh + (size_t)h * 128 * T;
        const bf16* Bl = Vl + (size_t)h * 128 * T;

        float acc[4][4][4];
        #pragma unroll
        for (int i = 0; i < 4; i++)
            #pragma unroll
            for (int j = 0; j < 4; j++)
                #pragma unroll
                for (int q = 0; q < 4; q++) acc[i][j][q] = 0.f;

        stage_chunk(g, Ah, Al, Bh, Bl, T, T, bm, 0, 128, 128, c0 * BK, 0);
        CP_COMMIT();
        for (int c = c0; c < c1; c++) {
            CP_WAIT0();
            __syncthreads();
            if (c + 1 < c1) {
                stage_chunk(g, Ah, Al, Bh, Bl, T, T, bm, 0, 128, 128, (c + 1) * BK,
                            (c - c0 + 1) & 1);
                CP_COMMIT();
            }
            compute_chunk(g, (c - c0) & 1, acc);
            __syncthreads();
        }

        #pragma unroll
        for (int mf = 0; mf < 4; mf++)
            #pragma unroll
            for (int nf = 0; nf < 4; nf++) {
                int m0 = bm + g.warp_m * 64 + mf * 16 + g.rrow;
                int n0 = h * 128 + g.warp_n * 32 + nf * 8 + g.rcol;
                float* cc = acc[mf][nf];
                #pragma unroll
                for (int half = 0; half < 2; half++) {
                    int mm = m0 + half * 8;
                    #pragma unroll
                    for (int jj = 0; jj < 2; jj++) {
                        int nn = n0 + jj;
                        float v = cc[half * 2 + jj];
                        if (full) C[(long)mm * HDV + nn] = v;
                        else atomicAdd(&C[(long)mm * HDV + nn], v);
                    }
                }
            }
        __syncthreads();
        u0 += c1 - c0;
    }
}

// ---------------- weight transpose + bf16 split ----------------
__global__ void wtrans_k(const float* __restrict__ W, bf16* __restrict__ Oh,
                         bf16* __restrict__ Ol, int K, int N, long zso) {
    long z = blockIdx.z;
    W += z * (long)K * N;
    Oh += z * zso;
    Ol += z * zso;
    __shared__ float tile[32][33];
    int n0 = blockIdx.x * 32, k0 = blockIdx.y * 32;
    int tx = threadIdx.x, ty = threadIdx.y;
    #pragma unroll
    for (int i = 0; i < 4; i++)
        tile[ty + i * 8][tx] = W[(long)(k0 + ty + i * 8) * N + n0 + tx];
    __syncthreads();
    #pragma unroll
    for (int i = 0; i < 4; i++) {
        int n = n0 + ty + i * 8, k = k0 + tx;
        wr_hl(Oh, Ol, (size_t)n * K + k, tile[tx][ty + i * 8]);
    }
}

// ---------------- elementwise / norm ----------------
__global__ void rms_hl_k(const float* __restrict__ x, const float* __restrict__ w,
                         bf16* __restrict__ oh, bf16* __restrict__ ol,
                         int cols, int ldx, int ldo) {
    long row = blockIdx.x;
    const float* xr = x + row * ldx;
    float s = 0.f;
    for (int i = threadIdx.x; i < cols; i += blockDim.x) { float v = xr[i]; s += v * v; }
    s = blockReduceSum(s);
    float sc = rsqrtf(s / cols + 1e-6f);
    for (int i = threadIdx.x; i < cols; i += blockDim.x)
        wr_hl(oh, ol, row * ldo + i, xr[i] * sc * w[i]);
}

__global__ void addnorm_hl_k(const float* __restrict__ a, const float* __restrict__ b,
                             const float* __restrict__ w, float* __restrict__ res,
                             bf16* __restrict__ oh, bf16* __restrict__ ol) {
    long row = blockIdx.x;
    const float* ar = a + row * D;
    const float* br = b + row * D;
    float* rr = res + row * D;
    float s = 0.f;
    for (int i = threadIdx.x; i < D; i += blockDim.x) {
        float v = ar[i] + br[i];
        rr[i] = v;
        s += v * v;
    }
    s = blockReduceSum(s);
    float sc = rsqrtf(s / D + 1e-6f);
    for (int i = threadIdx.x; i < D; i += blockDim.x)
        wr_hl(oh, ol, row * D + i, rr[i] * sc * w[i]);
}

__global__ void cvt_hl_k(const float* __restrict__ x, bf16* __restrict__ oh,
                         bf16* __restrict__ ol, long n) {
    long i = (long)blockIdx.x * blockDim.x + threadIdx.x;
    if (i < n) wr_hl(oh, ol, i, x[i]);
}

__global__ void rope_cvt_q_k(const float* __restrict__ q, const int* __restrict__ pos) {
    int t = blockIdx.x;
    float fp = (float)pos[t];
    for (int e = threadIdx.x; e < QTOT; e += blockDim.x) {
        int h = e / QD, d = e % QD;
        const float* qr = q + (size_t)t * QTOT + h * QD;
        float v;
        if (d < DN) {
            v = qr[d];
        } else {
            int j = d - DN;
            int i = j & 31;
            float inv = 1.f / powf(10000.f, (float)i * (2.f / 64.f));
            float sn, cs;
            sincosf(fp * inv, &sn, &cs);
            float x1 = qr[DN + i], x2 = qr[DN + i + 32];
            v = (j < 32) ? (x1 * cs - x2 * sn) : (x2 * cs + x1 * sn);
        }
        wr_hl(qq_h, qq_l, (size_t)t * QTOT + e, v);
    }
}

__global__ void build_kh_k(const int* __restrict__ pos) {
    int t = blockIdx.x;
    __shared__ float kr[64];
    int tid = threadIdx.x;
    if (tid < 32) {
        int i = tid;
        float inv = 1.f / powf(10000.f, (float)i * (2.f / 64.f));
        float sn, cs;
        sincosf((float)pos[t] * inv, &sn, &cs);
        const float* kb = g_qkv + (size_t)t * NQKV + QL + KL;
        float x1 = kb[i], x2 = kb[i + 32];
        kr[i] = x1 * cs - x2 * sn;
        kr[i + 32] = x2 * cs + x1 * sn;
    }
    __syncthreads();
    for (int e = tid; e < QTOT; e += blockDim.x) {
        int h = e / QD, d = e % QD;
        float v = (d < DN) ? g_kvb[(size_t)t * KVBD + h * (DN + DV) + d] : kr[d - DN];
        wr_hl(kh_h, kh_l, (size_t)t * QTOT + e, v);
    }
}

__global__ void build_vt_k() {
    int t = blockIdx.x;
    const float* row = g_kvb + (size_t)t * KVBD;
    for (int e = threadIdx.x; e < H * DV; e += blockDim.x) {
        int h = e >> 7, d = e & 127;
        wr_hl(vt_h, vt_l, (size_t)e * T + t, row[h * (DN + DV) + DN + d]);
    }
}

__global__ void softmaxP_k() {
    int t = blockIdx.x, h = blockIdx.y;
    const float* row = g_scores + ((size_t)h * T + t) * (size_t)T;
    size_t po = ((size_t)h * T + t) * (size_t)T;
    int n = t + 1;
    const float alpha = 0.07216878364870322f;
    float m = -1e30f;
    for (int i = threadIdx.x; i < n; i += blockDim.x) m = fmaxf(m, row[i] * alpha);
    m = blockReduceMax(m);
    float s = 0.f;
    for (int i = threadIdx.x; i < n; i += blockDim.x) s += expf(row[i] * alpha - m);
    s = blockReduceSum(s);
    float inv = 1.f / s;
    for (int i = threadIdx.x; i < n; i += blockDim.x)
        wr_hl(P_h, P_l, po + i, expf(row[i] * alpha - m) * inv);
    int fend = ((t >> 7) + 1) << 7;
    bf16 zz = __float2bfloat16(0.f);
    for (int i = n + threadIdx.x; i < fend; i += blockDim.x) { P_h[po + i] = zz; P_l[po + i] = zz; }
}

__global__ void silumul_mlp_k() {
    long idx = (long)blockIdx.x * blockDim.x + threadIdx.x;
    if (idx >= (long)T * FF) return;
    long r = idx / FF;
    int c = (int)(idx % FF);
    float g = g_gu[r * (2 * FF) + c], u = g_gu[r * (2 * FF) + FF + c];
    wr_hl(ff_h, ff_l, idx, g / (1.f + expf(-g)) * u);
}

__global__ void silumul2_k() {
    long idx = (long)blockIdx.x * blockDim.x + threadIdx.x;
    if (idx >= (long)2 * T * EF) return;
    long r = idx / EF;
    int c = (int)(idx % EF);
    float g = g_mgu[r * (2 * EF) + c], u = g_mgu[r * (2 * EF) + EF + c];
    wr_hl(mh_h, mh_l, idx, g / (1.f + expf(-g)) * u);
}

// ---------------- MoE routing ----------------
__global__ void top2_k() {
    int t = blockIdx.x * blockDim.x + threadIdx.x;
    if (t >= T) return;
    const float* l = g_logits + (size_t)t * E;
    int i0 = 0;
    float v0 = l[0];
    for (int i = 1; i < E; i++)
        if (l[i] > v0) { v0 = l[i]; i0 = i; }
    int i1 = -1;
    float v1 = -1e30f;
    for (int i = 0; i < E; i++)
        if (i != i0 && l[i] > v1) { v1 = l[i]; i1 = i; }
    float e = expf(v1 - v0);
    g_expid[2 * t] = i0;
    g_expid[2 * t + 1] = i1;
    g_gate[2 * t] = 1.f / (1.f + e);
    g_gate[2 * t + 1] = e / (1.f + e);
}
__global__ void zero_cnt_k() { if (threadIdx.x < E) g_cnt[threadIdx.x] = 0; }
__global__ void count_k() {
    int p = blockIdx.x * blockDim.x + threadIdx.x;
    if (p < 2 * T) g_slot[p] = atomicAdd(&g_cnt[g_expid[p]], 1);
}
__global__ void scan_k() {
    if (threadIdx.x == 0) {
        int o = 0;
        for (int e = 0; e < E; e++) { g_off[e] = o; o += g_cnt[e]; }
    }
}
__global__ void gather_k() {
    int p = blockIdx.x;
    int row = g_off[g_expid[p]] + g_slot[p];
    if (threadIdx.x == 0) g_rowOf[p] = row;
    size_t src = (size_t)(p >> 1) * D, dst = (size_t)row * D;
    for (int i = threadIdx.x; i < D; i += blockDim.x) {
        mx_h[dst + i] = x_h[src + i];
        mx_l[dst + i] = x_l[src + i];
    }
}
__global__ void moecomb_k() {
    long idx = (long)blockIdx.x * blockDim.x + threadIdx.x;
    if (idx >= (long)T * D) return;
    long t = idx / D;
    int d = (int)(idx % D);
    g_moe[idx] = g_gate[2 * t] * g_my[(size_t)g_rowOf[2 * t] * D + d] +
                 g_gate[2 * t + 1] * g_my[(size_t)g_rowOf[2 * t + 1] * D + d];
}
__global__ void add_k(const float* __restrict__ a, const float* __restrict__ b,
                      float* __restrict__ o, long n) {
    long idx = (long)blockIdx.x * blockDim.x + threadIdx.x;
    if (idx < n) o[idx] = a[idx] + b[idx];
}

// ---------------- host side ----------------
static void bgemm_f(const bf16* Ah, const bf16* Al, const bf16* Bh, const bf16* Bl,
                    float* C, int M, int N, int K, int lda, int ldb, int ldc,
                    long sA, long sB, long sC, int batch, int cskip) {
    dim3 g((N + BN - 1) / BN, (M + BM - 1) / BM, batch);
    bgemm_k<<<g, 256, GSMEM>>>(Ah, Al, Bh, Bl, C, M, N, K, lda, ldb, ldc, sA, sB, sC, cskip);
}
static void sgemm_split(const bf16* Ah, const bf16* Al, const bf16* Bh, const bf16* Bl,
                        float* C, int M, int N, int K, int lda, int ldb, int ldc) {
    cudaMemsetAsync(C, 0, (size_t)M * ldc * sizeof(float));
    int mt = (M + BM - 1) / BM, nt = (N + BN - 1) / BN;
    long U = (long)mt * nt * (K / BK);
    int G = U < GPERS ? (int)U : GPERS;
    sgemm_split_k<<<G, 256, GSMEM>>>(Ah, Al, Bh, Bl, C, M, N, K, lda, ldb, ldc, mt, nt);
}
static void mgemm_split(const bf16* Ah, const bf16* Al, const bf16* Bh, const bf16* Bl,
                        long sB, float* C, int N, int K, int lda, int ldc, size_t csize) {
    cudaMemsetAsync(C, 0, csize);
    mgemm_split_k<<<GPERS, 256, GSMEM>>>(Ah, Al, Bh, Bl, sB, C, N, K, lda, ldc);
}

extern "C" void kernel_launch(void* const* d_in, const int* in_sizes, int n_in,
                              void* d_out, int out_size) {
    const float* hidden = (const float*)d_in[0];
    const int* pos = (const int*)d_in[1];
    const float* ln_in = (const float*)d_in[2];
    const float* ln_post = (const float*)d_in[3];
    const float* wqa = (const float*)d_in[4];
    const float* qnorm = (const float*)d_in[5];
    const float* wqb = (const float*)d_in[6];
    const float* wkva = (const float*)d_in[7];
    const float* kvnorm = (const float*)d_in[8];
    const float* wkvb = (const float*)d_in[9];
    const float* wo = (const float*)d_in[10];
    const float* wgu = (const float*)d_in[11];
    const float* wd = (const float*)d_in[12];
    const float* rw = (const float*)d_in[13];
    const float* mwg = (const float*)d_in[14];
    const float* mwu = (const float*)d_in[15];
    const float* mwd = (const float*)d_in[16];
    float* out = (float*)d_out;

    cudaFuncSetAttribute(bgemm_k, cudaFuncAttributeMaxDynamicSharedMemorySize, GSMEM);
    cudaFuncSetAttribute(sgemm_split_k, cudaFuncAttributeMaxDynamicSharedMemorySize, GSMEM);
    cudaFuncSetAttribute(mgemm_split_k, cudaFuncAttributeMaxDynamicSharedMemorySize, GSMEM);
    cudaFuncSetAttribute(av_split_k, cudaFuncAttributeMaxDynamicSharedMemorySize, GSMEM);

    void* p;
#define SYMF(name) cudaGetSymbolAddress(&p, name); float* p_##name = (float*)p;
#define SYMB(name) cudaGetSymbolAddress(&p, name); bf16* p_##name = (bf16*)p;
#define SYMI(name) cudaGetSymbolAddress(&p, name); int* p_##name = (int*)p;
    SYMF(g_res) SYMF(g_h) SYMF(g_moe) SYMF(g_qkv) SYMF(g_q) SYMF(g_kvb) SYMF(g_attno)
    SYMF(g_scores) SYMF(g_gu) SYMF(g_mgu) SYMF(g_my) SYMF(g_logits)
    SYMB(x_h) SYMB(x_l) SYMB(qln_h) SYMB(qln_l) SYMB(qq_h) SYMB(qq_l)
    SYMB(kvcn_h) SYMB(kvcn_l) SYMB(kh_h) SYMB(kh_l) SYMB(vt_h) SYMB(vt_l)
    SYMB(P_h) SYMB(P_l) SYMB(ao_h) SYMB(ao_l) SYMB(ff_h) SYMB(ff_l)
    SYMB(mx_h) SYMB(mx_l) SYMB(mh_h) SYMB(mh_l)
    SYMB(wqkvT_h) SYMB(wqkvT_l) SYMB(wqbT_h) SYMB(wqbT_l)
    SYMB(wkvbT_h) SYMB(wkvbT_l) SYMB(woT_h) SYMB(woT_l) SYMB(wguT_h) SYMB(wguT_l)
    SYMB(wdT_h) SYMB(wdT_l) SYMB(rwT_h) SYMB(rwT_l)
    SYMB(mwguT_h) SYMB(mwguT_l) SYMB(mwdT_h) SYMB(mwdT_l)
    SYMI(g_cnt) SYMI(g_off)
#undef SYMF
#undef SYMB
#undef SYMI

    dim3 tb(32, 8);
    long zqkv = (long)NQKV * D;

    // kernels: rms(0), wtrans(1), wtrans(2), sgemm_split(3) <- ncu target
    rms_hl_k<<<T, 256>>>(hidden, ln_in, p_x_h, p_x_l, D, D, D);
    wtrans_k<<<dim3(QL / 32, D / 32, 2), tb>>>(wqa, p_wqkvT_h, p_wqkvT_l, D, QL, zqkv);
    wtrans_k<<<dim3(KVD / 32, D / 32, 2), tb>>>(wkva, p_wqkvT_h + (size_t)QL * D,
                                                p_wqkvT_l + (size_t)QL * D, D, KVD, zqkv);
    sgemm_split(p_x_h, p_x_l, p_wqkvT_h, p_wqkvT_l, p_g_qkv, T, NQKV, D, D, D, NQKV);
    // remaining weight preps
    wtrans_k<<<dim3(QTOT / 32, QL / 32, 2), tb>>>(wqb, p_wqbT_h, p_wqbT_l, QL, QTOT,
                                                  (long)QTOT * QL);
    wtrans_k<<<dim3(KVBD / 32, KL / 32, 2), tb>>>(wkvb, p_wkvbT_h, p_wkvbT_l, KL, KVBD,
                                                  (long)KVBD * KL);
    wtrans_k<<<dim3(D / 32, D / 32, 2), tb>>>(wo, p_woT_h, p_woT_l, HDV, D, (long)D * D);
    wtrans_k<<<dim3(2 * FF / 32, D / 32, 2), tb>>>(wgu, p_wguT_h, p_wguT_l, D, 2 * FF,
                                                   (long)2 * FF * D);
    wtrans_k<<<dim3(D / 32, FF / 32, 2), tb>>>(wd, p_wdT_h, p_wdT_l, FF, D, (long)D * FF);
    wtrans_k<<<dim3(E / 32, D / 32, 1), tb>>>(rw, p_rwT_h, p_rwT_l, D, E, 0);
    wtrans_k<<<dim3(EF / 32, D / 32, E), tb>>>(mwg, p_mwguT_h, p_mwguT_l, D, EF,
                                               (long)2 * EF * D);
    wtrans_k<<<dim3(EF / 32, D / 32, E), tb>>>(mwu, p_mwguT_h + (size_t)EF * D,
                                               p_mwguT_l + (size_t)EF * D, D, EF,
                                               (long)2 * EF * D);
    wtrans_k<<<dim3(D / 32, EF / 32, E), tb>>>(mwd, p_mwdT_h, p_mwdT_l, EF, D, (long)D * EF);

    auto mla = [&](int l, float* outbuf, bool qkv_done) {
        if (!qkv_done)
            sgemm_split(p_x_h, p_x_l, p_wqkvT_h + (size_t)l * zqkv, p_wqkvT_l + (size_t)l * zqkv,
                        p_g_qkv, T, NQKV, D, D, D, NQKV);
        rms_hl_k<<<T, 256>>>(p_g_qkv, qnorm + (size_t)l * QL, p_qln_h, p_qln_l, QL, NQKV, QL);
        sgemm_split(p_qln_h, p_qln_l, p_wqbT_h + (size_t)l * QTOT * QL,
                    p_wqbT_l + (size_t)l * QTOT * QL, p_g_q, T, QTOT, QL, QL, QL, QTOT);
        rms_hl_k<<<T, 256>>>(p_g_qkv + QL, kvnorm + (size_t)l * KL, p_kvcn_h, p_kvcn_l,
                             KL, NQKV, KL);
        sgemm_split(p_kvcn_h, p_kvcn_l, p_wkvbT_h + (size_t)l * KVBD * KL,
                    p_wkvbT_l + (size_t)l * KVBD * KL, p_g_kvb, T, KVBD, KL, KL, KL, KVBD);
        rope_cvt_q_k<<<T, 256>>>(p_g_q, pos);
        build_kh_k<<<T, 256>>>(pos);
        build_vt_k<<<T, 256>>>();
        bgemm_f(p_qq_h, p_qq_l, p_kh_h, p_kh_l, p_g_scores, T, T, QD,
                QTOT, QTOT, T, QD, QD, (long)T * T, H, 1);
        softmaxP_k<<<dim3(T, H), 256>>>();
        cudaMemsetAsync(p_g_attno, 0, (size_t)T * HDV * sizeof(float));
        av_split_k<<<GPERS, 256, GSMEM>>>(p_P_h, p_P_l, p_vt_h, p_vt_l, p_g_attno);
        cvt_hl_k<<<(int)(((long)T * HDV + 255) / 256), 256>>>(p_g_attno, p_ao_h, p_ao_l,
                                                              (long)T * HDV);
        sgemm_split(p_ao_h, p_ao_l, p_woT_h + (size_t)l * D * D, p_woT_l + (size_t)l * D * D,
                    outbuf, T, D, HDV, HDV, HDV, D);
    };

    auto mlp = [&](int l, float* outbuf) {
        sgemm_split(p_x_h, p_x_l, p_wguT_h + (size_t)l * 2 * FF * D,
                    p_wguT_l + (size_t)l * 2 * FF * D, p_g_gu, T, 2 * FF, D, D, D, 2 * FF);
        silumul_mlp_k<<<(int)(((long)T * FF + 255) / 256), 256>>>();
        sgemm_split(p_ff_h, p_ff_l, p_wdT_h + (size_t)l * D * FF, p_wdT_l + (size_t)l * D * FF,
                    outbuf, T, D, FF, FF, FF, D);
    };

    // ================= forward =================
    mla(0, p_g_h, true);
    addnorm_hl_k<<<T, 256>>>(p_g_h, hidden, ln_post, p_g_res, p_x_h, p_x_l);

    // ---- MoE ----
    sgemm_split(p_x_h, p_x_l, p_rwT_h, p_rwT_l, p_g_logits, T, E, D, D, D, E);
    top2_k<<<(T + 255) / 256, 256>>>();
    zero_cnt_k<<<1, 32>>>();
    count_k<<<(2 * T + 255) / 256, 256>>>();
    scan_k<<<1, 32>>>();
    gather_k<<<2 * T, 256>>>();
    mgemm_split(p_mx_h, p_mx_l, p_mwguT_h, p_mwguT_l, (long)2 * EF * D,
                p_g_mgu, 2 * EF, D, D, 2 * EF, (size_t)2 * T * 2 * EF * sizeof(float));
    silumul2_k<<<(int)(((long)2 * T * EF + 255) / 256), 256>>>();
    mgemm_split(p_mh_h, p_mh_l, p_mwdT_h, p_mwdT_l, (long)D * EF,
                p_g_my, D, EF, EF, D, (size_t)2 * T * D * sizeof(float));
    moecomb_k<<<(int)(((long)T * D + 255) / 256), 256>>>();

    // ---- MLP layer 0 ----
    mlp(0, p_g_h);
    addnorm_hl_k<<<T, 256>>>(p_g_h, p_g_res, ln_in + D, p_g_res, p_x_h, p_x_l);

    // ---- layer 1 ----
    mla(1, p_g_h, false);
    addnorm_hl_k<<<T, 256>>>(p_g_h, p_g_res, ln_post + D, p_g_res, p_x_h, p_x_l);
    mlp(1, p_g_h);

    add_k<<<(int)(((long)T * D + 255) / 256), 256>>>(p_g_h, p_g_moe, out, (long)T * D);
}

// round 14
// speedup vs baseline: 1.0216x; 1.0216x over previous
#include <cuda_runtime.h>
#include <cuda_bf16.h>
#include <math.h>
#include <stdint.h>

// ---------------- constants ----------------
constexpr int T = 2048, D = 2048, H = 16, DN = 128, DR = 64, DV = 128;
constexpr int QL = 768, KL = 512, FF = 8192, E = 32, EF = 1024;
constexpr int QD = DN + DR;          // 192
constexpr int KVD = KL + DR;         // 576
constexpr int NQKV = QL + KVD;       // 1344
constexpr int KVBD = H * (DN + DV);  // 4096
constexpr int QTOT = H * QD;         // 3072
constexpr int HDV = H * DV;          // 2048

constexpr int BM = 128, BN = 128, BK = 32;
constexpr int PAD = 40;                       // smem leading dim (80B rows, 16B-aligned)
constexpr int TILE_ELEMS = 128 * PAD;         // 5120 elems = 10240 B
constexpr int GSMEM = 2 * 4 * TILE_ELEMS * 2; // 81920 B
constexpr int GPERS = 304;                    // 2 CTAs x 152 SMs

typedef __nv_bfloat16 bf16;

// ---------------- PTX helpers ----------------
__device__ __forceinline__ uint32_t smem_to_u32(const void* p) {
    uint32_t a;
    asm("{ .reg .u64 t; cvta.to.shared.u64 t, %1; cvt.u32.u64 %0, t; }" : "=r"(a) : "l"(p));
    return a;
}
__device__ __forceinline__ void cp16(uint32_t smem_dst, const void* gsrc, bool valid) {
    int sz = valid ? 16 : 0;
    asm volatile("cp.async.cg.shared.global [%0], [%1], 16, %2;\n"
                 :: "r"(smem_dst), "l"(gsrc), "r"(sz));
}
#define CP_COMMIT() asm volatile("cp.async.commit_group;\n" ::: "memory")
#define CP_WAIT0()  asm volatile("cp.async.wait_group 0;\n" ::: "memory")

__device__ __forceinline__ void ldsm_x4(uint32_t* r, uint32_t addr) {
    asm volatile("ldmatrix.sync.aligned.m8n8.x4.shared.b16 {%0,%1,%2,%3}, [%4];\n"
                 : "=r"(r[0]), "=r"(r[1]), "=r"(r[2]), "=r"(r[3]) : "r"(addr));
}
__device__ __forceinline__ void mma_bf(float* c, const uint32_t* a, uint32_t b0, uint32_t b1) {
    asm volatile(
        "mma.sync.aligned.m16n8k16.row.col.f32.bf16.bf16.f32 "
        "{%0,%1,%2,%3}, {%4,%5,%6,%7}, {%8,%9}, {%0,%1,%2,%3};\n"
        : "+f"(c[0]), "+f"(c[1]), "+f"(c[2]), "+f"(c[3])
        : "r"(a[0]), "r"(a[1]), "r"(a[2]), "r"(a[3]), "r"(b0), "r"(b1));
}

// ---------------- scratch (device globals) ----------------
__device__ float g_res[(size_t)T * D];
__device__ float g_h[(size_t)T * D];
__device__ float g_moe[(size_t)T * D];
__device__ float g_qkv[(size_t)T * NQKV];
__device__ float g_q[(size_t)T * QTOT];
__device__ float g_kvb[(size_t)T * KVBD];
__device__ float g_attno[(size_t)T * HDV];
__device__ float g_scores[(size_t)H * T * T];
__device__ float g_gu[(size_t)T * 2 * FF];
__device__ float g_mgu[(size_t)2 * T * 2 * EF];
__device__ float g_my[(size_t)2 * T * D];
__device__ float g_logits[(size_t)T * E];
// bf16 hi/lo activations
__device__ bf16 x_h[(size_t)T * D], x_l[(size_t)T * D];
__device__ bf16 qln_h[(size_t)T * QL], qln_l[(size_t)T * QL];
__device__ bf16 qq_h[(size_t)T * QTOT], qq_l[(size_t)T * QTOT];
__device__ bf16 kvcn_h[(size_t)T * KL], kvcn_l[(size_t)T * KL];
__device__ bf16 kh_h[(size_t)T * QTOT], kh_l[(size_t)T * QTOT];
__device__ bf16 vt_h[(size_t)H * DV * T], vt_l[(size_t)H * DV * T];
__device__ bf16 P_h[(size_t)H * T * T], P_l[(size_t)H * T * T];
__device__ bf16 ao_h[(size_t)T * HDV], ao_l[(size_t)T * HDV];
__device__ bf16 ff_h[(size_t)T * FF], ff_l[(size_t)T * FF];
__device__ bf16 mx_h[(size_t)2 * T * D], mx_l[(size_t)2 * T * D];
__device__ bf16 mh_h[(size_t)2 * T * EF], mh_l[(size_t)2 * T * EF];
// bf16 hi/lo weights transposed to [N][K]
__device__ bf16 wqkvT_h[(size_t)2 * NQKV * D], wqkvT_l[(size_t)2 * NQKV * D];
__device__ bf16 wqbT_h[(size_t)2 * QTOT * QL], wqbT_l[(size_t)2 * QTOT * QL];
__device__ bf16 wkvbT_h[(size_t)2 * KVBD * KL], wkvbT_l[(size_t)2 * KVBD * KL];
__device__ bf16 woT_h[(size_t)2 * D * D], woT_l[(size_t)2 * D * D];
__device__ bf16 wguT_h[(size_t)2 * 2 * FF * D], wguT_l[(size_t)2 * 2 * FF * D];
__device__ bf16 wdT_h[(size_t)2 * D * FF], wdT_l[(size_t)2 * D * FF];
__device__ bf16 rwT_h[(size_t)E * D], rwT_l[(size_t)E * D];
__device__ bf16 mwguT_h[(size_t)E * 2 * EF * D], mwguT_l[(size_t)E * 2 * EF * D];
__device__ bf16 mwdT_h[(size_t)E * D * EF], mwdT_l[(size_t)E * D * EF];
// routing
__device__ int g_expid[2 * T];
__device__ int g_slot[2 * T];
__device__ int g_rowOf[2 * T];
__device__ float g_gate[2 * T];
__device__ int g_cnt[E];
__device__ int g_off[E];

// ---------------- small helpers ----------------
__device__ __forceinline__ void wr_hl(bf16* h, bf16* l, size_t i, float x) {
    bf16 hi = __float2bfloat16(x);
    h[i] = hi;
    l[i] = __float2bfloat16(x - __bfloat162float(hi));
}
__device__ __forceinline__ void split2(float x, unsigned short& h, unsigned short& l) {
    bf16 hi = __float2bfloat16(x);
    bf16 lo = __float2bfloat16(x - __bfloat162float(hi));
    h = *(unsigned short*)&hi;
    l = *(unsigned short*)&lo;
}
__device__ __forceinline__ float blockReduceSum(float v) {
    __shared__ float sh[32];
    int lane = threadIdx.x & 31, wid = threadIdx.x >> 5;
    #pragma unroll
    for (int o = 16; o; o >>= 1) v += __shfl_down_sync(0xffffffffu, v, o);
    if (lane == 0) sh[wid] = v;
    __syncthreads();
    int nw = (blockDim.x + 31) >> 5;
    v = (threadIdx.x < nw) ? sh[threadIdx.x] : 0.f;
    if (wid == 0) {
        #pragma unroll
        for (int o = 16; o; o >>= 1) v += __shfl_down_sync(0xffffffffu, v, o);
        if (lane == 0) sh[0] = v;
    }
    __syncthreads();
    float r = sh[0];
    __syncthreads();
    return r;
}
__device__ __forceinline__ float blockReduceMax(float v) {
    __shared__ float sh[32];
    int lane = threadIdx.x & 31, wid = threadIdx.x >> 5;
    #pragma unroll
    for (int o = 16; o; o >>= 1) v = fmaxf(v, __shfl_down_sync(0xffffffffu, v, o));
    if (lane == 0) sh[wid] = v;
    __syncthreads();
    int nw = (blockDim.x + 31) >> 5;
    v = (threadIdx.x < nw) ? sh[threadIdx.x] : -1e30f;
    if (wid == 0) {
        #pragma unroll
        for (int o = 16; o; o >>= 1) v = fmaxf(v, __shfl_down_sync(0xffffffffu, v, o));
        if (lane == 0) sh[0] = v;
    }
    __syncthreads();
    float r = sh[0];
    __syncthreads();
    return r;
}

// ---- shared GEMM inner body ----
struct GemmCtx {
    uint32_t smb, aoff, boff;
    int tid, lane, wid, warp_m, warp_n, srow0, sch, rrow, rcol;
};
__device__ __forceinline__ GemmCtx make_ctx(const void* sm) {
    GemmCtx c;
    c.smb = smem_to_u32(sm);
    c.tid = threadIdx.x;
    c.lane = c.tid & 31;
    c.wid = c.tid >> 5;
    c.warp_m = c.wid >> 2;
    c.warp_n = c.wid & 3;
    c.srow0 = c.tid >> 2;
    c.sch = c.tid & 3;
    c.aoff = ((uint32_t)((c.lane & 15) * PAD) + ((c.lane >> 4) << 3)) * 2;
    c.boff = ((uint32_t)(((c.lane & 7) + ((c.lane >> 1) & 8)) * PAD) + (c.lane & 8)) * 2;
    c.rrow = c.lane >> 2;
    c.rcol = (c.lane & 3) * 2;
    return c;
}
__device__ __forceinline__ void stage_chunk(const GemmCtx& g, const bf16* Ah, const bf16* Al,
                                            const bf16* Bh, const bf16* Bl,
                                            int lda, int ldb, int bm, int bn,
                                            int rcA, int rcB, int k0, int buf) {
    uint32_t base = g.smb + (uint32_t)buf * 4 * TILE_ELEMS * 2;
    #pragma unroll
    for (int it = 0; it < 2; it++) {
        int row = g.srow0 + it * 64;
        uint32_t soff = (uint32_t)(row * PAD + g.sch * 8) * 2;
        bool vA = row < rcA;
        bool vB = row < rcB;
        long ga = (long)(bm + (vA ? row : 0)) * lda + k0 + g.sch * 8;
        long gb = (long)(bn + (vB ? row : 0)) * ldb + k0 + g.sch * 8;
        cp16(base + 0 * TILE_ELEMS * 2 + soff, Ah + ga, vA);
        cp16(base + 1 * TILE_ELEMS * 2 + soff, Al + ga, vA);
        cp16(base + 2 * TILE_ELEMS * 2 + soff, Bh + gb, vB);
        cp16(base + 3 * TILE_ELEMS * 2 + soff, Bl + gb, vB);
    }
}
__device__ __forceinline__ void compute_chunk(const GemmCtx& g, int buf, float acc[4][4][4]) {
    uint32_t base = g.smb + (uint32_t)buf * 4 * TILE_ELEMS * 2;
    uint32_t tAh = base, tAl = base + TILE_ELEMS * 2;
    uint32_t tBh = base + 2 * TILE_ELEMS * 2, tBl = base + 3 * TILE_ELEMS * 2;
    #pragma unroll
    for (int ks = 0; ks < 2; ks++) {
        uint32_t bh[2][4], bl[2][4];
        #pragma unroll
        for (int nf2 = 0; nf2 < 2; nf2++) {
            uint32_t o = (uint32_t)((g.warp_n * 32 + nf2 * 16) * PAD) * 2 + (uint32_t)(ks * 32) + g.boff;
            ldsm_x4(bh[nf2], tBh + o);
            ldsm_x4(bl[nf2], tBl + o);
        }
        #pragma unroll
        for (int mf = 0; mf < 4; mf++) {
            uint32_t ah[4], al[4];
            uint32_t o = (uint32_t)((g.warp_m * 64 + mf * 16) * PAD) * 2 + (uint32_t)(ks * 32) + g.aoff;
            ldsm_x4(ah, tAh + o);
            ldsm_x4(al, tAl + o);
            #pragma unroll
            for (int nf = 0; nf < 4; nf++) {
                int n2 = nf >> 1, pb = (nf & 1) * 2;
                float* cc = acc[mf][nf];
                mma_bf(cc, ah, bh[n2][pb], bh[n2][pb + 1]);
                mma_bf(cc, ah, bl[n2][pb], bl[n2][pb + 1]);
                mma_bf(cc, al, bh[n2][pb], bh[n2][pb + 1]);
            }
        }
    }
}

// =======================================================================
// bf16x3 GEMM (2-stage, 2 CTA/SM) — scores (cskip)
// =======================================================================
__global__ void __launch_bounds__(256, 2)
bgemm_k(const bf16* __restrict__ Ah, const bf16* __restrict__ Al,
        const bf16* __restrict__ Bh, const bf16* __restrict__ Bl,
        float* __restrict__ C, int M, int N, int K,
        int lda, int ldb, int ldc, long sA, long sB, long sC, int cskip) {
    int z = blockIdx.z;
    Ah += (long)z * sA; Al += (long)z * sA;
    Bh += (long)z * sB; Bl += (long)z * sB;
    C += (long)z * sC;
    int bid = blockIdx.y * gridDim.x + blockIdx.x;
    int mt = gridDim.y;
    int bm = (bid % mt) * BM;
    int bn = (bid / mt) * BN;
    if (bm >= M) return;
    if (cskip && bn > bm + 127) return;
    int nch = K / BK;

    extern __shared__ bf16 sm[];
    GemmCtx g = make_ctx(sm);
    float acc[4][4][4];
    #pragma unroll
    for (int i = 0; i < 4; i++)
        #pragma unroll
        for (int j = 0; j < 4; j++)
            #pragma unroll
            for (int q = 0; q < 4; q++) acc[i][j][q] = 0.f;

    int rcA = (M - bm) < BM ? (M - bm) : BM;
    int rcB = (N - bn) < BN ? (N - bn) : BN;

    stage_chunk(g, Ah, Al, Bh, Bl, lda, ldb, bm, bn, rcA, rcB, 0, 0);
    CP_COMMIT();
    for (int c = 0; c < nch; c++) {
        CP_WAIT0();
        __syncthreads();
        if (c + 1 < nch) {
            stage_chunk(g, Ah, Al, Bh, Bl, lda, ldb, bm, bn, rcA, rcB, (c + 1) * BK, (c + 1) & 1);
            CP_COMMIT();
        }
        compute_chunk(g, c & 1, acc);
        __syncthreads();
    }

    #pragma unroll
    for (int mf = 0; mf < 4; mf++)
        #pragma unroll
        for (int nf = 0; nf < 4; nf++) {
            int m0 = bm + g.warp_m * 64 + mf * 16 + g.rrow;
            int n0 = bn + g.warp_n * 32 + nf * 8 + g.rcol;
            float* cc = acc[mf][nf];
            #pragma unroll
            for (int half = 0; half < 2; half++) {
                int mm = m0 + half * 8;
                if (mm >= M) continue;
                #pragma unroll
                for (int jj = 0; jj < 2; jj++) {
                    int nn = n0 + jj;
                    if (nn < N) C[(long)mm * ldc + nn] = cc[half * 2 + jj];
                }
            }
        }
}

// =======================================================================
// Balanced-range split GEMM (plain GEMMs)
// =======================================================================
__global__ void __launch_bounds__(256, 2)
sgemm_split_k(const bf16* __restrict__ Ah, const bf16* __restrict__ Al,
              const bf16* __restrict__ Bh, const bf16* __restrict__ Bl,
              float* __restrict__ C, int M, int N, int K,
              int lda, int ldb, int ldc, int mt, int nt) {
    int nch = K / BK;
    long U = (long)mt * nt * nch;
    int G = gridDim.x;
    long u0 = (long)blockIdx.x * U / G;
    long u1 = ((long)blockIdx.x + 1) * U / G;

    extern __shared__ bf16 sm[];
    GemmCtx g = make_ctx(sm);

    while (u0 < u1) {
        int tile = (int)(u0 / nch);
        int c0 = (int)(u0 % nch);
        long rem = u1 - (long)tile * nch;
        int c1 = rem < (long)nch ? (int)rem : nch;

        int bm = (tile % mt) * BM;
        int bn = (tile / mt) * BN;
        int rcA = (M - bm) < BM ? (M - bm) : BM;
        int rcB = (N - bn) < BN ? (N - bn) : BN;
        bool full = (c0 == 0) && (c1 == nch);

        float acc[4][4][4];
        #pragma unroll
        for (int i = 0; i < 4; i++)
            #pragma unroll
            for (int j = 0; j < 4; j++)
                #pragma unroll
                for (int q = 0; q < 4; q++) acc[i][j][q] = 0.f;

        stage_chunk(g, Ah, Al, Bh, Bl, lda, ldb, bm, bn, rcA, rcB, c0 * BK, 0);
        CP_COMMIT();
        for (int c = c0; c < c1; c++) {
            CP_WAIT0();
            __syncthreads();
            if (c + 1 < c1) {
                stage_chunk(g, Ah, Al, Bh, Bl, lda, ldb, bm, bn, rcA, rcB, (c + 1) * BK,
                            (c - c0 + 1) & 1);
                CP_COMMIT();
            }
            compute_chunk(g, (c - c0) & 1, acc);
            __syncthreads();
        }

        #pragma unroll
        for (int mf = 0; mf < 4; mf++)
            #pragma unroll
            for (int nf = 0; nf < 4; nf++) {
                int m0 = bm + g.warp_m * 64 + mf * 16 + g.rrow;
                int n0 = bn + g.warp_n * 32 + nf * 8 + g.rcol;
                float* cc = acc[mf][nf];
                #pragma unroll
                for (int half = 0; half < 2; half++) {
                    int mm = m0 + half * 8;
                    if (mm >= M) continue;
                    #pragma unroll
                    for (int jj = 0; jj < 2; jj++) {
                        int nn = n0 + jj;
                        if (nn >= N) continue;
                        float v = cc[half * 2 + jj];
                        if (full) C[(long)mm * ldc + nn] = v;
                        else atomicAdd(&C[(long)mm * ldc + nn], v);
                    }
                }
            }
        __syncthreads();
        u0 = (long)tile * nch + c1;
    }
}

// =======================================================================
// Balanced MoE segmented GEMM
// =======================================================================
__global__ void __launch_bounds__(256, 2)
mgemm_split_k(const bf16* __restrict__ Ah, const bf16* __restrict__ Al,
              const bf16* __restrict__ Bh, const bf16* __restrict__ Bl, long sB,
              float* __restrict__ C, int N, int K, int lda, int ldc) {
    int nch = K / BK;
    int ntN = (N + BN - 1) / BN;
    long U = 0;
    #pragma unroll
    for (int e = 0; e < E; e++)
        U += (long)((g_cnt[e] + 127) >> 7) * ntN * nch;
    int G = gridDim.x;
    long u0 = (long)blockIdx.x * U / G;
    long u1 = ((long)blockIdx.x + 1) * U / G;

    extern __shared__ bf16 sm[];
    GemmCtx g = make_ctx(sm);

    while (u0 < u1) {
        long pre = 0;
        int e = 0, M = 0;
        for (; e < E; e++) {
            M = g_cnt[e];
            long ue = (long)((M + 127) >> 7) * ntN * nch;
            if (u0 < pre + ue) break;
            pre += ue;
        }
        int rs = g_off[e];
        long lu = u0 - pre;
        int tile = (int)(lu / nch);
        int c0 = (int)(lu % nch);
        long luend = u1 - pre;
        long tend = (long)(tile + 1) * nch;
        if (luend > tend) luend = tend;
        int c1 = (int)(luend - (long)tile * nch);
        bool full = (c0 == 0) && (c1 == nch);

        int mtiles = (M + 127) >> 7;
        int bm = (tile % mtiles) * BM;
        int bn = (tile / mtiles) * BN;
        int rcA = (M - bm) < BM ? (M - bm) : BM;
        int rcB = (N - bn) < BN ? (N - bn) : BN;

        const bf16* eAh = Ah + (long)rs * lda;
        const bf16* eAl = Al + (long)rs * lda;
        const bf16* eBh = Bh + (long)e * sB;
        const bf16* eBl = Bl + (long)e * sB;
        float* eC = C + (long)rs * ldc;

        float acc[4][4][4];
        #pragma unroll
        for (int i = 0; i < 4; i++)
            #pragma unroll
            for (int j = 0; j < 4; j++)
                #pragma unroll
                for (int q = 0; q < 4; q++) acc[i][j][q] = 0.f;

        stage_chunk(g, eAh, eAl, eBh, eBl, lda, K, bm, bn, rcA, rcB, c0 * BK, 0);
        CP_COMMIT();
        for (int c = c0; c < c1; c++) {
            CP_WAIT0();
            __syncthreads();
            if (c + 1 < c1) {
                stage_chunk(g, eAh, eAl, eBh, eBl, lda, K, bm, bn, rcA, rcB, (c + 1) * BK,
                            (c - c0 + 1) & 1);
                CP_COMMIT();
            }
            compute_chunk(g, (c - c0) & 1, acc);
            __syncthreads();
        }

        #pragma unroll
        for (int mf = 0; mf < 4; mf++)
            #pragma unroll
            for (int nf = 0; nf < 4; nf++) {
                int m0 = bm + g.warp_m * 64 + mf * 16 + g.rrow;
                int n0 = bn + g.warp_n * 32 + nf * 8 + g.rcol;
                float* cc = acc[mf][nf];
                #pragma unroll
                for (int half = 0; half < 2; half++) {
                    int mm = m0 + half * 8;
                    if (mm >= M) continue;
                    #pragma unroll
                    for (int jj = 0; jj < 2; jj++) {
                        int nn = n0 + jj;
                        if (nn >= N) continue;
                        float v = cc[half * 2 + jj];
                        if (full) eC[(long)mm * ldc + nn] = v;
                        else atomicAdd(&eC[(long)mm * ldc + nn], v);
                    }
                }
            }
        __syncthreads();
        u0 = pre + (long)tile * nch + c1;
    }
}

// =======================================================================
// Balanced AV GEMM: chunks(m)=4(m+1); U=8704
// =======================================================================
__global__ void __launch_bounds__(256, 2)
av_split_k(const bf16* __restrict__ Ph, const bf16* __restrict__ Pl,
           const bf16* __restrict__ Vh, const bf16* __restrict__ Vl,
           float* __restrict__ C) {
    const long U = 8704;
    int G = gridDim.x;
    long u0 = (long)blockIdx.x * U / G;
    long u1 = ((long)blockIdx.x + 1) * U / G;

    extern __shared__ bf16 sm[];
    GemmCtx g = make_ctx(sm);

    while (u0 < u1) {
        int h = (int)(u0 / 544);
        int rem = (int)(u0 - (long)h * 544);
        int m = 0;
        while (rem >= 2 * (m + 1) * (m + 2)) m++;
        int c0 = rem - 2 * m * (m + 1);
        int nchT = 4 * (m + 1);
        long avail = u1 - u0;
        int c1 = (c0 + avail < (long)nchT) ? (int)(c0 + avail) : nchT;
        bool full = (c0 == 0) && (c1 == nchT);
        int bm = m * 128;

        const bf16* Ah = Ph + (size_t)h * T * T;
        const bf16* Al = Pl + (size_t)h * T * T;
        const bf16* Bh = Vh + (size_t)h * 128 * T;
        const bf16* Bl = Vl + (size_t)h * 128 * T;

        float acc[4][4][4];
        #pragma unroll
        for (int i = 0; i < 4; i++)
            #pragma unroll
            for (int j = 0; j < 4; j++)
                #pragma unroll
                for (int q = 0; q < 4; q++) acc[i][j][q] = 0.f;

        stage_chunk(g, Ah, Al, Bh, Bl, T, T, bm, 0, 128, 128, c0 * BK, 0);
        CP_COMMIT();
        for (int c = c0; c < c1; c++) {
            CP_WAIT0();
            __syncthreads();
            if (c + 1 < c1) {
                stage_chunk(g, Ah, Al, Bh, Bl, T, T, bm, 0, 128, 128, (c + 1) * BK,
                            (c - c0 + 1) & 1);
                CP_COMMIT();
            }
            compute_chunk(g, (c - c0) & 1, acc);
            __syncthreads();
        }

        #pragma unroll
        for (int mf = 0; mf < 4; mf++)
            #pragma unroll
            for (int nf = 0; nf < 4; nf++) {
                int m0 = bm + g.warp_m * 64 + mf * 16 + g.rrow;
                int n0 = h * 128 + g.warp_n * 32 + nf * 8 + g.rcol;
                float* cc = acc[mf][nf];
                #pragma unroll
                for (int half = 0; half < 2; half++) {
                    int mm = m0 + half * 8;
                    #pragma unroll
                    for (int jj = 0; jj < 2; jj++) {
                        int nn = n0 + jj;
                        float v = cc[half * 2 + jj];
                        if (full) C[(long)mm * HDV + nn] = v;
                        else atomicAdd(&C[(long)mm * HDV + nn], v);
                    }
                }
            }
        __syncthreads();
        u0 += c1 - c0;
    }
}

// ---------------- vectorized weight transpose + bf16 split ----------------
// W[K][N] -> Oh/Ol[N][K]; 64k x 32n tile; packed uint4 stores (8 bf16 each).
// Requires K % 64 == 0, N % 32 == 0 (holds for all weights here).
__global__ void wtrans_k(const float* __restrict__ W, bf16* __restrict__ Oh,
                         bf16* __restrict__ Ol, int K, int N, long zso) {
    long z = blockIdx.z;
    W += z * (long)K * N;
    Oh += z * zso;
    Ol += z * zso;
    __shared__ float tile[64][33];
    int n0 = blockIdx.x * 32, k0 = blockIdx.y * 64;
    int tid = threadIdx.x;  // 256
    int c = tid & 31, r0 = tid >> 5;
    #pragma unroll
    for (int i = 0; i < 8; i++)
        tile[r0 + i * 8][c] = W[(long)(k0 + r0 + i * 8) * N + n0 + c];
    __syncthreads();
    int nl = tid >> 3, kc = tid & 7;
    int n = n0 + nl;
    unsigned short hi[8], lo[8];
    #pragma unroll
    for (int j = 0; j < 8; j++)
        split2(tile[kc * 8 + j][nl], hi[j], lo[j]);
    *(uint4*)(Oh + (size_t)n * K + k0 + kc * 8) = *(uint4*)hi;
    *(uint4*)(Ol + (size_t)n * K + k0 + kc * 8) = *(uint4*)lo;
}

// ---------------- elementwise / norm ----------------
__global__ void rms_hl_k(const float* __restrict__ x, const float* __restrict__ w,
                         bf16* __restrict__ oh, bf16* __restrict__ ol,
                         int cols, int ldx, int ldo) {
    long row = blockIdx.x;
    const float* xr = x + row * ldx;
    float s = 0.f;
    for (int i = threadIdx.x; i < cols; i += blockDim.x) { float v = xr[i]; s += v * v; }
    s = blockReduceSum(s);
    float sc = rsqrtf(s / cols + 1e-6f);
    for (int i = threadIdx.x; i < cols; i += blockDim.x)
        wr_hl(oh, ol, row * ldo + i, xr[i] * sc * w[i]);
}

__global__ void addnorm_hl_k(const float* __restrict__ a, const float* __restrict__ b,
                             const float* __restrict__ w, float* __restrict__ res,
                             bf16* __restrict__ oh, bf16* __restrict__ ol) {
    long row = blockIdx.x;
    const float* ar = a + row * D;
    const float* br = b + row * D;
    float* rr = res + row * D;
    float s = 0.f;
    for (int i = threadIdx.x; i < D; i += blockDim.x) {
        float v = ar[i] + br[i];
        rr[i] = v;
        s += v * v;
    }
    s = blockReduceSum(s);
    float sc = rsqrtf(s / D + 1e-6f);
    for (int i = threadIdx.x; i < D; i += blockDim.x)
        wr_hl(oh, ol, row * D + i, rr[i] * sc * w[i]);
}

// vectorized fp32 -> bf16 hi/lo (8 elems/thread); n must be multiple of 8
__global__ void cvt_hl_k(const float* __restrict__ x, bf16* __restrict__ oh,
                         bf16* __restrict__ ol, long n) {
    long i = ((long)blockIdx.x * blockDim.x + threadIdx.x) * 8;
    if (i >= n) return;
    unsigned short hi[8], lo[8];
    #pragma unroll
    for (int j = 0; j < 8; j++) split2(x[i + j], hi[j], lo[j]);
    *(uint4*)(oh + i) = *(uint4*)hi;
    *(uint4*)(ol + i) = *(uint4*)lo;
}

__global__ void rope_cvt_q_k(const float* __restrict__ q, const int* __restrict__ pos) {
    int t = blockIdx.x;
    float fp = (float)pos[t];
    for (int e = threadIdx.x; e < QTOT; e += blockDim.x) {
        int h = e / QD, d = e % QD;
        const float* qr = q + (size_t)t * QTOT + h * QD;
        float v;
        if (d < DN) {
            v = qr[d];
        } else {
            int j = d - DN;
            int i = j & 31;
            float inv = 1.f / powf(10000.f, (float)i * (2.f / 64.f));
            float sn, cs;
            sincosf(fp * inv, &sn, &cs);
            float x1 = qr[DN + i], x2 = qr[DN + i + 32];
            v = (j < 32) ? (x1 * cs - x2 * sn) : (x2 * cs + x1 * sn);
        }
        wr_hl(qq_h, qq_l, (size_t)t * QTOT + e, v);
    }
}

__global__ void build_kh_k(const int* __restrict__ pos) {
    int t = blockIdx.x;
    __shared__ float kr[64];
    int tid = threadIdx.x;
    if (tid < 32) {
        int i = tid;
        float inv = 1.f / powf(10000.f, (float)i * (2.f / 64.f));
        float sn, cs;
        sincosf((float)pos[t] * inv, &sn, &cs);
        const float* kb = g_qkv + (size_t)t * NQKV + QL + KL;
        float x1 = kb[i], x2 = kb[i + 32];
        kr[i] = x1 * cs - x2 * sn;
        kr[i + 32] = x2 * cs + x1 * sn;
    }
    __syncthreads();
    for (int e = tid; e < QTOT; e += blockDim.x) {
        int h = e / QD, d = e % QD;
        float v = (d < DN) ? g_kvb[(size_t)t * KVBD + h * (DN + DV) + d] : kr[d - DN];
        wr_hl(kh_h, kh_l, (size_t)t * QTOT + e, v);
    }
}

__global__ void build_vt_k() {
    int t = blockIdx.x;
    const float* row = g_kvb + (size_t)t * KVBD;
    for (int e = threadIdx.x; e < H * DV; e += blockDim.x) {
        int h = e >> 7, d = e & 127;
        wr_hl(vt_h, vt_l, (size_t)e * T + t, row[h * (DN + DV) + DN + d]);
    }
}

__global__ void softmaxP_k() {
    int t = blockIdx.x, h = blockIdx.y;
    const float* row = g_scores + ((size_t)h * T + t) * (size_t)T;
    size_t po = ((size_t)h * T + t) * (size_t)T;
    int n = t + 1;
    const float alpha = 0.07216878364870322f;
    float m = -1e30f;
    for (int i = threadIdx.x; i < n; i += blockDim.x) m = fmaxf(m, row[i] * alpha);
    m = blockReduceMax(m);
    float s = 0.f;
    for (int i = threadIdx.x; i < n; i += blockDim.x) s += expf(row[i] * alpha - m);
    s = blockReduceSum(s);
    float inv = 1.f / s;
    for (int i = threadIdx.x; i < n; i += blockDim.x)
        wr_hl(P_h, P_l, po + i, expf(row[i] * alpha - m) * inv);
    int fend = ((t >> 7) + 1) << 7;
    bf16 zz = __float2bfloat16(0.f);
    for (int i = n + threadIdx.x; i < fend; i += blockDim.x) { P_h[po + i] = zz; P_l[po + i] = zz; }
}

// vectorized silu*mul for dense MLP (8 elems/thread)
__global__ void silumul_mlp_k() {
    long idx = ((long)blockIdx.x * blockDim.x + threadIdx.x) * 8;
    if (idx >= (long)T * FF) return;
    long r = idx / FF;
    int c = (int)(idx % FF);
    const float* gr = g_gu + r * (2 * FF);
    unsigned short hi[8], lo[8];
    #pragma unroll
    for (int j = 0; j < 8; j++) {
        float gv = gr[c + j], u = gr[FF + c + j];
        split2(gv / (1.f + expf(-gv)) * u, hi[j], lo[j]);
    }
    *(uint4*)(ff_h + idx) = *(uint4*)hi;
    *(uint4*)(ff_l + idx) = *(uint4*)lo;
}

// vectorized silu*mul for MoE (8 elems/thread)
__global__ void silumul2_k() {
    long idx = ((long)blockIdx.x * blockDim.x + threadIdx.x) * 8;
    if (idx >= (long)2 * T * EF) return;
    long r = idx / EF;
    int c = (int)(idx % EF);
    const float* gr = g_mgu + r * (2 * EF);
    unsigned short hi[8], lo[8];
    #pragma unroll
    for (int j = 0; j < 8; j++) {
        float gv = gr[c + j], u = gr[EF + c + j];
        split2(gv / (1.f + expf(-gv)) * u, hi[j], lo[j]);
    }
    *(uint4*)(mh_h + idx) = *(uint4*)hi;
    *(uint4*)(mh_l + idx) = *(uint4*)lo;
}

// ---------------- MoE routing ----------------
__global__ void top2_k() {
    int t = blockIdx.x * blockDim.x + threadIdx.x;
    if (t >= T) return;
    const float* l = g_logits + (size_t)t * E;
    int i0 = 0;
    float v0 = l[0];
    for (int i = 1; i < E; i++)
        if (l[i] > v0) { v0 = l[i]; i0 = i; }
    int i1 = -1;
    float v1 = -1e30f;
    for (int i = 0; i < E; i++)
        if (i != i0 && l[i] > v1) { v1 = l[i]; i1 = i; }
    float e = expf(v1 - v0);
    g_expid[2 * t] = i0;
    g_expid[2 * t + 1] = i1;
    g_gate[2 * t] = 1.f / (1.f + e);
    g_gate[2 * t + 1] = e / (1.f + e);
}
__global__ void zero_cnt_k() { if (threadIdx.x < E) g_cnt[threadIdx.x] = 0; }
__global__ void count_k() {
    int p = blockIdx.x * blockDim.x + threadIdx.x;
    if (p < 2 * T) g_slot[p] = atomicAdd(&g_cnt[g_expid[p]], 1);
}
__global__ void scan_k() {
    if (threadIdx.x == 0) {
        int o = 0;
        for (int e = 0; e < E; e++) { g_off[e] = o; o += g_cnt[e]; }
    }
}
__global__ void gather_k() {
    int p = blockIdx.x;
    int row = g_off[g_expid[p]] + g_slot[p];
    if (threadIdx.x == 0) g_rowOf[p] = row;
    size_t src = (size_t)(p >> 1) * D, dst = (size_t)row * D;
    for (int i = threadIdx.x; i < D; i += blockDim.x) {
        mx_h[dst + i] = x_h[src + i];
        mx_l[dst + i] = x_l[src + i];
    }
}
__global__ void moecomb_k() {
    long idx = (long)blockIdx.x * blockDim.x + threadIdx.x;
    if (idx >= (long)T * D) return;
    long t = idx / D;
    int d = (int)(idx % D);
    g_moe[idx] = g_gate[2 * t] * g_my[(size_t)g_rowOf[2 * t] * D + d] +
                 g_gate[2 * t + 1] * g_my[(size_t)g_rowOf[2 * t + 1] * D + d];
}
__global__ void add_k(const float* __restrict__ a, const float* __restrict__ b,
                      float* __restrict__ o, long n) {
    long idx = (long)blockIdx.x * blockDim.x + threadIdx.x;
    if (idx < n) o[idx] = a[idx] + b[idx];
}

// ---------------- host side ----------------
static void bgemm_f(const bf16* Ah, const bf16* Al, const bf16* Bh, const bf16* Bl,
                    float* C, int M, int N, int K, int lda, int ldb, int ldc,
                    long sA, long sB, long sC, int batch, int cskip) {
    dim3 g((N + BN - 1) / BN, (M + BM - 1) / BM, batch);
    bgemm_k<<<g, 256, GSMEM>>>(Ah, Al, Bh, Bl, C, M, N, K, lda, ldb, ldc, sA, sB, sC, cskip);
}
static void sgemm_split(const bf16* Ah, const bf16* Al, const bf16* Bh, const bf16* Bl,
                        float* C, int M, int N, int K, int lda, int ldb, int ldc) {
    cudaMemsetAsync(C, 0, (size_t)M * ldc * sizeof(float));
    int mt = (M + BM - 1) / BM, nt = (N + BN - 1) / BN;
    long U = (long)mt * nt * (K / BK);
    int G = U < GPERS ? (int)U : GPERS;
    sgemm_split_k<<<G, 256, GSMEM>>>(Ah, Al, Bh, Bl, C, M, N, K, lda, ldb, ldc, mt, nt);
}
static void mgemm_split(const bf16* Ah, const bf16* Al, const bf16* Bh, const bf16* Bl,
                        long sB, float* C, int N, int K, int lda, int ldc, size_t csize) {
    cudaMemsetAsync(C, 0, csize);
    mgemm_split_k<<<GPERS, 256, GSMEM>>>(Ah, Al, Bh, Bl, sB, C, N, K, lda, ldc);
}

extern "C" void kernel_launch(void* const* d_in, const int* in_sizes, int n_in,
                              void* d_out, int out_size) {
    const float* hidden = (const float*)d_in[0];
    const int* pos = (const int*)d_in[1];
    const float* ln_in = (const float*)d_in[2];
    const float* ln_post = (const float*)d_in[3];
    const float* wqa = (const float*)d_in[4];
    const float* qnorm = (const float*)d_in[5];
    const float* wqb = (const float*)d_in[6];
    const float* wkva = (const float*)d_in[7];
    const float* kvnorm = (const float*)d_in[8];
    const float* wkvb = (const float*)d_in[9];
    const float* wo = (const float*)d_in[10];
    const float* wgu = (const float*)d_in[11];
    const float* wd = (const float*)d_in[12];
    const float* rw = (const float*)d_in[13];
    const float* mwg = (const float*)d_in[14];
    const float* mwu = (const float*)d_in[15];
    const float* mwd = (const float*)d_in[16];
    float* out = (float*)d_out;

    cudaFuncSetAttribute(bgemm_k, cudaFuncAttributeMaxDynamicSharedMemorySize, GSMEM);
    cudaFuncSetAttribute(sgemm_split_k, cudaFuncAttributeMaxDynamicSharedMemorySize, GSMEM);
    cudaFuncSetAttribute(mgemm_split_k, cudaFuncAttributeMaxDynamicSharedMemorySize, GSMEM);
    cudaFuncSetAttribute(av_split_k, cudaFuncAttributeMaxDynamicSharedMemorySize, GSMEM);

    void* p;
#define SYMF(name) cudaGetSymbolAddress(&p, name); float* p_##name = (float*)p;
#define SYMB(name) cudaGetSymbolAddress(&p, name); bf16* p_##name = (bf16*)p;
#define SYMI(name) cudaGetSymbolAddress(&p, name); int* p_##name = (int*)p;
    SYMF(g_res) SYMF(g_h) SYMF(g_moe) SYMF(g_qkv) SYMF(g_q) SYMF(g_kvb) SYMF(g_attno)
    SYMF(g_scores) SYMF(g_gu) SYMF(g_mgu) SYMF(g_my) SYMF(g_logits)
    SYMB(x_h) SYMB(x_l) SYMB(qln_h) SYMB(qln_l) SYMB(qq_h) SYMB(qq_l)
    SYMB(kvcn_h) SYMB(kvcn_l) SYMB(kh_h) SYMB(kh_l) SYMB(vt_h) SYMB(vt_l)
    SYMB(P_h) SYMB(P_l) SYMB(ao_h) SYMB(ao_l) SYMB(ff_h) SYMB(ff_l)
    SYMB(mx_h) SYMB(mx_l) SYMB(mh_h) SYMB(mh_l)
    SYMB(wqkvT_h) SYMB(wqkvT_l) SYMB(wqbT_h) SYMB(wqbT_l)
    SYMB(wkvbT_h) SYMB(wkvbT_l) SYMB(woT_h) SYMB(woT_l) SYMB(wguT_h) SYMB(wguT_l)
    SYMB(wdT_h) SYMB(wdT_l) SYMB(rwT_h) SYMB(rwT_l)
    SYMB(mwguT_h) SYMB(mwguT_l) SYMB(mwdT_h) SYMB(mwdT_l)
    SYMI(g_cnt) SYMI(g_off)
#undef SYMF
#undef SYMB
#undef SYMI

    long zqkv = (long)NQKV * D;

    // kernels: rms(0), wtrans(1), wtrans(2), sgemm_split(3) <- ncu target
    rms_hl_k<<<T, 256>>>(hidden, ln_in, p_x_h, p_x_l, D, D, D);
    wtrans_k<<<dim3(QL / 32, D / 64, 2), 256>>>(wqa, p_wqkvT_h, p_wqkvT_l, D, QL, zqkv);
    wtrans_k<<<dim3(KVD / 32, D / 64, 2), 256>>>(wkva, p_wqkvT_h + (size_t)QL * D,
                                                 p_wqkvT_l + (size_t)QL * D, D, KVD, zqkv);
    sgemm_split(p_x_h, p_x_l, p_wqkvT_h, p_wqkvT_l, p_g_qkv, T, NQKV, D, D, D, NQKV);
    // remaining weight preps
    wtrans_k<<<dim3(QTOT / 32, QL / 64, 2), 256>>>(wqb, p_wqbT_h, p_wqbT_l, QL, QTOT,
                                                   (long)QTOT * QL);
    wtrans_k<<<dim3(KVBD / 32, KL / 64, 2), 256>>>(wkvb, p_wkvbT_h, p_wkvbT_l, KL, KVBD,
                                                   (long)KVBD * KL);
    wtrans_k<<<dim3(D / 32, HDV / 64, 2), 256>>>(wo, p_woT_h, p_woT_l, HDV, D, (long)D * D);
    wtrans_k<<<dim3(2 * FF / 32, D / 64, 2), 256>>>(wgu, p_wguT_h, p_wguT_l, D, 2 * FF,
                                                    (long)2 * FF * D);
    wtrans_k<<<dim3(D / 32, FF / 64, 2), 256>>>(wd, p_wdT_h, p_wdT_l, FF, D, (long)D * FF);
    wtrans_k<<<dim3(E / 32, D / 64, 1), 256>>>(rw, p_rwT_h, p_rwT_l, D, E, 0);
    wtrans_k<<<dim3(EF / 32, D / 64, E), 256>>>(mwg, p_mwguT_h, p_mwguT_l, D, EF,
                                                (long)2 * EF * D);
    wtrans_k<<<dim3(EF / 32, D / 64, E), 256>>>(mwu, p_mwguT_h + (size_t)EF * D,
                                                p_mwguT_l + (size_t)EF * D, D, EF,
                                                (long)2 * EF * D);
    wtrans_k<<<dim3(D / 32, EF / 64, E), 256>>>(mwd, p_mwdT_h, p_mwdT_l, EF, D, (long)D * EF);

    auto mla = [&](int l, float* outbuf, bool qkv_done) {
        if (!qkv_done)
            sgemm_split(p_x_h, p_x_l, p_wqkvT_h + (size_t)l * zqkv, p_wqkvT_l + (size_t)l * zqkv,
                        p_g_qkv, T, NQKV, D, D, D, NQKV);
        rms_hl_k<<<T, 256>>>(p_g_qkv, qnorm + (size_t)l * QL, p_qln_h, p_qln_l, QL, NQKV, QL);
        sgemm_split(p_qln_h, p_qln_l, p_wqbT_h + (size_t)l * QTOT * QL,
                    p_wqbT_l + (size_t)l * QTOT * QL, p_g_q, T, QTOT, QL, QL, QL, QTOT);
        rms_hl_k<<<T, 256>>>(p_g_qkv + QL, kvnorm + (size_t)l * KL, p_kvcn_h, p_kvcn_l,
                             KL, NQKV, KL);
        sgemm_split(p_kvcn_h, p_kvcn_l, p_wkvbT_h + (size_t)l * KVBD * KL,
                    p_wkvbT_l + (size_t)l * KVBD * KL, p_g_kvb, T, KVBD, KL, KL, KL, KVBD);
        rope_cvt_q_k<<<T, 256>>>(p_g_q, pos);
        build_kh_k<<<T, 256>>>(pos);
        build_vt_k<<<T, 256>>>();
        bgemm_f(p_qq_h, p_qq_l, p_kh_h, p_kh_l, p_g_scores, T, T, QD,
                QTOT, QTOT, T, QD, QD, (long)T * T, H, 1);
        softmaxP_k<<<dim3(T, H), 256>>>();
        cudaMemsetAsync(p_g_attno, 0, (size_t)T * HDV * sizeof(float));
        av_split_k<<<GPERS, 256, GSMEM>>>(p_P_h, p_P_l, p_vt_h, p_vt_l, p_g_attno);
        cvt_hl_k<<<(int)(((long)T * HDV / 8 + 255) / 256), 256>>>(p_g_attno, p_ao_h, p_ao_l,
                                                                  (long)T * HDV);
        sgemm_split(p_ao_h, p_ao_l, p_woT_h + (size_t)l * D * D, p_woT_l + (size_t)l * D * D,
                    outbuf, T, D, HDV, HDV, HDV, D);
    };

    auto mlp = [&](int l, float* outbuf) {
        sgemm_split(p_x_h, p_x_l, p_wguT_h + (size_t)l * 2 * FF * D,
                    p_wguT_l + (size_t)l * 2 * FF * D, p_g_gu, T, 2 * FF, D, D, D, 2 * FF);
        silumul_mlp_k<<<(int)(((long)T * FF / 8 + 255) / 256), 256>>>();
        sgemm_split(p_ff_h, p_ff_l, p_wdT_h + (size_t)l * D * FF, p_wdT_l + (size_t)l * D * FF,
                    outbuf, T, D, FF, FF, FF, D);
    };

    // ================= forward =================
    mla(0, p_g_h, true);
    addnorm_hl_k<<<T, 256>>>(p_g_h, hidden, ln_post, p_g_res, p_x_h, p_x_l);

    // ---- MoE ----
    sgemm_split(p_x_h, p_x_l, p_rwT_h, p_rwT_l, p_g_logits, T, E, D, D, D, E);
    top2_k<<<(T + 255) / 256, 256>>>();
    zero_cnt_k<<<1, 32>>>();
    count_k<<<(2 * T + 255) / 256, 256>>>();
    scan_k<<<1, 32>>>();
    gather_k<<<2 * T, 256>>>();
    mgemm_split(p_mx_h, p_mx_l, p_mwguT_h, p_mwguT_l, (long)2 * EF * D,
                p_g_mgu, 2 * EF, D, D, 2 * EF, (size_t)2 * T * 2 * EF * sizeof(float));
    silumul2_k<<<(int)(((long)2 * T * EF / 8 + 255) / 256), 256>>>();
    mgemm_split(p_mh_h, p_mh_l, p_mwdT_h, p_mwdT_l, (long)D * EF,
                p_g_my, D, EF, EF, D, (size_t)2 * T * D * sizeof(float));
    moecomb_k<<<(int)(((long)T * D + 255) / 256), 256>>>();

    // ---- MLP layer 0 ----
    mlp(0, p_g_h);
    addnorm_hl_k<<<T, 256>>>(p_g_h, p_g_res, ln_in + D, p_g_res, p_x_h, p_x_l);

    // ---- layer 1 ----
    mla(1, p_g_h, false);
    addnorm_hl_k<<<T, 256>>>(p_g_h, p_g_res, ln_post + D, p_g_res, p_x_h, p_x_l);
    mlp(1, p_g_h);

    add_k<<<(int)(((long)T * D + 255) / 256), 256>>>(p_g_h, p_g_moe, out, (long)T * D);
}

// round 15
// speedup vs baseline: 1.0415x; 1.0195x over previous
#include <cuda_runtime.h>
#include <cuda_bf16.h>
#include <math.h>
#include <stdint.h>

// ---------------- constants ----------------
constexpr int T = 2048, D = 2048, H = 16, DN = 128, DR = 64, DV = 128;
constexpr int QL = 768, KL = 512, FF = 8192, E = 32, EF = 1024;
constexpr int QD = DN + DR;          // 192
constexpr int KVD = KL + DR;         // 576
constexpr int NQKV = QL + KVD;       // 1344
constexpr int KVBD = H * (DN + DV);  // 4096
constexpr int QTOT = H * QD;         // 3072
constexpr int HDV = H * DV;          // 2048

constexpr int BM = 128, BN = 128, BK = 32;
constexpr int PAD = 40;                       // smem leading dim (80B rows, 16B-aligned)
constexpr int TILE_ELEMS = 128 * PAD;         // 5120 elems = 10240 B
constexpr int GSMEM = 2 * 4 * TILE_ELEMS * 2; // 81920 B
constexpr int GPERS = 304;                    // 2 CTAs x 152 SMs

typedef __nv_bfloat16 bf16;

// ---------------- PTX helpers ----------------
__device__ __forceinline__ uint32_t smem_to_u32(const void* p) {
    uint32_t a;
    asm("{ .reg .u64 t; cvta.to.shared.u64 t, %1; cvt.u32.u64 %0, t; }" : "=r"(a) : "l"(p));
    return a;
}
__device__ __forceinline__ void cp16(uint32_t smem_dst, const void* gsrc, bool valid) {
    int sz = valid ? 16 : 0;
    asm volatile("cp.async.cg.shared.global [%0], [%1], 16, %2;\n"
                 :: "r"(smem_dst), "l"(gsrc), "r"(sz));
}
#define CP_COMMIT() asm volatile("cp.async.commit_group;\n" ::: "memory")
#define CP_WAIT0()  asm volatile("cp.async.wait_group 0;\n" ::: "memory")

__device__ __forceinline__ void ldsm_x4(uint32_t* r, uint32_t addr) {
    asm volatile("ldmatrix.sync.aligned.m8n8.x4.shared.b16 {%0,%1,%2,%3}, [%4];\n"
                 : "=r"(r[0]), "=r"(r[1]), "=r"(r[2]), "=r"(r[3]) : "r"(addr));
}
__device__ __forceinline__ void mma_bf(float* c, const uint32_t* a, uint32_t b0, uint32_t b1) {
    asm volatile(
        "mma.sync.aligned.m16n8k16.row.col.f32.bf16.bf16.f32 "
        "{%0,%1,%2,%3}, {%4,%5,%6,%7}, {%8,%9}, {%0,%1,%2,%3};\n"
        : "+f"(c[0]), "+f"(c[1]), "+f"(c[2]), "+f"(c[3])
        : "r"(a[0]), "r"(a[1]), "r"(a[2]), "r"(a[3]), "r"(b0), "r"(b1));
}

// ---------------- scratch (device globals) ----------------
__device__ float g_res[(size_t)T * D];
__device__ float g_h[(size_t)T * D];
__device__ float g_moe[(size_t)T * D];
__device__ float g_qkv[(size_t)T * NQKV];
__device__ float g_q[(size_t)T * QTOT];
__device__ float g_kvb[(size_t)T * KVBD];
__device__ float g_attno[(size_t)T * HDV];
__device__ float g_scores[(size_t)H * T * T];
__device__ float g_gu[(size_t)T * 2 * FF];
__device__ float g_mgu[(size_t)2 * T * 2 * EF];
__device__ float g_my[(size_t)2 * T * D];
__device__ float g_logits[(size_t)T * E];
// bf16 hi/lo activations
__device__ bf16 x_h[(size_t)T * D], x_l[(size_t)T * D];
__device__ bf16 qln_h[(size_t)T * QL], qln_l[(size_t)T * QL];
__device__ bf16 qq_h[(size_t)T * QTOT], qq_l[(size_t)T * QTOT];
__device__ bf16 kvcn_h[(size_t)T * KL], kvcn_l[(size_t)T * KL];
__device__ bf16 kh_h[(size_t)T * QTOT], kh_l[(size_t)T * QTOT];
__device__ bf16 vt_h[(size_t)H * DV * T], vt_l[(size_t)H * DV * T];
__device__ bf16 P_h[(size_t)H * T * T], P_l[(size_t)H * T * T];
__device__ bf16 ao_h[(size_t)T * HDV], ao_l[(size_t)T * HDV];
__device__ bf16 ff_h[(size_t)T * FF], ff_l[(size_t)T * FF];
__device__ bf16 mx_h[(size_t)2 * T * D], mx_l[(size_t)2 * T * D];
__device__ bf16 mh_h[(size_t)2 * T * EF], mh_l[(size_t)2 * T * EF];
// bf16 hi/lo weights transposed to [N][K]
__device__ bf16 wqkvT_h[(size_t)2 * NQKV * D], wqkvT_l[(size_t)2 * NQKV * D];
__device__ bf16 wqbT_h[(size_t)2 * QTOT * QL], wqbT_l[(size_t)2 * QTOT * QL];
__device__ bf16 wkvbT_h[(size_t)2 * KVBD * KL], wkvbT_l[(size_t)2 * KVBD * KL];
__device__ bf16 woT_h[(size_t)2 * D * D], woT_l[(size_t)2 * D * D];
__device__ bf16 wguT_h[(size_t)2 * 2 * FF * D], wguT_l[(size_t)2 * 2 * FF * D];
__device__ bf16 wdT_h[(size_t)2 * D * FF], wdT_l[(size_t)2 * D * FF];
__device__ bf16 rwT_h[(size_t)E * D], rwT_l[(size_t)E * D];
__device__ bf16 mwguT_h[(size_t)E * 2 * EF * D], mwguT_l[(size_t)E * 2 * EF * D];
__device__ bf16 mwdT_h[(size_t)E * D * EF], mwdT_l[(size_t)E * D * EF];
// routing
__device__ int g_expid[2 * T];
__device__ int g_slot[2 * T];
__device__ int g_rowOf[2 * T];
__device__ float g_gate[2 * T];
__device__ int g_cnt[E];
__device__ int g_off[E];

// ---------------- small helpers ----------------
__device__ __forceinline__ void wr_hl(bf16* h, bf16* l, size_t i, float x) {
    bf16 hi = __float2bfloat16(x);
    h[i] = hi;
    l[i] = __float2bfloat16(x - __bfloat162float(hi));
}
__device__ __forceinline__ void split2(float x, unsigned short& h, unsigned short& l) {
    bf16 hi = __float2bfloat16(x);
    bf16 lo = __float2bfloat16(x - __bfloat162float(hi));
    h = *(unsigned short*)&hi;
    l = *(unsigned short*)&lo;
}
__device__ __forceinline__ float blockReduceSum(float v) {
    __shared__ float sh[32];
    int lane = threadIdx.x & 31, wid = threadIdx.x >> 5;
    #pragma unroll
    for (int o = 16; o; o >>= 1) v += __shfl_down_sync(0xffffffffu, v, o);
    if (lane == 0) sh[wid] = v;
    __syncthreads();
    int nw = (blockDim.x + 31) >> 5;
    v = (threadIdx.x < nw) ? sh[threadIdx.x] : 0.f;
    if (wid == 0) {
        #pragma unroll
        for (int o = 16; o; o >>= 1) v += __shfl_down_sync(0xffffffffu, v, o);
        if (lane == 0) sh[0] = v;
    }
    __syncthreads();
    float r = sh[0];
    __syncthreads();
    return r;
}
__device__ __forceinline__ float blockReduceMax(float v) {
    __shared__ float sh[32];
    int lane = threadIdx.x & 31, wid = threadIdx.x >> 5;
    #pragma unroll
    for (int o = 16; o; o >>= 1) v = fmaxf(v, __shfl_down_sync(0xffffffffu, v, o));
    if (lane == 0) sh[wid] = v;
    __syncthreads();
    int nw = (blockDim.x + 31) >> 5;
    v = (threadIdx.x < nw) ? sh[threadIdx.x] : -1e30f;
    if (wid == 0) {
        #pragma unroll
        for (int o = 16; o; o >>= 1) v = fmaxf(v, __shfl_down_sync(0xffffffffu, v, o));
        if (lane == 0) sh[0] = v;
    }
    __syncthreads();
    float r = sh[0];
    __syncthreads();
    return r;
}

// ---- shared GEMM inner body ----
struct GemmCtx {
    uint32_t smb, aoff, boff;
    int tid, lane, wid, warp_m, warp_n, srow0, sch, rrow, rcol;
};
__device__ __forceinline__ GemmCtx make_ctx(const void* sm) {
    GemmCtx c;
    c.smb = smem_to_u32(sm);
    c.tid = threadIdx.x;
    c.lane = c.tid & 31;
    c.wid = c.tid >> 5;
    c.warp_m = c.wid >> 2;
    c.warp_n = c.wid & 3;
    c.srow0 = c.tid >> 2;
    c.sch = c.tid & 3;
    c.aoff = ((uint32_t)((c.lane & 15) * PAD) + ((c.lane >> 4) << 3)) * 2;
    c.boff = ((uint32_t)(((c.lane & 7) + ((c.lane >> 1) & 8)) * PAD) + (c.lane & 8)) * 2;
    c.rrow = c.lane >> 2;
    c.rcol = (c.lane & 3) * 2;
    return c;
}
__device__ __forceinline__ void stage_chunk(const GemmCtx& g, const bf16* Ah, const bf16* Al,
                                            const bf16* Bh, const bf16* Bl,
                                            int lda, int ldb, int bm, int bn,
                                            int rcA, int rcB, int k0, int buf) {
    uint32_t base = g.smb + (uint32_t)buf * 4 * TILE_ELEMS * 2;
    #pragma unroll
    for (int it = 0; it < 2; it++) {
        int row = g.srow0 + it * 64;
        uint32_t soff = (uint32_t)(row * PAD + g.sch * 8) * 2;
        bool vA = row < rcA;
        bool vB = row < rcB;
        long ga = (long)(bm + (vA ? row : 0)) * lda + k0 + g.sch * 8;
        long gb = (long)(bn + (vB ? row : 0)) * ldb + k0 + g.sch * 8;
        cp16(base + 0 * TILE_ELEMS * 2 + soff, Ah + ga, vA);
        cp16(base + 1 * TILE_ELEMS * 2 + soff, Al + ga, vA);
        cp16(base + 2 * TILE_ELEMS * 2 + soff, Bh + gb, vB);
        cp16(base + 3 * TILE_ELEMS * 2 + soff, Bl + gb, vB);
    }
}
__device__ __forceinline__ void compute_chunk(const GemmCtx& g, int buf, float acc[4][4][4]) {
    uint32_t base = g.smb + (uint32_t)buf * 4 * TILE_ELEMS * 2;
    uint32_t tAh = base, tAl = base + TILE_ELEMS * 2;
    uint32_t tBh = base + 2 * TILE_ELEMS * 2, tBl = base + 3 * TILE_ELEMS * 2;
    #pragma unroll
    for (int ks = 0; ks < 2; ks++) {
        uint32_t bh[2][4], bl[2][4];
        #pragma unroll
        for (int nf2 = 0; nf2 < 2; nf2++) {
            uint32_t o = (uint32_t)((g.warp_n * 32 + nf2 * 16) * PAD) * 2 + (uint32_t)(ks * 32) + g.boff;
            ldsm_x4(bh[nf2], tBh + o);
            ldsm_x4(bl[nf2], tBl + o);
        }
        #pragma unroll
        for (int mf = 0; mf < 4; mf++) {
            uint32_t ah[4], al[4];
            uint32_t o = (uint32_t)((g.warp_m * 64 + mf * 16) * PAD) * 2 + (uint32_t)(ks * 32) + g.aoff;
            ldsm_x4(ah, tAh + o);
            ldsm_x4(al, tAl + o);
            #pragma unroll
            for (int nf = 0; nf < 4; nf++) {
                int n2 = nf >> 1, pb = (nf & 1) * 2;
                float* cc = acc[mf][nf];
                mma_bf(cc, ah, bh[n2][pb], bh[n2][pb + 1]);
                mma_bf(cc, ah, bl[n2][pb], bl[n2][pb + 1]);
                mma_bf(cc, al, bh[n2][pb], bh[n2][pb + 1]);
            }
        }
    }
}

// =======================================================================
// bf16x3 GEMM (2-stage, 2 CTA/SM) — scores (cskip)
// =======================================================================
__global__ void __launch_bounds__(256, 2)
bgemm_k(const bf16* __restrict__ Ah, const bf16* __restrict__ Al,
        const bf16* __restrict__ Bh, const bf16* __restrict__ Bl,
        float* __restrict__ C, int M, int N, int K,
        int lda, int ldb, int ldc, long sA, long sB, long sC, int cskip) {
    int z = blockIdx.z;
    Ah += (long)z * sA; Al += (long)z * sA;
    Bh += (long)z * sB; Bl += (long)z * sB;
    C += (long)z * sC;
    int bid = blockIdx.y * gridDim.x + blockIdx.x;
    int mt = gridDim.y;
    int bm = (bid % mt) * BM;
    int bn = (bid / mt) * BN;
    if (bm >= M) return;
    if (cskip && bn > bm + 127) return;
    int nch = K / BK;

    extern __shared__ bf16 sm[];
    GemmCtx g = make_ctx(sm);
    float acc[4][4][4];
    #pragma unroll
    for (int i = 0; i < 4; i++)
        #pragma unroll
        for (int j = 0; j < 4; j++)
            #pragma unroll
            for (int q = 0; q < 4; q++) acc[i][j][q] = 0.f;

    int rcA = (M - bm) < BM ? (M - bm) : BM;
    int rcB = (N - bn) < BN ? (N - bn) : BN;

    stage_chunk(g, Ah, Al, Bh, Bl, lda, ldb, bm, bn, rcA, rcB, 0, 0);
    CP_COMMIT();
    for (int c = 0; c < nch; c++) {
        CP_WAIT0();
        __syncthreads();
        if (c + 1 < nch) {
            stage_chunk(g, Ah, Al, Bh, Bl, lda, ldb, bm, bn, rcA, rcB, (c + 1) * BK, (c + 1) & 1);
            CP_COMMIT();
        }
        compute_chunk(g, c & 1, acc);
        __syncthreads();
    }

    #pragma unroll
    for (int mf = 0; mf < 4; mf++)
        #pragma unroll
        for (int nf = 0; nf < 4; nf++) {
            int m0 = bm + g.warp_m * 64 + mf * 16 + g.rrow;
            int n0 = bn + g.warp_n * 32 + nf * 8 + g.rcol;
            float* cc = acc[mf][nf];
            #pragma unroll
            for (int half = 0; half < 2; half++) {
                int mm = m0 + half * 8;
                if (mm >= M) continue;
                #pragma unroll
                for (int jj = 0; jj < 2; jj++) {
                    int nn = n0 + jj;
                    if (nn < N) C[(long)mm * ldc + nn] = cc[half * 2 + jj];
                }
            }
        }
}

// =======================================================================
// Balanced-range split GEMM (plain GEMMs)
// =======================================================================
__global__ void __launch_bounds__(256, 2)
sgemm_split_k(const bf16* __restrict__ Ah, const bf16* __restrict__ Al,
              const bf16* __restrict__ Bh, const bf16* __restrict__ Bl,
              float* __restrict__ C, int M, int N, int K,
              int lda, int ldb, int ldc, int mt, int nt) {
    int nch = K / BK;
    long U = (long)mt * nt * nch;
    int G = gridDim.x;
    long u0 = (long)blockIdx.x * U / G;
    long u1 = ((long)blockIdx.x + 1) * U / G;

    extern __shared__ bf16 sm[];
    GemmCtx g = make_ctx(sm);

    while (u0 < u1) {
        int tile = (int)(u0 / nch);
        int c0 = (int)(u0 % nch);
        long rem = u1 - (long)tile * nch;
        int c1 = rem < (long)nch ? (int)rem : nch;

        int bm = (tile % mt) * BM;
        int bn = (tile / mt) * BN;
        int rcA = (M - bm) < BM ? (M - bm) : BM;
        int rcB = (N - bn) < BN ? (N - bn) : BN;
        bool full = (c0 == 0) && (c1 == nch);

        float acc[4][4][4];
        #pragma unroll
        for (int i = 0; i < 4; i++)
            #pragma unroll
            for (int j = 0; j < 4; j++)
                #pragma unroll
                for (int q = 0; q < 4; q++) acc[i][j][q] = 0.f;

        stage_chunk(g, Ah, Al, Bh, Bl, lda, ldb, bm, bn, rcA, rcB, c0 * BK, 0);
        CP_COMMIT();
        for (int c = c0; c < c1; c++) {
            CP_WAIT0();
            __syncthreads();
            if (c + 1 < c1) {
                stage_chunk(g, Ah, Al, Bh, Bl, lda, ldb, bm, bn, rcA, rcB, (c + 1) * BK,
                            (c - c0 + 1) & 1);
                CP_COMMIT();
            }
            compute_chunk(g, (c - c0) & 1, acc);
            __syncthreads();
        }

        #pragma unroll
        for (int mf = 0; mf < 4; mf++)
            #pragma unroll
            for (int nf = 0; nf < 4; nf++) {
                int m0 = bm + g.warp_m * 64 + mf * 16 + g.rrow;
                int n0 = bn + g.warp_n * 32 + nf * 8 + g.rcol;
                float* cc = acc[mf][nf];
                #pragma unroll
                for (int half = 0; half < 2; half++) {
                    int mm = m0 + half * 8;
                    if (mm >= M) continue;
                    #pragma unroll
                    for (int jj = 0; jj < 2; jj++) {
                        int nn = n0 + jj;
                        if (nn >= N) continue;
                        float v = cc[half * 2 + jj];
                        if (full) C[(long)mm * ldc + nn] = v;
                        else atomicAdd(&C[(long)mm * ldc + nn], v);
                    }
                }
            }
        __syncthreads();
        u0 = (long)tile * nch + c1;
    }
}

// =======================================================================
// Balanced MoE segmented GEMM
// =======================================================================
__global__ void __launch_bounds__(256, 2)
mgemm_split_k(const bf16* __restrict__ Ah, const bf16* __restrict__ Al,
              const bf16* __restrict__ Bh, const bf16* __restrict__ Bl, long sB,
              float* __restrict__ C, int N, int K, int lda, int ldc) {
    int nch = K / BK;
    int ntN = (N + BN - 1) / BN;
    long U = 0;
    #pragma unroll
    for (int e = 0; e < E; e++)
        U += (long)((g_cnt[e] + 127) >> 7) * ntN * nch;
    int G = gridDim.x;
    long u0 = (long)blockIdx.x * U / G;
    long u1 = ((long)blockIdx.x + 1) * U / G;

    extern __shared__ bf16 sm[];
    GemmCtx g = make_ctx(sm);

    while (u0 < u1) {
        long pre = 0;
        int e = 0, M = 0;
        for (; e < E; e++) {
            M = g_cnt[e];
            long ue = (long)((M + 127) >> 7) * ntN * nch;
            if (u0 < pre + ue) break;
            pre += ue;
        }
        int rs = g_off[e];
        long lu = u0 - pre;
        int tile = (int)(lu / nch);
        int c0 = (int)(lu % nch);
        long luend = u1 - pre;
        long tend = (long)(tile + 1) * nch;
        if (luend > tend) luend = tend;
        int c1 = (int)(luend - (long)tile * nch);
        bool full = (c0 == 0) && (c1 == nch);

        int mtiles = (M + 127) >> 7;
        int bm = (tile % mtiles) * BM;
        int bn = (tile / mtiles) * BN;
        int rcA = (M - bm) < BM ? (M - bm) : BM;
        int rcB = (N - bn) < BN ? (N - bn) : BN;

        const bf16* eAh = Ah + (long)rs * lda;
        const bf16* eAl = Al + (long)rs * lda;
        const bf16* eBh = Bh + (long)e * sB;
        const bf16* eBl = Bl + (long)e * sB;
        float* eC = C + (long)rs * ldc;

        float acc[4][4][4];
        #pragma unroll
        for (int i = 0; i < 4; i++)
            #pragma unroll
            for (int j = 0; j < 4; j++)
                #pragma unroll
                for (int q = 0; q < 4; q++) acc[i][j][q] = 0.f;

        stage_chunk(g, eAh, eAl, eBh, eBl, lda, K, bm, bn, rcA, rcB, c0 * BK, 0);
        CP_COMMIT();
        for (int c = c0; c < c1; c++) {
            CP_WAIT0();
            __syncthreads();
            if (c + 1 < c1) {
                stage_chunk(g, eAh, eAl, eBh, eBl, lda, K, bm, bn, rcA, rcB, (c + 1) * BK,
                            (c - c0 + 1) & 1);
                CP_COMMIT();
            }
            compute_chunk(g, (c - c0) & 1, acc);
            __syncthreads();
        }

        #pragma unroll
        for (int mf = 0; mf < 4; mf++)
            #pragma unroll
            for (int nf = 0; nf < 4; nf++) {
                int m0 = bm + g.warp_m * 64 + mf * 16 + g.rrow;
                int n0 = bn + g.warp_n * 32 + nf * 8 + g.rcol;
                float* cc = acc[mf][nf];
                #pragma unroll
                for (int half = 0; half < 2; half++) {
                    int mm = m0 + half * 8;
                    if (mm >= M) continue;
                    #pragma unroll
                    for (int jj = 0; jj < 2; jj++) {
                        int nn = n0 + jj;
                        if (nn >= N) continue;
                        float v = cc[half * 2 + jj];
                        if (full) eC[(long)mm * ldc + nn] = v;
                        else atomicAdd(&eC[(long)mm * ldc + nn], v);
                    }
                }
            }
        __syncthreads();
        u0 = pre + (long)tile * nch + c1;
    }
}

// =======================================================================
// Balanced AV GEMM: chunks(m)=4(m+1); U=8704
// =======================================================================
__global__ void __launch_bounds__(256, 2)
av_split_k(const bf16* __restrict__ Ph, const bf16* __restrict__ Pl,
           const bf16* __restrict__ Vh, const bf16* __restrict__ Vl,
           float* __restrict__ C) {
    const long U = 8704;
    int G = gridDim.x;
    long u0 = (long)blockIdx.x * U / G;
    long u1 = ((long)blockIdx.x + 1) * U / G;

    extern __shared__ bf16 sm[];
    GemmCtx g = make_ctx(sm);

    while (u0 < u1) {
        int h = (int)(u0 / 544);
        int rem = (int)(u0 - (long)h * 544);
        int m = 0;
        while (rem >= 2 * (m + 1) * (m + 2)) m++;
        int c0 = rem - 2 * m * (m + 1);
        int nchT = 4 * (m + 1);
        long avail = u1 - u0;
        int c1 = (c0 + avail < (long)nchT) ? (int)(c0 + avail) : nchT;
        bool full = (c0 == 0) && (c1 == nchT);
        int bm = m * 128;

        const bf16* Ah = Ph + (size_t)h * T * T;
        const bf16* Al = Pl + (size_t)h * T * T;
        const bf16* Bh = Vh + (size_t)h * 128 * T;
        const bf16* Bl = Vl + (size_t)h * 128 * T;

        float acc[4][4][4];
        #pragma unroll
        for (int i = 0; i < 4; i++)
            #pragma unroll
            for (int j = 0; j < 4; j++)
                #pragma unroll
                for (int q = 0; q < 4; q++) acc[i][j][q] = 0.f;

        stage_chunk(g, Ah, Al, Bh, Bl, T, T, bm, 0, 128, 128, c0 * BK, 0);
        CP_COMMIT();
        for (int c = c0; c < c1; c++) {
            CP_WAIT0();
            __syncthreads();
            if (c + 1 < c1) {
                stage_chunk(g, Ah, Al, Bh, Bl, T, T, bm, 0, 128, 128, (c + 1) * BK,
                            (c - c0 + 1) & 1);
                CP_COMMIT();
            }
            compute_chunk(g, (c - c0) & 1, acc);
            __syncthreads();
        }

        #pragma unroll
        for (int mf = 0; mf < 4; mf++)
            #pragma unroll
            for (int nf = 0; nf < 4; nf++) {
                int m0 = bm + g.warp_m * 64 + mf * 16 + g.rrow;
                int n0 = h * 128 + g.warp_n * 32 + nf * 8 + g.rcol;
                float* cc = acc[mf][nf];
                #pragma unroll
                for (int half = 0; half < 2; half++) {
                    int mm = m0 + half * 8;
                    #pragma unroll
                    for (int jj = 0; jj < 2; jj++) {
                        int nn = n0 + jj;
                        float v = cc[half * 2 + jj];
                        if (full) C[(long)mm * HDV + nn] = v;
                        else atomicAdd(&C[(long)mm * HDV + nn], v);
                    }
                }
            }
        __syncthreads();
        u0 += c1 - c0;
    }
}

// ---------------- vectorized weight transpose + bf16 split ----------------
__global__ void wtrans_k(const float* __restrict__ W, bf16* __restrict__ Oh,
                         bf16* __restrict__ Ol, int K, int N, long zso) {
    long z = blockIdx.z;
    W += z * (long)K * N;
    Oh += z * zso;
    Ol += z * zso;
    __shared__ float tile[64][33];
    int n0 = blockIdx.x * 32, k0 = blockIdx.y * 64;
    int tid = threadIdx.x;  // 256
    int c = tid & 31, r0 = tid >> 5;
    #pragma unroll
    for (int i = 0; i < 8; i++)
        tile[r0 + i * 8][c] = W[(long)(k0 + r0 + i * 8) * N + n0 + c];
    __syncthreads();
    int nl = tid >> 3, kc = tid & 7;
    int n = n0 + nl;
    unsigned short hi[8], lo[8];
    #pragma unroll
    for (int j = 0; j < 8; j++)
        split2(tile[kc * 8 + j][nl], hi[j], lo[j]);
    *(uint4*)(Oh + (size_t)n * K + k0 + kc * 8) = *(uint4*)hi;
    *(uint4*)(Ol + (size_t)n * K + k0 + kc * 8) = *(uint4*)lo;
}

// ---------------- elementwise / norm ----------------
__global__ void rms_hl_k(const float* __restrict__ x, const float* __restrict__ w,
                         bf16* __restrict__ oh, bf16* __restrict__ ol,
                         int cols, int ldx, int ldo) {
    long row = blockIdx.x;
    const float* xr = x + row * ldx;
    float s = 0.f;
    for (int i = threadIdx.x; i < cols; i += blockDim.x) { float v = xr[i]; s += v * v; }
    s = blockReduceSum(s);
    float sc = rsqrtf(s / cols + 1e-6f);
    for (int i = threadIdx.x; i < cols; i += blockDim.x)
        wr_hl(oh, ol, row * ldo + i, xr[i] * sc * w[i]);
}

__global__ void addnorm_hl_k(const float* __restrict__ a, const float* __restrict__ b,
                             const float* __restrict__ w, float* __restrict__ res,
                             bf16* __restrict__ oh, bf16* __restrict__ ol) {
    long row = blockIdx.x;
    const float* ar = a + row * D;
    const float* br = b + row * D;
    float* rr = res + row * D;
    float s = 0.f;
    for (int i = threadIdx.x; i < D; i += blockDim.x) {
        float v = ar[i] + br[i];
        rr[i] = v;
        s += v * v;
    }
    s = blockReduceSum(s);
    float sc = rsqrtf(s / D + 1e-6f);
    for (int i = threadIdx.x; i < D; i += blockDim.x)
        wr_hl(oh, ol, row * D + i, rr[i] * sc * w[i]);
}

// vectorized fp32 -> bf16 hi/lo (8 elems/thread); n must be multiple of 8
__global__ void cvt_hl_k(const float* __restrict__ x, bf16* __restrict__ oh,
                         bf16* __restrict__ ol, long n) {
    long i = ((long)blockIdx.x * blockDim.x + threadIdx.x) * 8;
    if (i >= n) return;
    unsigned short hi[8], lo[8];
    #pragma unroll
    for (int j = 0; j < 8; j++) split2(x[i + j], hi[j], lo[j]);
    *(uint4*)(oh + i) = *(uint4*)hi;
    *(uint4*)(ol + i) = *(uint4*)lo;
}

__global__ void rope_cvt_q_k(const float* __restrict__ q, const int* __restrict__ pos) {
    int t = blockIdx.x;
    float fp = (float)pos[t];
    for (int e = threadIdx.x; e < QTOT; e += blockDim.x) {
        int h = e / QD, d = e % QD;
        const float* qr = q + (size_t)t * QTOT + h * QD;
        float v;
        if (d < DN) {
            v = qr[d];
        } else {
            int j = d - DN;
            int i = j & 31;
            float inv = 1.f / powf(10000.f, (float)i * (2.f / 64.f));
            float sn, cs;
            sincosf(fp * inv, &sn, &cs);
            float x1 = qr[DN + i], x2 = qr[DN + i + 32];
            v = (j < 32) ? (x1 * cs - x2 * sn) : (x2 * cs + x1 * sn);
        }
        wr_hl(qq_h, qq_l, (size_t)t * QTOT + e, v);
    }
}

__global__ void build_kh_k(const int* __restrict__ pos) {
    int t = blockIdx.x;
    __shared__ float kr[64];
    int tid = threadIdx.x;
    if (tid < 32) {
        int i = tid;
        float inv = 1.f / powf(10000.f, (float)i * (2.f / 64.f));
        float sn, cs;
        sincosf((float)pos[t] * inv, &sn, &cs);
        const float* kb = g_qkv + (size_t)t * NQKV + QL + KL;
        float x1 = kb[i], x2 = kb[i + 32];
        kr[i] = x1 * cs - x2 * sn;
        kr[i + 32] = x2 * cs + x1 * sn;
    }
    __syncthreads();
    for (int e = tid; e < QTOT; e += blockDim.x) {
        int h = e / QD, d = e % QD;
        float v = (d < DN) ? g_kvb[(size_t)t * KVBD + h * (DN + DV) + d] : kr[d - DN];
        wr_hl(kh_h, kh_l, (size_t)t * QTOT + e, v);
    }
}

// =======================================================================
// build_vt: smem-transposed, vectorized stores.
// vt[(h*128+d)*T + t] = kvb[t][h*256 + 128 + d]; block = 64t x 128d of one head.
// =======================================================================
__global__ void build_vt_k() {
    __shared__ float tile[64][129];
    int t0 = blockIdx.x * 64;
    int h = blockIdx.y;
    int tid = threadIdx.x;  // 256
    // load: coalesced 128 consecutive floats per row
    #pragma unroll
    for (int i = 0; i < 32; i++) {
        int idx = i * 256 + tid;
        int tt = idx >> 7, dd = idx & 127;
        tile[tt][dd] = g_kvb[(size_t)(t0 + tt) * KVBD + h * (DN + DV) + DN + dd];
    }
    __syncthreads();
    // write: thread -> (d, half); 4 x uint4 (8 bf16) per buffer, contiguous in t
    int d = tid >> 1, half = tid & 1;
    size_t obase = ((size_t)h * 128 + d) * T + t0 + half * 32;
    #pragma unroll
    for (int v = 0; v < 4; v++) {
        unsigned short hi[8], lo[8];
        #pragma unroll
        for (int j = 0; j < 8; j++)
            split2(tile[half * 32 + v * 8 + j][d], hi[j], lo[j]);
        *(uint4*)(vt_h + obase + v * 8) = *(uint4*)hi;
        *(uint4*)(vt_l + obase + v * 8) = *(uint4*)lo;
    }
}

__global__ void softmaxP_k() {
    int t = blockIdx.x, h = blockIdx.y;
    const float* row = g_scores + ((size_t)h * T + t) * (size_t)T;
    size_t po = ((size_t)h * T + t) * (size_t)T;
    int n = t + 1;
    const float alpha = 0.07216878364870322f;
    float m = -1e30f;
    for (int i = threadIdx.x; i < n; i += blockDim.x) m = fmaxf(m, row[i] * alpha);
    m = blockReduceMax(m);
    float s = 0.f;
    for (int i = threadIdx.x; i < n; i += blockDim.x) s += expf(row[i] * alpha - m);
    s = blockReduceSum(s);
    float inv = 1.f / s;
    for (int i = threadIdx.x; i < n; i += blockDim.x)
        wr_hl(P_h, P_l, po + i, expf(row[i] * alpha - m) * inv);
    int fend = ((t >> 7) + 1) << 7;
    bf16 zz = __float2bfloat16(0.f);
    for (int i = n + threadIdx.x; i < fend; i += blockDim.x) { P_h[po + i] = zz; P_l[po + i] = zz; }
}

// vectorized silu*mul for dense MLP (8 elems/thread)
__global__ void silumul_mlp_k() {
    long idx = ((long)blockIdx.x * blockDim.x + threadIdx.x) * 8;
    if (idx >= (long)T * FF) return;
    long r = idx / FF;
    int c = (int)(idx % FF);
    const float* gr = g_gu + r * (2 * FF);
    unsigned short hi[8], lo[8];
    #pragma unroll
    for (int j = 0; j < 8; j++) {
        float gv = gr[c + j], u = gr[FF + c + j];
        split2(gv / (1.f + expf(-gv)) * u, hi[j], lo[j]);
    }
    *(uint4*)(ff_h + idx) = *(uint4*)hi;
    *(uint4*)(ff_l + idx) = *(uint4*)lo;
}

// vectorized silu*mul for MoE (8 elems/thread)
__global__ void silumul2_k() {
    long idx = ((long)blockIdx.x * blockDim.x + threadIdx.x) * 8;
    if (idx >= (long)2 * T * EF) return;
    long r = idx / EF;
    int c = (int)(idx % EF);
    const float* gr = g_mgu + r * (2 * EF);
    unsigned short hi[8], lo[8];
    #pragma unroll
    for (int j = 0; j < 8; j++) {
        float gv = gr[c + j], u = gr[EF + c + j];
        split2(gv / (1.f + expf(-gv)) * u, hi[j], lo[j]);
    }
    *(uint4*)(mh_h + idx) = *(uint4*)hi;
    *(uint4*)(mh_l + idx) = *(uint4*)lo;
}

// ---------------- MoE routing ----------------
__global__ void top2_k() {
    int t = blockIdx.x * blockDim.x + threadIdx.x;
    if (t >= T) return;
    const float* l = g_logits + (size_t)t * E;
    int i0 = 0;
    float v0 = l[0];
    for (int i = 1; i < E; i++)
        if (l[i] > v0) { v0 = l[i]; i0 = i; }
    int i1 = -1;
    float v1 = -1e30f;
    for (int i = 0; i < E; i++)
        if (i != i0 && l[i] > v1) { v1 = l[i]; i1 = i; }
    float e = expf(v1 - v0);
    g_expid[2 * t] = i0;
    g_expid[2 * t + 1] = i1;
    g_gate[2 * t] = 1.f / (1.f + e);
    g_gate[2 * t + 1] = e / (1.f + e);
}
__global__ void zero_cnt_k() { if (threadIdx.x < E) g_cnt[threadIdx.x] = 0; }
__global__ void count_k() {
    int p = blockIdx.x * blockDim.x + threadIdx.x;
    if (p < 2 * T) g_slot[p] = atomicAdd(&g_cnt[g_expid[p]], 1);
}
__global__ void scan_k() {
    if (threadIdx.x == 0) {
        int o = 0;
        for (int e = 0; e < E; e++) { g_off[e] = o; o += g_cnt[e]; }
    }
}
__global__ void gather_k() {
    int p = blockIdx.x;
    int row = g_off[g_expid[p]] + g_slot[p];
    if (threadIdx.x == 0) g_rowOf[p] = row;
    size_t src = (size_t)(p >> 1) * D, dst = (size_t)row * D;
    for (int i = threadIdx.x; i < D; i += blockDim.x) {
        mx_h[dst + i] = x_h[src + i];
        mx_l[dst + i] = x_l[src + i];
    }
}
__global__ void moecomb_k() {
    long idx = (long)blockIdx.x * blockDim.x + threadIdx.x;
    if (idx >= (long)T * D) return;
    long t = idx / D;
    int d = (int)(idx % D);
    g_moe[idx] = g_gate[2 * t] * g_my[(size_t)g_rowOf[2 * t] * D + d] +
                 g_gate[2 * t + 1] * g_my[(size_t)g_rowOf[2 * t + 1] * D + d];
}
__global__ void add_k(const float* __restrict__ a, const float* __restrict__ b,
                      float* __restrict__ o, long n) {
    long idx = (long)blockIdx.x * blockDim.x + threadIdx.x;
    if (idx < n) o[idx] = a[idx] + b[idx];
}

// ---------------- host side ----------------
static void bgemm_f(const bf16* Ah, const bf16* Al, const bf16* Bh, const bf16* Bl,
                    float* C, int M, int N, int K, int lda, int ldb, int ldc,
                    long sA, long sB, long sC, int batch, int cskip) {
    dim3 g((N + BN - 1) / BN, (M + BM - 1) / BM, batch);
    bgemm_k<<<g, 256, GSMEM>>>(Ah, Al, Bh, Bl, C, M, N, K, lda, ldb, ldc, sA, sB, sC, cskip);
}
static void sgemm_split(const bf16* Ah, const bf16* Al, const bf16* Bh, const bf16* Bl,
                        float* C, int M, int N, int K, int lda, int ldb, int ldc) {
    cudaMemsetAsync(C, 0, (size_t)M * ldc * sizeof(float));
    int mt = (M + BM - 1) / BM, nt = (N + BN - 1) / BN;
    long U = (long)mt * nt * (K / BK);
    int G = U < GPERS ? (int)U : GPERS;
    sgemm_split_k<<<G, 256, GSMEM>>>(Ah, Al, Bh, Bl, C, M, N, K, lda, ldb, ldc, mt, nt);
}
static void mgemm_split(const bf16* Ah, const bf16* Al, const bf16* Bh, const bf16* Bl,
                        long sB, float* C, int N, int K, int lda, int ldc, size_t csize) {
    cudaMemsetAsync(C, 0, csize);
    mgemm_split_k<<<GPERS, 256, GSMEM>>>(Ah, Al, Bh, Bl, sB, C, N, K, lda, ldc);
}

extern "C" void kernel_launch(void* const* d_in, const int* in_sizes, int n_in,
                              void* d_out, int out_size) {
    const float* hidden = (const float*)d_in[0];
    const int* pos = (const int*)d_in[1];
    const float* ln_in = (const float*)d_in[2];
    const float* ln_post = (const float*)d_in[3];
    const float* wqa = (const float*)d_in[4];
    const float* qnorm = (const float*)d_in[5];
    const float* wqb = (const float*)d_in[6];
    const float* wkva = (const float*)d_in[7];
    const float* kvnorm = (const float*)d_in[8];
    const float* wkvb = (const float*)d_in[9];
    const float* wo = (const float*)d_in[10];
    const float* wgu = (const float*)d_in[11];
    const float* wd = (const float*)d_in[12];
    const float* rw = (const float*)d_in[13];
    const float* mwg = (const float*)d_in[14];
    const float* mwu = (const float*)d_in[15];
    const float* mwd = (const float*)d_in[16];
    float* out = (float*)d_out;

    cudaFuncSetAttribute(bgemm_k, cudaFuncAttributeMaxDynamicSharedMemorySize, GSMEM);
    cudaFuncSetAttribute(sgemm_split_k, cudaFuncAttributeMaxDynamicSharedMemorySize, GSMEM);
    cudaFuncSetAttribute(mgemm_split_k, cudaFuncAttributeMaxDynamicSharedMemorySize, GSMEM);
    cudaFuncSetAttribute(av_split_k, cudaFuncAttributeMaxDynamicSharedMemorySize, GSMEM);

    void* p;
#define SYMF(name) cudaGetSymbolAddress(&p, name); float* p_##name = (float*)p;
#define SYMB(name) cudaGetSymbolAddress(&p, name); bf16* p_##name = (bf16*)p;
#define SYMI(name) cudaGetSymbolAddress(&p, name); int* p_##name = (int*)p;
    SYMF(g_res) SYMF(g_h) SYMF(g_moe) SYMF(g_qkv) SYMF(g_q) SYMF(g_kvb) SYMF(g_attno)
    SYMF(g_scores) SYMF(g_gu) SYMF(g_mgu) SYMF(g_my) SYMF(g_logits)
    SYMB(x_h) SYMB(x_l) SYMB(qln_h) SYMB(qln_l) SYMB(qq_h) SYMB(qq_l)
    SYMB(kvcn_h) SYMB(kvcn_l) SYMB(kh_h) SYMB(kh_l) SYMB(vt_h) SYMB(vt_l)
    SYMB(P_h) SYMB(P_l) SYMB(ao_h) SYMB(ao_l) SYMB(ff_h) SYMB(ff_l)
    SYMB(mx_h) SYMB(mx_l) SYMB(mh_h) SYMB(mh_l)
    SYMB(wqkvT_h) SYMB(wqkvT_l) SYMB(wqbT_h) SYMB(wqbT_l)
    SYMB(wkvbT_h) SYMB(wkvbT_l) SYMB(woT_h) SYMB(woT_l) SYMB(wguT_h) SYMB(wguT_l)
    SYMB(wdT_h) SYMB(wdT_l) SYMB(rwT_h) SYMB(rwT_l)
    SYMB(mwguT_h) SYMB(mwguT_l) SYMB(mwdT_h) SYMB(mwdT_l)
    SYMI(g_cnt) SYMI(g_off)
#undef SYMF
#undef SYMB
#undef SYMI

    long zqkv = (long)NQKV * D;

    // kernels: rms(0), wtrans(1), wtrans(2), sgemm_split(3) <- ncu target
    rms_hl_k<<<T, 256>>>(hidden, ln_in, p_x_h, p_x_l, D, D, D);
    wtrans_k<<<dim3(QL / 32, D / 64, 2), 256>>>(wqa, p_wqkvT_h, p_wqkvT_l, D, QL, zqkv);
    wtrans_k<<<dim3(KVD / 32, D / 64, 2), 256>>>(wkva, p_wqkvT_h + (size_t)QL * D,
                                                 p_wqkvT_l + (size_t)QL * D, D, KVD, zqkv);
    sgemm_split(p_x_h, p_x_l, p_wqkvT_h, p_wqkvT_l, p_g_qkv, T, NQKV, D, D, D, NQKV);
    // remaining weight preps
    wtrans_k<<<dim3(QTOT / 32, QL / 64, 2), 256>>>(wqb, p_wqbT_h, p_wqbT_l, QL, QTOT,
                                                   (long)QTOT * QL);
    wtrans_k<<<dim3(KVBD / 32, KL / 64, 2), 256>>>(wkvb, p_wkvbT_h, p_wkvbT_l, KL, KVBD,
                                                   (long)KVBD * KL);
    wtrans_k<<<dim3(D / 32, HDV / 64, 2), 256>>>(wo, p_woT_h, p_woT_l, HDV, D, (long)D * D);
    wtrans_k<<<dim3(2 * FF / 32, D / 64, 2), 256>>>(wgu, p_wguT_h, p_wguT_l, D, 2 * FF,
                                                    (long)2 * FF * D);
    wtrans_k<<<dim3(D / 32, FF / 64, 2), 256>>>(wd, p_wdT_h, p_wdT_l, FF, D, (long)D * FF);
    wtrans_k<<<dim3(E / 32, D / 64, 1), 256>>>(rw, p_rwT_h, p_rwT_l, D, E, 0);
    wtrans_k<<<dim3(EF / 32, D / 64, E), 256>>>(mwg, p_mwguT_h, p_mwguT_l, D, EF,
                                                (long)2 * EF * D);
    wtrans_k<<<dim3(EF / 32, D / 64, E), 256>>>(mwu, p_mwguT_h + (size_t)EF * D,
                                                p_mwguT_l + (size_t)EF * D, D, EF,
                                                (long)2 * EF * D);
    wtrans_k<<<dim3(D / 32, EF / 64, E), 256>>>(mwd, p_mwdT_h, p_mwdT_l, EF, D, (long)D * EF);

    auto mla = [&](int l, float* outbuf, bool qkv_done) {
        if (!qkv_done)
            sgemm_split(p_x_h, p_x_l, p_wqkvT_h + (size_t)l * zqkv, p_wqkvT_l + (size_t)l * zqkv,
                        p_g_qkv, T, NQKV, D, D, D, NQKV);
        rms_hl_k<<<T, 256>>>(p_g_qkv, qnorm + (size_t)l * QL, p_qln_h, p_qln_l, QL, NQKV, QL);
        sgemm_split(p_qln_h, p_qln_l, p_wqbT_h + (size_t)l * QTOT * QL,
                    p_wqbT_l + (size_t)l * QTOT * QL, p_g_q, T, QTOT, QL, QL, QL, QTOT);
        rms_hl_k<<<T, 256>>>(p_g_qkv + QL, kvnorm + (size_t)l * KL, p_kvcn_h, p_kvcn_l,
                             KL, NQKV, KL);
        sgemm_split(p_kvcn_h, p_kvcn_l, p_wkvbT_h + (size_t)l * KVBD * KL,
                    p_wkvbT_l + (size_t)l * KVBD * KL, p_g_kvb, T, KVBD, KL, KL, KL, KVBD);
        rope_cvt_q_k<<<T, 256>>>(p_g_q, pos);
        build_kh_k<<<T, 256>>>(pos);
        build_vt_k<<<dim3(T / 64, H), 256>>>();
        bgemm_f(p_qq_h, p_qq_l, p_kh_h, p_kh_l, p_g_scores, T, T, QD,
                QTOT, QTOT, T, QD, QD, (long)T * T, H, 1);
        softmaxP_k<<<dim3(T, H), 256>>>();
        cudaMemsetAsync(p_g_attno, 0, (size_t)T * HDV * sizeof(float));
        av_split_k<<<GPERS, 256, GSMEM>>>(p_P_h, p_P_l, p_vt_h, p_vt_l, p_g_attno);
        cvt_hl_k<<<(int)(((long)T * HDV / 8 + 255) / 256), 256>>>(p_g_attno, p_ao_h, p_ao_l,
                                                                  (long)T * HDV);
        sgemm_split(p_ao_h, p_ao_l, p_woT_h + (size_t)l * D * D, p_woT_l + (size_t)l * D * D,
                    outbuf, T, D, HDV, HDV, HDV, D);
    };

    auto mlp = [&](int l, float* outbuf) {
        sgemm_split(p_x_h, p_x_l, p_wguT_h + (size_t)l * 2 * FF * D,
                    p_wguT_l + (size_t)l * 2 * FF * D, p_g_gu, T, 2 * FF, D, D, D, 2 * FF);
        silumul_mlp_k<<<(int)(((long)T * FF / 8 + 255) / 256), 256>>>();
        sgemm_split(p_ff_h, p_ff_l, p_wdT_h + (size_t)l * D * FF, p_wdT_l + (size_t)l * D * FF,
                    outbuf, T, D, FF, FF, FF, D);
    };

    // ================= forward =================
    mla(0, p_g_h, true);
    addnorm_hl_k<<<T, 256>>>(p_g_h, hidden, ln_post, p_g_res, p_x_h, p_x_l);

    // ---- MoE ----
    sgemm_split(p_x_h, p_x_l, p_rwT_h, p_rwT_l, p_g_logits, T, E, D, D, D, E);
    top2_k<<<(T + 255) / 256, 256>>>();
    zero_cnt_k<<<1, 32>>>();
    count_k<<<(2 * T + 255) / 256, 256>>>();
    scan_k<<<1, 32>>>();
    gather_k<<<2 * T, 256>>>();
    mgemm_split(p_mx_h, p_mx_l, p_mwguT_h, p_mwguT_l, (long)2 * EF * D,
                p_g_mgu, 2 * EF, D, D, 2 * EF, (size_t)2 * T * 2 * EF * sizeof(float));
    silumul2_k<<<(int)(((long)2 * T * EF / 8 + 255) / 256), 256>>>();
    mgemm_split(p_mh_h, p_mh_l, p_mwdT_h, p_mwdT_l, (long)D * EF,
                p_g_my, D, EF, EF, D, (size_t)2 * T * D * sizeof(float));
    moecomb_k<<<(int)(((long)T * D + 255) / 256), 256>>>();

    // ---- MLP layer 0 ----
    mlp(0, p_g_h);
    addnorm_hl_k<<<T, 256>>>(p_g_h, p_g_res, ln_in + D, p_g_res, p_x_h, p_x_l);

    // ---- layer 1 ----
    mla(1, p_g_h, false);
    addnorm_hl_k<<<T, 256>>>(p_g_h, p_g_res, ln_post + D, p_g_res, p_x_h, p_x_l);
    mlp(1, p_g_h);

    add_k<<<(int)(((long)T * D + 255) / 256), 256>>>(p_g_h, p_g_moe, out, (long)T * D);
}

// round 16
// speedup vs baseline: 1.0442x; 1.0026x over previous
#include <cuda_runtime.h>
#include <cuda_bf16.h>
#include <math.h>
#include <stdint.h>

// ---------------- constants ----------------
constexpr int T = 2048, D = 2048, H = 16, DN = 128, DR = 64, DV = 128;
constexpr int QL = 768, KL = 512, FF = 8192, E = 32, EF = 1024;
constexpr int QD = DN + DR;          // 192
constexpr int KVD = KL + DR;         // 576
constexpr int NQKV = QL + KVD;       // 1344
constexpr int KVBD = H * (DN + DV);  // 4096
constexpr int QTOT = H * QD;         // 3072
constexpr int HDV = H * DV;          // 2048

constexpr int BM = 128, BN = 128, BK = 32;
constexpr int PAD = 40;                       // smem leading dim (80B rows, 16B-aligned)
constexpr int TILE_ELEMS = 128 * PAD;         // 5120 elems = 10240 B
constexpr int GSMEM = 2 * 4 * TILE_ELEMS * 2; // 81920 B
constexpr int GPERS = 304;                    // 2 CTAs x 152 SMs

typedef __nv_bfloat16 bf16;

// ---------------- PTX helpers ----------------
__device__ __forceinline__ uint32_t smem_to_u32(const void* p) {
    uint32_t a;
    asm("{ .reg .u64 t; cvta.to.shared.u64 t, %1; cvt.u32.u64 %0, t; }" : "=r"(a) : "l"(p));
    return a;
}
__device__ __forceinline__ void cp16(uint32_t smem_dst, const void* gsrc, bool valid) {
    int sz = valid ? 16 : 0;
    asm volatile("cp.async.cg.shared.global [%0], [%1], 16, %2;\n"
                 :: "r"(smem_dst), "l"(gsrc), "r"(sz));
}
#define CP_COMMIT() asm volatile("cp.async.commit_group;\n" ::: "memory")
#define CP_WAIT0()  asm volatile("cp.async.wait_group 0;\n" ::: "memory")

__device__ __forceinline__ void ldsm_x4(uint32_t* r, uint32_t addr) {
    asm volatile("ldmatrix.sync.aligned.m8n8.x4.shared.b16 {%0,%1,%2,%3}, [%4];\n"
                 : "=r"(r[0]), "=r"(r[1]), "=r"(r[2]), "=r"(r[3]) : "r"(addr));
}
__device__ __forceinline__ void mma_bf(float* c, const uint32_t* a, uint32_t b0, uint32_t b1) {
    asm volatile(
        "mma.sync.aligned.m16n8k16.row.col.f32.bf16.bf16.f32 "
        "{%0,%1,%2,%3}, {%4,%5,%6,%7}, {%8,%9}, {%0,%1,%2,%3};\n"
        : "+f"(c[0]), "+f"(c[1]), "+f"(c[2]), "+f"(c[3])
        : "r"(a[0]), "r"(a[1]), "r"(a[2]), "r"(a[3]), "r"(b0), "r"(b1));
}

// ---------------- scratch (device globals) ----------------
__device__ float g_res[(size_t)T * D];
__device__ float g_h[(size_t)T * D];
__device__ float g_moe[(size_t)T * D];
__device__ float g_qkv[(size_t)T * NQKV];
__device__ float g_q[(size_t)T * QTOT];
__device__ float g_kvb[(size_t)T * KVBD];
__device__ float g_attno[(size_t)T * HDV];
__device__ float g_scores[(size_t)H * T * T];
__device__ float g_gu[(size_t)T * 2 * FF];
__device__ float g_mgu[(size_t)2 * T * 2 * EF];
__device__ float g_my[(size_t)2 * T * D];
__device__ float g_logits[(size_t)T * E];
// bf16 hi/lo activations
__device__ bf16 x_h[(size_t)T * D], x_l[(size_t)T * D];
__device__ bf16 qln_h[(size_t)T * QL], qln_l[(size_t)T * QL];
__device__ bf16 qq_h[(size_t)T * QTOT], qq_l[(size_t)T * QTOT];
__device__ bf16 kvcn_h[(size_t)T * KL], kvcn_l[(size_t)T * KL];
__device__ bf16 kh_h[(size_t)T * QTOT], kh_l[(size_t)T * QTOT];
__device__ bf16 vt_h[(size_t)H * DV * T], vt_l[(size_t)H * DV * T];
__device__ bf16 P_h[(size_t)H * T * T], P_l[(size_t)H * T * T];
__device__ bf16 ao_h[(size_t)T * HDV], ao_l[(size_t)T * HDV];
__device__ bf16 ff_h[(size_t)T * FF], ff_l[(size_t)T * FF];
__device__ bf16 mx_h[(size_t)2 * T * D], mx_l[(size_t)2 * T * D];
__device__ bf16 mh_h[(size_t)2 * T * EF], mh_l[(size_t)2 * T * EF];
// bf16 hi/lo weights transposed to [N][K]
__device__ bf16 wqkvT_h[(size_t)2 * NQKV * D], wqkvT_l[(size_t)2 * NQKV * D];
__device__ bf16 wqbT_h[(size_t)2 * QTOT * QL], wqbT_l[(size_t)2 * QTOT * QL];
__device__ bf16 wkvbT_h[(size_t)2 * KVBD * KL], wkvbT_l[(size_t)2 * KVBD * KL];
__device__ bf16 woT_h[(size_t)2 * D * D], woT_l[(size_t)2 * D * D];
__device__ bf16 wguT_h[(size_t)2 * 2 * FF * D], wguT_l[(size_t)2 * 2 * FF * D];
__device__ bf16 wdT_h[(size_t)2 * D * FF], wdT_l[(size_t)2 * D * FF];
__device__ bf16 rwT_h[(size_t)E * D], rwT_l[(size_t)E * D];
__device__ bf16 mwguT_h[(size_t)E * 2 * EF * D], mwguT_l[(size_t)E * 2 * EF * D];
__device__ bf16 mwdT_h[(size_t)E * D * EF], mwdT_l[(size_t)E * D * EF];
// routing
__device__ int g_expid[2 * T];
__device__ int g_slot[2 * T];
__device__ int g_rowOf[2 * T];
__device__ float g_gate[2 * T];
__device__ int g_cnt[E];
__device__ int g_off[E];

// ---------------- small helpers ----------------
__device__ __forceinline__ void wr_hl(bf16* h, bf16* l, size_t i, float x) {
    bf16 hi = __float2bfloat16(x);
    h[i] = hi;
    l[i] = __float2bfloat16(x - __bfloat162float(hi));
}
__device__ __forceinline__ void split2(float x, unsigned short& h, unsigned short& l) {
    bf16 hi = __float2bfloat16(x);
    bf16 lo = __float2bfloat16(x - __bfloat162float(hi));
    h = *(unsigned short*)&hi;
    l = *(unsigned short*)&lo;
}
__device__ __forceinline__ float blockReduceSum(float v) {
    __shared__ float sh[32];
    int lane = threadIdx.x & 31, wid = threadIdx.x >> 5;
    #pragma unroll
    for (int o = 16; o; o >>= 1) v += __shfl_down_sync(0xffffffffu, v, o);
    if (lane == 0) sh[wid] = v;
    __syncthreads();
    int nw = (blockDim.x + 31) >> 5;
    v = (threadIdx.x < nw) ? sh[threadIdx.x] : 0.f;
    if (wid == 0) {
        #pragma unroll
        for (int o = 16; o; o >>= 1) v += __shfl_down_sync(0xffffffffu, v, o);
        if (lane == 0) sh[0] = v;
    }
    __syncthreads();
    float r = sh[0];
    __syncthreads();
    return r;
}
__device__ __forceinline__ float blockReduceMax(float v) {
    __shared__ float sh[32];
    int lane = threadIdx.x & 31, wid = threadIdx.x >> 5;
    #pragma unroll
    for (int o = 16; o; o >>= 1) v = fmaxf(v, __shfl_down_sync(0xffffffffu, v, o));
    if (lane == 0) sh[wid] = v;
    __syncthreads();
    int nw = (blockDim.x + 31) >> 5;
    v = (threadIdx.x < nw) ? sh[threadIdx.x] : -1e30f;
    if (wid == 0) {
        #pragma unroll
        for (int o = 16; o; o >>= 1) v = fmaxf(v, __shfl_down_sync(0xffffffffu, v, o));
        if (lane == 0) sh[0] = v;
    }
    __syncthreads();
    float r = sh[0];
    __syncthreads();
    return r;
}

// ---- shared GEMM inner body ----
struct GemmCtx {
    uint32_t smb, aoff, boff;
    int tid, lane, wid, warp_m, warp_n, srow0, sch, rrow, rcol;
};
__device__ __forceinline__ GemmCtx make_ctx(const void* sm) {
    GemmCtx c;
    c.smb = smem_to_u32(sm);
    c.tid = threadIdx.x;
    c.lane = c.tid & 31;
    c.wid = c.tid >> 5;
    c.warp_m = c.wid >> 2;
    c.warp_n = c.wid & 3;
    c.srow0 = c.tid >> 2;
    c.sch = c.tid & 3;
    c.aoff = ((uint32_t)((c.lane & 15) * PAD) + ((c.lane >> 4) << 3)) * 2;
    c.boff = ((uint32_t)(((c.lane & 7) + ((c.lane >> 1) & 8)) * PAD) + (c.lane & 8)) * 2;
    c.rrow = c.lane >> 2;
    c.rcol = (c.lane & 3) * 2;
    return c;
}
__device__ __forceinline__ void stage_chunk(const GemmCtx& g, const bf16* Ah, const bf16* Al,
                                            const bf16* Bh, const bf16* Bl,
                                            int lda, int ldb, int bm, int bn,
                                            int rcA, int rcB, int k0, int buf) {
    uint32_t base = g.smb + (uint32_t)buf * 4 * TILE_ELEMS * 2;
    #pragma unroll
    for (int it = 0; it < 2; it++) {
        int row = g.srow0 + it * 64;
        uint32_t soff = (uint32_t)(row * PAD + g.sch * 8) * 2;
        bool vA = row < rcA;
        bool vB = row < rcB;
        long ga = (long)(bm + (vA ? row : 0)) * lda + k0 + g.sch * 8;
        long gb = (long)(bn + (vB ? row : 0)) * ldb + k0 + g.sch * 8;
        cp16(base + 0 * TILE_ELEMS * 2 + soff, Ah + ga, vA);
        cp16(base + 1 * TILE_ELEMS * 2 + soff, Al + ga, vA);
        cp16(base + 2 * TILE_ELEMS * 2 + soff, Bh + gb, vB);
        cp16(base + 3 * TILE_ELEMS * 2 + soff, Bl + gb, vB);
    }
}
__device__ __forceinline__ void compute_chunk(const GemmCtx& g, int buf, float acc[4][4][4]) {
    uint32_t base = g.smb + (uint32_t)buf * 4 * TILE_ELEMS * 2;
    uint32_t tAh = base, tAl = base + TILE_ELEMS * 2;
    uint32_t tBh = base + 2 * TILE_ELEMS * 2, tBl = base + 3 * TILE_ELEMS * 2;
    #pragma unroll
    for (int ks = 0; ks < 2; ks++) {
        uint32_t bh[2][4], bl[2][4];
        #pragma unroll
        for (int nf2 = 0; nf2 < 2; nf2++) {
            uint32_t o = (uint32_t)((g.warp_n * 32 + nf2 * 16) * PAD) * 2 + (uint32_t)(ks * 32) + g.boff;
            ldsm_x4(bh[nf2], tBh + o);
            ldsm_x4(bl[nf2], tBl + o);
        }
        #pragma unroll
        for (int mf = 0; mf < 4; mf++) {
            uint32_t ah[4], al[4];
            uint32_t o = (uint32_t)((g.warp_m * 64 + mf * 16) * PAD) * 2 + (uint32_t)(ks * 32) + g.aoff;
            ldsm_x4(ah, tAh + o);
            ldsm_x4(al, tAl + o);
            #pragma unroll
            for (int nf = 0; nf < 4; nf++) {
                int n2 = nf >> 1, pb = (nf & 1) * 2;
                float* cc = acc[mf][nf];
                mma_bf(cc, ah, bh[n2][pb], bh[n2][pb + 1]);
                mma_bf(cc, ah, bl[n2][pb], bl[n2][pb + 1]);
                mma_bf(cc, al, bh[n2][pb], bh[n2][pb + 1]);
            }
        }
    }
}

// =======================================================================
// bf16x3 GEMM (2-stage, 2 CTA/SM) — scores (cskip)
// =======================================================================
__global__ void __launch_bounds__(256, 2)
bgemm_k(const bf16* __restrict__ Ah, const bf16* __restrict__ Al,
        const bf16* __restrict__ Bh, const bf16* __restrict__ Bl,
        float* __restrict__ C, int M, int N, int K,
        int lda, int ldb, int ldc, long sA, long sB, long sC, int cskip) {
    int z = blockIdx.z;
    Ah += (long)z * sA; Al += (long)z * sA;
    Bh += (long)z * sB; Bl += (long)z * sB;
    C += (long)z * sC;
    int bid = blockIdx.y * gridDim.x + blockIdx.x;
    int mt = gridDim.y;
    int bm = (bid % mt) * BM;
    int bn = (bid / mt) * BN;
    if (bm >= M) return;
    if (cskip && bn > bm + 127) return;
    int nch = K / BK;

    extern __shared__ bf16 sm[];
    GemmCtx g = make_ctx(sm);
    float acc[4][4][4];
    #pragma unroll
    for (int i = 0; i < 4; i++)
        #pragma unroll
        for (int j = 0; j < 4; j++)
            #pragma unroll
            for (int q = 0; q < 4; q++) acc[i][j][q] = 0.f;

    int rcA = (M - bm) < BM ? (M - bm) : BM;
    int rcB = (N - bn) < BN ? (N - bn) : BN;

    stage_chunk(g, Ah, Al, Bh, Bl, lda, ldb, bm, bn, rcA, rcB, 0, 0);
    CP_COMMIT();
    for (int c = 0; c < nch; c++) {
        CP_WAIT0();
        __syncthreads();
        if (c + 1 < nch) {
            stage_chunk(g, Ah, Al, Bh, Bl, lda, ldb, bm, bn, rcA, rcB, (c + 1) * BK, (c + 1) & 1);
            CP_COMMIT();
        }
        compute_chunk(g, c & 1, acc);
        __syncthreads();
    }

    #pragma unroll
    for (int mf = 0; mf < 4; mf++)
        #pragma unroll
        for (int nf = 0; nf < 4; nf++) {
            int m0 = bm + g.warp_m * 64 + mf * 16 + g.rrow;
            int n0 = bn + g.warp_n * 32 + nf * 8 + g.rcol;
            float* cc = acc[mf][nf];
            #pragma unroll
            for (int half = 0; half < 2; half++) {
                int mm = m0 + half * 8;
                if (mm >= M) continue;
                #pragma unroll
                for (int jj = 0; jj < 2; jj++) {
                    int nn = n0 + jj;
                    if (nn < N) C[(long)mm * ldc + nn] = cc[half * 2 + jj];
                }
            }
        }
}

// =======================================================================
// Balanced-range split GEMM (plain GEMMs)
// =======================================================================
__global__ void __launch_bounds__(256, 2)
sgemm_split_k(const bf16* __restrict__ Ah, const bf16* __restrict__ Al,
              const bf16* __restrict__ Bh, const bf16* __restrict__ Bl,
              float* __restrict__ C, int M, int N, int K,
              int lda, int ldb, int ldc, int mt, int nt) {
    int nch = K / BK;
    long U = (long)mt * nt * nch;
    int G = gridDim.x;
    long u0 = (long)blockIdx.x * U / G;
    long u1 = ((long)blockIdx.x + 1) * U / G;

    extern __shared__ bf16 sm[];
    GemmCtx g = make_ctx(sm);

    while (u0 < u1) {
        int tile = (int)(u0 / nch);
        int c0 = (int)(u0 % nch);
        long rem = u1 - (long)tile * nch;
        int c1 = rem < (long)nch ? (int)rem : nch;

        int bm = (tile % mt) * BM;
        int bn = (tile / mt) * BN;
        int rcA = (M - bm) < BM ? (M - bm) : BM;
        int rcB = (N - bn) < BN ? (N - bn) : BN;
        bool full = (c0 == 0) && (c1 == nch);

        float acc[4][4][4];
        #pragma unroll
        for (int i = 0; i < 4; i++)
            #pragma unroll
            for (int j = 0; j < 4; j++)
                #pragma unroll
                for (int q = 0; q < 4; q++) acc[i][j][q] = 0.f;

        stage_chunk(g, Ah, Al, Bh, Bl, lda, ldb, bm, bn, rcA, rcB, c0 * BK, 0);
        CP_COMMIT();
        for (int c = c0; c < c1; c++) {
            CP_WAIT0();
            __syncthreads();
            if (c + 1 < c1) {
                stage_chunk(g, Ah, Al, Bh, Bl, lda, ldb, bm, bn, rcA, rcB, (c + 1) * BK,
                            (c - c0 + 1) & 1);
                CP_COMMIT();
            }
            compute_chunk(g, (c - c0) & 1, acc);
            __syncthreads();
        }

        #pragma unroll
        for (int mf = 0; mf < 4; mf++)
            #pragma unroll
            for (int nf = 0; nf < 4; nf++) {
                int m0 = bm + g.warp_m * 64 + mf * 16 + g.rrow;
                int n0 = bn + g.warp_n * 32 + nf * 8 + g.rcol;
                float* cc = acc[mf][nf];
                #pragma unroll
                for (int half = 0; half < 2; half++) {
                    int mm = m0 + half * 8;
                    if (mm >= M) continue;
                    #pragma unroll
                    for (int jj = 0; jj < 2; jj++) {
                        int nn = n0 + jj;
                        if (nn >= N) continue;
                        float v = cc[half * 2 + jj];
                        if (full) C[(long)mm * ldc + nn] = v;
                        else atomicAdd(&C[(long)mm * ldc + nn], v);
                    }
                }
            }
        __syncthreads();
        u0 = (long)tile * nch + c1;
    }
}

// =======================================================================
// Balanced MoE segmented GEMM
// =======================================================================
__global__ void __launch_bounds__(256, 2)
mgemm_split_k(const bf16* __restrict__ Ah, const bf16* __restrict__ Al,
              const bf16* __restrict__ Bh, const bf16* __restrict__ Bl, long sB,
              float* __restrict__ C, int N, int K, int lda, int ldc) {
    int nch = K / BK;
    int ntN = (N + BN - 1) / BN;
    long U = 0;
    #pragma unroll
    for (int e = 0; e < E; e++)
        U += (long)((g_cnt[e] + 127) >> 7) * ntN * nch;
    int G = gridDim.x;
    long u0 = (long)blockIdx.x * U / G;
    long u1 = ((long)blockIdx.x + 1) * U / G;

    extern __shared__ bf16 sm[];
    GemmCtx g = make_ctx(sm);

    while (u0 < u1) {
        long pre = 0;
        int e = 0, M = 0;
        for (; e < E; e++) {
            M = g_cnt[e];
            long ue = (long)((M + 127) >> 7) * ntN * nch;
            if (u0 < pre + ue) break;
            pre += ue;
        }
        int rs = g_off[e];
        long lu = u0 - pre;
        int tile = (int)(lu / nch);
        int c0 = (int)(lu % nch);
        long luend = u1 - pre;
        long tend = (long)(tile + 1) * nch;
        if (luend > tend) luend = tend;
        int c1 = (int)(luend - (long)tile * nch);
        bool full = (c0 == 0) && (c1 == nch);

        int mtiles = (M + 127) >> 7;
        int bm = (tile % mtiles) * BM;
        int bn = (tile / mtiles) * BN;
        int rcA = (M - bm) < BM ? (M - bm) : BM;
        int rcB = (N - bn) < BN ? (N - bn) : BN;

        const bf16* eAh = Ah + (long)rs * lda;
        const bf16* eAl = Al + (long)rs * lda;
        const bf16* eBh = Bh + (long)e * sB;
        const bf16* eBl = Bl + (long)e * sB;
        float* eC = C + (long)rs * ldc;

        float acc[4][4][4];
        #pragma unroll
        for (int i = 0; i < 4; i++)
            #pragma unroll
            for (int j = 0; j < 4; j++)
                #pragma unroll
                for (int q = 0; q < 4; q++) acc[i][j][q] = 0.f;

        stage_chunk(g, eAh, eAl, eBh, eBl, lda, K, bm, bn, rcA, rcB, c0 * BK, 0);
        CP_COMMIT();
        for (int c = c0; c < c1; c++) {
            CP_WAIT0();
            __syncthreads();
            if (c + 1 < c1) {
                stage_chunk(g, eAh, eAl, eBh, eBl, lda, K, bm, bn, rcA, rcB, (c + 1) * BK,
                            (c - c0 + 1) & 1);
                CP_COMMIT();
            }
            compute_chunk(g, (c - c0) & 1, acc);
            __syncthreads();
        }

        #pragma unroll
        for (int mf = 0; mf < 4; mf++)
            #pragma unroll
            for (int nf = 0; nf < 4; nf++) {
                int m0 = bm + g.warp_m * 64 + mf * 16 + g.rrow;
                int n0 = bn + g.warp_n * 32 + nf * 8 + g.rcol;
                float* cc = acc[mf][nf];
                #pragma unroll
                for (int half = 0; half < 2; half++) {
                    int mm = m0 + half * 8;
                    if (mm >= M) continue;
                    #pragma unroll
                    for (int jj = 0; jj < 2; jj++) {
                        int nn = n0 + jj;
                        if (nn >= N) continue;
                        float v = cc[half * 2 + jj];
                        if (full) eC[(long)mm * ldc + nn] = v;
                        else atomicAdd(&eC[(long)mm * ldc + nn], v);
                    }
                }
            }
        __syncthreads();
        u0 = pre + (long)tile * nch + c1;
    }
}

// =======================================================================
// Balanced AV GEMM: chunks(m)=4(m+1); U=8704
// =======================================================================
__global__ void __launch_bounds__(256, 2)
av_split_k(const bf16* __restrict__ Ph, const bf16* __restrict__ Pl,
           const bf16* __restrict__ Vh, const bf16* __restrict__ Vl,
           float* __restrict__ C) {
    const long U = 8704;
    int G = gridDim.x;
    long u0 = (long)blockIdx.x * U / G;
    long u1 = ((long)blockIdx.x + 1) * U / G;

    extern __shared__ bf16 sm[];
    GemmCtx g = make_ctx(sm);

    while (u0 < u1) {
        int h = (int)(u0 / 544);
        int rem = (int)(u0 - (long)h * 544);
        int m = 0;
        while (rem >= 2 * (m + 1) * (m + 2)) m++;
        int c0 = rem - 2 * m * (m + 1);
        int nchT = 4 * (m + 1);
        long avail = u1 - u0;
        int c1 = (c0 + avail < (long)nchT) ? (int)(c0 + avail) : nchT;
        bool full = (c0 == 0) && (c1 == nchT);
        int bm = m * 128;

        const bf16* Ah = Ph + (size_t)h * T * T;
        const bf16* Al = Pl + (size_t)h * T * T;
        const bf16* Bh = Vh + (size_t)h * 128 * T;
        const bf16* Bl = Vl + (size_t)h * 128 * T;

        float acc[4][4][4];
        #pragma unroll
        for (int i = 0; i < 4; i++)
            #pragma unroll
            for (int j = 0; j < 4; j++)
                #pragma unroll
                for (int q = 0; q < 4; q++) acc[i][j][q] = 0.f;

        stage_chunk(g, Ah, Al, Bh, Bl, T, T, bm, 0, 128, 128, c0 * BK, 0);
        CP_COMMIT();
        for (int c = c0; c < c1; c++) {
            CP_WAIT0();
            __syncthreads();
            if (c + 1 < c1) {
                stage_chunk(g, Ah, Al, Bh, Bl, T, T, bm, 0, 128, 128, (c + 1) * BK,
                            (c - c0 + 1) & 1);
                CP_COMMIT();
            }
            compute_chunk(g, (c - c0) & 1, acc);
            __syncthreads();
        }

        #pragma unroll
        for (int mf = 0; mf < 4; mf++)
            #pragma unroll
            for (int nf = 0; nf < 4; nf++) {
                int m0 = bm + g.warp_m * 64 + mf * 16 + g.rrow;
                int n0 = h * 128 + g.warp_n * 32 + nf * 8 + g.rcol;
                float* cc = acc[mf][nf];
                #pragma unroll
                for (int half = 0; half < 2; half++) {
                    int mm = m0 + half * 8;
                    #pragma unroll
                    for (int jj = 0; jj < 2; jj++) {
                        int nn = n0 + jj;
                        float v = cc[half * 2 + jj];
                        if (full) C[(long)mm * HDV + nn] = v;
                        else atomicAdd(&C[(long)mm * HDV + nn], v);
                    }
                }
            }
        __syncthreads();
        u0 += c1 - c0;
    }
}

// ---------------- vectorized weight transpose + bf16 split ----------------
__global__ void wtrans_k(const float* __restrict__ W, bf16* __restrict__ Oh,
                         bf16* __restrict__ Ol, int K, int N, long zso) {
    long z = blockIdx.z;
    W += z * (long)K * N;
    Oh += z * zso;
    Ol += z * zso;
    __shared__ float tile[64][33];
    int n0 = blockIdx.x * 32, k0 = blockIdx.y * 64;
    int tid = threadIdx.x;  // 256
    int c = tid & 31, r0 = tid >> 5;
    #pragma unroll
    for (int i = 0; i < 8; i++)
        tile[r0 + i * 8][c] = W[(long)(k0 + r0 + i * 8) * N + n0 + c];
    __syncthreads();
    int nl = tid >> 3, kc = tid & 7;
    int n = n0 + nl;
    unsigned short hi[8], lo[8];
    #pragma unroll
    for (int j = 0; j < 8; j++)
        split2(tile[kc * 8 + j][nl], hi[j], lo[j]);
    *(uint4*)(Oh + (size_t)n * K + k0 + kc * 8) = *(uint4*)hi;
    *(uint4*)(Ol + (size_t)n * K + k0 + kc * 8) = *(uint4*)lo;
}

// ---------------- elementwise / norm ----------------
__global__ void rms_hl_k(const float* __restrict__ x, const float* __restrict__ w,
                         bf16* __restrict__ oh, bf16* __restrict__ ol,
                         int cols, int ldx, int ldo) {
    long row = blockIdx.x;
    const float* xr = x + row * ldx;
    float s = 0.f;
    for (int i = threadIdx.x; i < cols; i += blockDim.x) { float v = xr[i]; s += v * v; }
    s = blockReduceSum(s);
    float sc = rsqrtf(s / cols + 1e-6f);
    for (int i = threadIdx.x; i < cols; i += blockDim.x)
        wr_hl(oh, ol, row * ldo + i, xr[i] * sc * w[i]);
}

__global__ void addnorm_hl_k(const float* __restrict__ a, const float* __restrict__ b,
                             const float* __restrict__ w, float* __restrict__ res,
                             bf16* __restrict__ oh, bf16* __restrict__ ol) {
    long row = blockIdx.x;
    const float* ar = a + row * D;
    const float* br = b + row * D;
    float* rr = res + row * D;
    float s = 0.f;
    for (int i = threadIdx.x; i < D; i += blockDim.x) {
        float v = ar[i] + br[i];
        rr[i] = v;
        s += v * v;
    }
    s = blockReduceSum(s);
    float sc = rsqrtf(s / D + 1e-6f);
    for (int i = threadIdx.x; i < D; i += blockDim.x)
        wr_hl(oh, ol, row * D + i, rr[i] * sc * w[i]);
}

// vectorized fp32 -> bf16 hi/lo (8 elems/thread); n must be multiple of 8
__global__ void cvt_hl_k(const float* __restrict__ x, bf16* __restrict__ oh,
                         bf16* __restrict__ ol, long n) {
    long i = ((long)blockIdx.x * blockDim.x + threadIdx.x) * 8;
    if (i >= n) return;
    unsigned short hi[8], lo[8];
    #pragma unroll
    for (int j = 0; j < 8; j++) split2(x[i + j], hi[j], lo[j]);
    *(uint4*)(oh + i) = *(uint4*)hi;
    *(uint4*)(ol + i) = *(uint4*)lo;
}

__global__ void rope_cvt_q_k(const float* __restrict__ q, const int* __restrict__ pos) {
    int t = blockIdx.x;
    float fp = (float)pos[t];
    for (int e = threadIdx.x; e < QTOT; e += blockDim.x) {
        int h = e / QD, d = e % QD;
        const float* qr = q + (size_t)t * QTOT + h * QD;
        float v;
        if (d < DN) {
            v = qr[d];
        } else {
            int j = d - DN;
            int i = j & 31;
            float inv = 1.f / powf(10000.f, (float)i * (2.f / 64.f));
            float sn, cs;
            sincosf(fp * inv, &sn, &cs);
            float x1 = qr[DN + i], x2 = qr[DN + i + 32];
            v = (j < 32) ? (x1 * cs - x2 * sn) : (x2 * cs + x1 * sn);
        }
        wr_hl(qq_h, qq_l, (size_t)t * QTOT + e, v);
    }
}

__global__ void build_kh_k(const int* __restrict__ pos) {
    int t = blockIdx.x;
    __shared__ float kr[64];
    int tid = threadIdx.x;
    if (tid < 32) {
        int i = tid;
        float inv = 1.f / powf(10000.f, (float)i * (2.f / 64.f));
        float sn, cs;
        sincosf((float)pos[t] * inv, &sn, &cs);
        const float* kb = g_qkv + (size_t)t * NQKV + QL + KL;
        float x1 = kb[i], x2 = kb[i + 32];
        kr[i] = x1 * cs - x2 * sn;
        kr[i + 32] = x2 * cs + x1 * sn;
    }
    __syncthreads();
    for (int e = tid; e < QTOT; e += blockDim.x) {
        int h = e / QD, d = e % QD;
        float v = (d < DN) ? g_kvb[(size_t)t * KVBD + h * (DN + DV) + d] : kr[d - DN];
        wr_hl(kh_h, kh_l, (size_t)t * QTOT + e, v);
    }
}

// =======================================================================
// build_vt: smem-transposed, vectorized stores.
// =======================================================================
__global__ void build_vt_k() {
    __shared__ float tile[64][129];
    int t0 = blockIdx.x * 64;
    int h = blockIdx.y;
    int tid = threadIdx.x;  // 256
    #pragma unroll
    for (int i = 0; i < 32; i++) {
        int idx = i * 256 + tid;
        int tt = idx >> 7, dd = idx & 127;
        tile[tt][dd] = g_kvb[(size_t)(t0 + tt) * KVBD + h * (DN + DV) + DN + dd];
    }
    __syncthreads();
    int d = tid >> 1, half = tid & 1;
    size_t obase = ((size_t)h * 128 + d) * T + t0 + half * 32;
    #pragma unroll
    for (int v = 0; v < 4; v++) {
        unsigned short hi[8], lo[8];
        #pragma unroll
        for (int j = 0; j < 8; j++)
            split2(tile[half * 32 + v * 8 + j][d], hi[j], lo[j]);
        *(uint4*)(vt_h + obase + v * 8) = *(uint4*)hi;
        *(uint4*)(vt_l + obase + v * 8) = *(uint4*)lo;
    }
}

// =======================================================================
// softmax: single global read via 8KB smem row buffer (pre-scaled by alpha)
// =======================================================================
__global__ void softmaxP_k() {
    __shared__ float buf[2048];
    int t = blockIdx.x, h = blockIdx.y;
    const float* row = g_scores + ((size_t)h * T + t) * (size_t)T;
    size_t po = ((size_t)h * T + t) * (size_t)T;
    int n = t + 1;
    const float alpha = 0.07216878364870322f;
    float m = -1e30f;
    for (int i = threadIdx.x; i < n; i += blockDim.x) {
        float v = row[i] * alpha;
        buf[i] = v;
        m = fmaxf(m, v);
    }
    m = blockReduceMax(m);
    float s = 0.f;
    for (int i = threadIdx.x; i < n; i += blockDim.x) s += expf(buf[i] - m);
    s = blockReduceSum(s);
    float inv = 1.f / s;
    for (int i = threadIdx.x; i < n; i += blockDim.x)
        wr_hl(P_h, P_l, po + i, expf(buf[i] - m) * inv);
    int fend = ((t >> 7) + 1) << 7;
    bf16 zz = __float2bfloat16(0.f);
    for (int i = n + threadIdx.x; i < fend; i += blockDim.x) { P_h[po + i] = zz; P_l[po + i] = zz; }
}

// vectorized silu*mul for dense MLP (8 elems/thread)
__global__ void silumul_mlp_k() {
    long idx = ((long)blockIdx.x * blockDim.x + threadIdx.x) * 8;
    if (idx >= (long)T * FF) return;
    long r = idx / FF;
    int c = (int)(idx % FF);
    const float* gr = g_gu + r * (2 * FF);
    unsigned short hi[8], lo[8];
    #pragma unroll
    for (int j = 0; j < 8; j++) {
        float gv = gr[c + j], u = gr[FF + c + j];
        split2(gv / (1.f + expf(-gv)) * u, hi[j], lo[j]);
    }
    *(uint4*)(ff_h + idx) = *(uint4*)hi;
    *(uint4*)(ff_l + idx) = *(uint4*)lo;
}

// vectorized silu*mul for MoE (8 elems/thread)
__global__ void silumul2_k() {
    long idx = ((long)blockIdx.x * blockDim.x + threadIdx.x) * 8;
    if (idx >= (long)2 * T * EF) return;
    long r = idx / EF;
    int c = (int)(idx % EF);
    const float* gr = g_mgu + r * (2 * EF);
    unsigned short hi[8], lo[8];
    #pragma unroll
    for (int j = 0; j < 8; j++) {
        float gv = gr[c + j], u = gr[EF + c + j];
        split2(gv / (1.f + expf(-gv)) * u, hi[j], lo[j]);
    }
    *(uint4*)(mh_h + idx) = *(uint4*)hi;
    *(uint4*)(mh_l + idx) = *(uint4*)lo;
}

// ---------------- MoE routing ----------------
__global__ void top2_k() {
    int t = blockIdx.x * blockDim.x + threadIdx.x;
    if (t >= T) return;
    const float* l = g_logits + (size_t)t * E;
    int i0 = 0;
    float v0 = l[0];
    for (int i = 1; i < E; i++)
        if (l[i] > v0) { v0 = l[i]; i0 = i; }
    int i1 = -1;
    float v1 = -1e30f;
    for (int i = 0; i < E; i++)
        if (i != i0 && l[i] > v1) { v1 = l[i]; i1 = i; }
    float e = expf(v1 - v0);
    g_expid[2 * t] = i0;
    g_expid[2 * t + 1] = i1;
    g_gate[2 * t] = 1.f / (1.f + e);
    g_gate[2 * t + 1] = e / (1.f + e);
}
__global__ void zero_cnt_k() { if (threadIdx.x < E) g_cnt[threadIdx.x] = 0; }
__global__ void count_k() {
    int p = blockIdx.x * blockDim.x + threadIdx.x;
    if (p < 2 * T) g_slot[p] = atomicAdd(&g_cnt[g_expid[p]], 1);
}
__global__ void scan_k() {
    if (threadIdx.x == 0) {
        int o = 0;
        for (int e = 0; e < E; e++) { g_off[e] = o; o += g_cnt[e]; }
    }
}
__global__ void gather_k() {
    int p = blockIdx.x;
    int row = g_off[g_expid[p]] + g_slot[p];
    if (threadIdx.x == 0) g_rowOf[p] = row;
    size_t src = (size_t)(p >> 1) * D, dst = (size_t)row * D;
    for (int i = threadIdx.x; i < D; i += blockDim.x) {
        mx_h[dst + i] = x_h[src + i];
        mx_l[dst + i] = x_l[src + i];
    }
}
__global__ void moecomb_k() {
    long idx = (long)blockIdx.x * blockDim.x + threadIdx.x;
    if (idx >= (long)T * D) return;
    long t = idx / D;
    int d = (int)(idx % D);
    g_moe[idx] = g_gate[2 * t] * g_my[(size_t)g_rowOf[2 * t] * D + d] +
                 g_gate[2 * t + 1] * g_my[(size_t)g_rowOf[2 * t + 1] * D + d];
}
__global__ void add_k(const float* __restrict__ a, const float* __restrict__ b,
                      float* __restrict__ o, long n) {
    long idx = (long)blockIdx.x * blockDim.x + threadIdx.x;
    if (idx < n) o[idx] = a[idx] + b[idx];
}

// ---------------- host side ----------------
static void bgemm_f(const bf16* Ah, const bf16* Al, const bf16* Bh, const bf16* Bl,
                    float* C, int M, int N, int K, int lda, int ldb, int ldc,
                    long sA, long sB, long sC, int batch, int cskip) {
    dim3 g((N + BN - 1) / BN, (M + BM - 1) / BM, batch);
    bgemm_k<<<g, 256, GSMEM>>>(Ah, Al, Bh, Bl, C, M, N, K, lda, ldb, ldc, sA, sB, sC, cskip);
}
static void sgemm_split(const bf16* Ah, const bf16* Al, const bf16* Bh, const bf16* Bl,
                        float* C, int M, int N, int K, int lda, int ldb, int ldc) {
    cudaMemsetAsync(C, 0, (size_t)M * ldc * sizeof(float));
    int mt = (M + BM - 1) / BM, nt = (N + BN - 1) / BN;
    long U = (long)mt * nt * (K / BK);
    int G = U < GPERS ? (int)U : GPERS;
    sgemm_split_k<<<G, 256, GSMEM>>>(Ah, Al, Bh, Bl, C, M, N, K, lda, ldb, ldc, mt, nt);
}
static void mgemm_split(const bf16* Ah, const bf16* Al, const bf16* Bh, const bf16* Bl,
                        long sB, float* C, int N, int K, int lda, int ldc, size_t csize) {
    cudaMemsetAsync(C, 0, csize);
    mgemm_split_k<<<GPERS, 256, GSMEM>>>(Ah, Al, Bh, Bl, sB, C, N, K, lda, ldc);
}

extern "C" void kernel_launch(void* const* d_in, const int* in_sizes, int n_in,
                              void* d_out, int out_size) {
    const float* hidden = (const float*)d_in[0];
    const int* pos = (const int*)d_in[1];
    const float* ln_in = (const float*)d_in[2];
    const float* ln_post = (const float*)d_in[3];
    const float* wqa = (const float*)d_in[4];
    const float* qnorm = (const float*)d_in[5];
    const float* wqb = (const float*)d_in[6];
    const float* wkva = (const float*)d_in[7];
    const float* kvnorm = (const float*)d_in[8];
    const float* wkvb = (const float*)d_in[9];
    const float* wo = (const float*)d_in[10];
    const float* wgu = (const float*)d_in[11];
    const float* wd = (const float*)d_in[12];
    const float* rw = (const float*)d_in[13];
    const float* mwg = (const float*)d_in[14];
    const float* mwu = (const float*)d_in[15];
    const float* mwd = (const float*)d_in[16];
    float* out = (float*)d_out;

    cudaFuncSetAttribute(bgemm_k, cudaFuncAttributeMaxDynamicSharedMemorySize, GSMEM);
    cudaFuncSetAttribute(sgemm_split_k, cudaFuncAttributeMaxDynamicSharedMemorySize, GSMEM);
    cudaFuncSetAttribute(mgemm_split_k, cudaFuncAttributeMaxDynamicSharedMemorySize, GSMEM);
    cudaFuncSetAttribute(av_split_k, cudaFuncAttributeMaxDynamicSharedMemorySize, GSMEM);

    void* p;
#define SYMF(name) cudaGetSymbolAddress(&p, name); float* p_##name = (float*)p;
#define SYMB(name) cudaGetSymbolAddress(&p, name); bf16* p_##name = (bf16*)p;
#define SYMI(name) cudaGetSymbolAddress(&p, name); int* p_##name = (int*)p;
    SYMF(g_res) SYMF(g_h) SYMF(g_moe) SYMF(g_qkv) SYMF(g_q) SYMF(g_kvb) SYMF(g_attno)
    SYMF(g_scores) SYMF(g_gu) SYMF(g_mgu) SYMF(g_my) SYMF(g_logits)
    SYMB(x_h) SYMB(x_l) SYMB(qln_h) SYMB(qln_l) SYMB(qq_h) SYMB(qq_l)
    SYMB(kvcn_h) SYMB(kvcn_l) SYMB(kh_h) SYMB(kh_l) SYMB(vt_h) SYMB(vt_l)
    SYMB(P_h) SYMB(P_l) SYMB(ao_h) SYMB(ao_l) SYMB(ff_h) SYMB(ff_l)
    SYMB(mx_h) SYMB(mx_l) SYMB(mh_h) SYMB(mh_l)
    SYMB(wqkvT_h) SYMB(wqkvT_l) SYMB(wqbT_h) SYMB(wqbT_l)
    SYMB(wkvbT_h) SYMB(wkvbT_l) SYMB(woT_h) SYMB(woT_l) SYMB(wguT_h) SYMB(wguT_l)
    SYMB(wdT_h) SYMB(wdT_l) SYMB(rwT_h) SYMB(rwT_l)
    SYMB(mwguT_h) SYMB(mwguT_l) SYMB(mwdT_h) SYMB(mwdT_l)
    SYMI(g_cnt) SYMI(g_off)
#undef SYMF
#undef SYMB
#undef SYMI

    long zqkv = (long)NQKV * D;

    // kernels: rms(0), wtrans(1), wtrans(2), sgemm_split(3) <- ncu target
    rms_hl_k<<<T, 256>>>(hidden, ln_in, p_x_h, p_x_l, D, D, D);
    wtrans_k<<<dim3(QL / 32, D / 64, 2), 256>>>(wqa, p_wqkvT_h, p_wqkvT_l, D, QL, zqkv);
    wtrans_k<<<dim3(KVD / 32, D / 64, 2), 256>>>(wkva, p_wqkvT_h + (size_t)QL * D,
                                                 p_wqkvT_l + (size_t)QL * D, D, KVD, zqkv);
    sgemm_split(p_x_h, p_x_l, p_wqkvT_h, p_wqkvT_l, p_g_qkv, T, NQKV, D, D, D, NQKV);
    // remaining weight preps
    wtrans_k<<<dim3(QTOT / 32, QL / 64, 2), 256>>>(wqb, p_wqbT_h, p_wqbT_l, QL, QTOT,
                                                   (long)QTOT * QL);
    wtrans_k<<<dim3(KVBD / 32, KL / 64, 2), 256>>>(wkvb, p_wkvbT_h, p_wkvbT_l, KL, KVBD,
                                                   (long)KVBD * KL);
    wtrans_k<<<dim3(D / 32, HDV / 64, 2), 256>>>(wo, p_woT_h, p_woT_l, HDV, D, (long)D * D);
    wtrans_k<<<dim3(2 * FF / 32, D / 64, 2), 256>>>(wgu, p_wguT_h, p_wguT_l, D, 2 * FF,
                                                    (long)2 * FF * D);
    wtrans_k<<<dim3(D / 32, FF / 64, 2), 256>>>(wd, p_wdT_h, p_wdT_l, FF, D, (long)D * FF);
    wtrans_k<<<dim3(E / 32, D / 64, 1), 256>>>(rw, p_rwT_h, p_rwT_l, D, E, 0);
    wtrans_k<<<dim3(EF / 32, D / 64, E), 256>>>(mwg, p_mwguT_h, p_mwguT_l, D, EF,
                                                (long)2 * EF * D);
    wtrans_k<<<dim3(EF / 32, D / 64, E), 256>>>(mwu, p_mwguT_h + (size_t)EF * D,
                                                p_mwguT_l + (size_t)EF * D, D, EF,
                                                (long)2 * EF * D);
    wtrans_k<<<dim3(D / 32, EF / 64, E), 256>>>(mwd, p_mwdT_h, p_mwdT_l, EF, D, (long)D * EF);

    auto mla = [&](int l, float* outbuf, bool qkv_done) {
        if (!qkv_done)
            sgemm_split(p_x_h, p_x_l, p_wqkvT_h + (size_t)l * zqkv, p_wqkvT_l + (size_t)l * zqkv,
                        p_g_qkv, T, NQKV, D, D, D, NQKV);
        rms_hl_k<<<T, 256>>>(p_g_qkv, qnorm + (size_t)l * QL, p_qln_h, p_qln_l, QL, NQKV, QL);
        sgemm_split(p_qln_h, p_qln_l, p_wqbT_h + (size_t)l * QTOT * QL,
                    p_wqbT_l + (size_t)l * QTOT * QL, p_g_q, T, QTOT, QL, QL, QL, QTOT);
        rms_hl_k<<<T, 256>>>(p_g_qkv + QL, kvnorm + (size_t)l * KL, p_kvcn_h, p_kvcn_l,
                             KL, NQKV, KL);
        sgemm_split(p_kvcn_h, p_kvcn_l, p_wkvbT_h + (size_t)l * KVBD * KL,
                    p_wkvbT_l + (size_t)l * KVBD * KL, p_g_kvb, T, KVBD, KL, KL, KL, KVBD);
        rope_cvt_q_k<<<T, 256>>>(p_g_q, pos);
        build_kh_k<<<T, 256>>>(pos);
        build_vt_k<<<dim3(T / 64, H), 256>>>();
        bgemm_f(p_qq_h, p_qq_l, p_kh_h, p_kh_l, p_g_scores, T, T, QD,
                QTOT, QTOT, T, QD, QD, (long)T * T, H, 1);
        softmaxP_k<<<dim3(T, H), 256>>>();
        cudaMemsetAsync(p_g_attno, 0, (size_t)T * HDV * sizeof(float));
        av_split_k<<<GPERS, 256, GSMEM>>>(p_P_h, p_P_l, p_vt_h, p_vt_l, p_g_attno);
        cvt_hl_k<<<(int)(((long)T * HDV / 8 + 255) / 256), 256>>>(p_g_attno, p_ao_h, p_ao_l,
                                                                  (long)T * HDV);
        sgemm_split(p_ao_h, p_ao_l, p_woT_h + (size_t)l * D * D, p_woT_l + (size_t)l * D * D,
                    outbuf, T, D, HDV, HDV, HDV, D);
    };

    auto mlp = [&](int l, float* outbuf) {
        sgemm_split(p_x_h, p_x_l, p_wguT_h + (size_t)l * 2 * FF * D,
                    p_wguT_l + (size_t)l * 2 * FF * D, p_g_gu, T, 2 * FF, D, D, D, 2 * FF);
        silumul_mlp_k<<<(int)(((long)T * FF / 8 + 255) / 256), 256>>>();
        sgemm_split(p_ff_h, p_ff_l, p_wdT_h + (size_t)l * D * FF, p_wdT_l + (size_t)l * D * FF,
                    outbuf, T, D, FF, FF, FF, D);
    };

    // ================= forward =================
    mla(0, p_g_h, true);
    addnorm_hl_k<<<T, 256>>>(p_g_h, hidden, ln_post, p_g_res, p_x_h, p_x_l);

    // ---- MoE ----
    sgemm_split(p_x_h, p_x_l, p_rwT_h, p_rwT_l, p_g_logits, T, E, D, D, D, E);
    top2_k<<<(T + 255) / 256, 256>>>();
    zero_cnt_k<<<1, 32>>>();
    count_k<<<(2 * T + 255) / 256, 256>>>();
    scan_k<<<1, 32>>>();
    gather_k<<<2 * T, 256>>>();
    mgemm_split(p_mx_h, p_mx_l, p_mwguT_h, p_mwguT_l, (long)2 * EF * D,
                p_g_mgu, 2 * EF, D, D, 2 * EF, (size_t)2 * T * 2 * EF * sizeof(float));
    silumul2_k<<<(int)(((long)2 * T * EF / 8 + 255) / 256), 256>>>();
    mgemm_split(p_mh_h, p_mh_l, p_mwdT_h, p_mwdT_l, (long)D * EF,
                p_g_my, D, EF, EF, D, (size_t)2 * T * D * sizeof(float));
    moecomb_k<<<(int)(((long)T * D + 255) / 256), 256>>>();

    // ---- MLP layer 0 ----
    mlp(0, p_g_h);
    addnorm_hl_k<<<T, 256>>>(p_g_h, p_g_res, ln_in + D, p_g_res, p_x_h, p_x_l);

    // ---- layer 1 ----
    mla(1, p_g_h, false);
    addnorm_hl_k<<<T, 256>>>(p_g_h, p_g_res, ln_post + D, p_g_res, p_x_h, p_x_l);
    mlp(1, p_g_h);

    add_k<<<(int)(((long)T * D + 255) / 256), 256>>>(p_g_h, p_g_moe, out, (long)T * D);
}

// round 17
// speedup vs baseline: 1.1944x; 1.1439x over previous
#include <cuda_runtime.h>
#include <cuda_bf16.h>
#include <math.h>
#include <stdint.h>

// ---------------- constants ----------------
constexpr int T = 2048, D = 2048, H = 16, DN = 128, DR = 64, DV = 128;
constexpr int QL = 768, KL = 512, FF = 8192, E = 32, EF = 1024;
constexpr int QD = DN + DR;          // 192
constexpr int KVD = KL + DR;         // 576
constexpr int NQKV = QL + KVD;       // 1344
constexpr int KVBD = H * (DN + DV);  // 4096
constexpr int QTOT = H * QD;         // 3072
constexpr int HDV = H * DV;          // 2048

constexpr int BM = 128, BN = 128, BK = 32;
constexpr int TILE_BYTES = 128 * 64;          // 64B rows (XOR chunk swizzle), 8192 B
constexpr int STAGES = 3;
constexpr int GSMEM = STAGES * 4 * TILE_BYTES;  // 98304 B -> 2 CTA/SM
constexpr int GPERS = 304;                    // 2 CTAs x 152 SMs

typedef __nv_bfloat16 bf16;

// ---------------- PTX helpers ----------------
__device__ __forceinline__ uint32_t smem_to_u32(const void* p) {
    uint32_t a;
    asm("{ .reg .u64 t; cvta.to.shared.u64 t, %1; cvt.u32.u64 %0, t; }" : "=r"(a) : "l"(p));
    return a;
}
__device__ __forceinline__ void cp16(uint32_t smem_dst, const void* gsrc, bool valid) {
    int sz = valid ? 16 : 0;
    asm volatile("cp.async.cg.shared.global [%0], [%1], 16, %2;\n"
                 :: "r"(smem_dst), "l"(gsrc), "r"(sz));
}
#define CP_COMMIT() asm volatile("cp.async.commit_group;\n" ::: "memory")
#define CP_WAIT1()  asm volatile("cp.async.wait_group 1;\n" ::: "memory")

__device__ __forceinline__ void ldsm_x4(uint32_t* r, uint32_t addr) {
    asm volatile("ldmatrix.sync.aligned.m8n8.x4.shared.b16 {%0,%1,%2,%3}, [%4];\n"
                 : "=r"(r[0]), "=r"(r[1]), "=r"(r[2]), "=r"(r[3]) : "r"(addr));
}
__device__ __forceinline__ void mma_bf(float* c, const uint32_t* a, uint32_t b0, uint32_t b1) {
    asm volatile(
        "mma.sync.aligned.m16n8k16.row.col.f32.bf16.bf16.f32 "
        "{%0,%1,%2,%3}, {%4,%5,%6,%7}, {%8,%9}, {%0,%1,%2,%3};\n"
        : "+f"(c[0]), "+f"(c[1]), "+f"(c[2]), "+f"(c[3])
        : "r"(a[0]), "r"(a[1]), "r"(a[2]), "r"(a[3]), "r"(b0), "r"(b1));
}
// swizzled byte offset within a tile: 64B rows, 16B chunks, phys = ch ^ ((row>>1)&3)
__device__ __forceinline__ uint32_t swz(int row, int ch) {
    return (uint32_t)(row * 64 + ((ch ^ ((row >> 1) & 3)) << 4));
}

// ---------------- scratch (device globals) ----------------
__device__ float g_res[(size_t)T * D];
__device__ float g_h[(size_t)T * D];
__device__ float g_moe[(size_t)T * D];
__device__ float g_qkv[(size_t)T * NQKV];
__device__ float g_q[(size_t)T * QTOT];
__device__ float g_kvb[(size_t)T * KVBD];
__device__ float g_attno[(size_t)T * HDV];
__device__ float g_scores[(size_t)H * T * T];
__device__ float g_gu[(size_t)T * 2 * FF];
__device__ float g_mgu[(size_t)2 * T * 2 * EF];
__device__ float g_my[(size_t)2 * T * D];
__device__ float g_logits[(size_t)T * E];
// bf16 hi/lo activations
__device__ bf16 x_h[(size_t)T * D], x_l[(size_t)T * D];
__device__ bf16 qln_h[(size_t)T * QL], qln_l[(size_t)T * QL];
__device__ bf16 qq_h[(size_t)T * QTOT], qq_l[(size_t)T * QTOT];
__device__ bf16 kvcn_h[(size_t)T * KL], kvcn_l[(size_t)T * KL];
__device__ bf16 kh_h[(size_t)T * QTOT], kh_l[(size_t)T * QTOT];
__device__ bf16 vt_h[(size_t)H * DV * T], vt_l[(size_t)H * DV * T];
__device__ bf16 P_h[(size_t)H * T * T], P_l[(size_t)H * T * T];
__device__ bf16 ao_h[(size_t)T * HDV], ao_l[(size_t)T * HDV];
__device__ bf16 ff_h[(size_t)T * FF], ff_l[(size_t)T * FF];
__device__ bf16 mx_h[(size_t)2 * T * D], mx_l[(size_t)2 * T * D];
__device__ bf16 mh_h[(size_t)2 * T * EF], mh_l[(size_t)2 * T * EF];
// bf16 hi/lo weights transposed to [N][K]
__device__ bf16 wqkvT_h[(size_t)2 * NQKV * D], wqkvT_l[(size_t)2 * NQKV * D];
__device__ bf16 wqbT_h[(size_t)2 * QTOT * QL], wqbT_l[(size_t)2 * QTOT * QL];
__device__ bf16 wkvbT_h[(size_t)2 * KVBD * KL], wkvbT_l[(size_t)2 * KVBD * KL];
__device__ bf16 woT_h[(size_t)2 * D * D], woT_l[(size_t)2 * D * D];
__device__ bf16 wguT_h[(size_t)2 * 2 * FF * D], wguT_l[(size_t)2 * 2 * FF * D];
__device__ bf16 wdT_h[(size_t)2 * D * FF], wdT_l[(size_t)2 * D * FF];
__device__ bf16 rwT_h[(size_t)E * D], rwT_l[(size_t)E * D];
__device__ bf16 mwguT_h[(size_t)E * 2 * EF * D], mwguT_l[(size_t)E * 2 * EF * D];
__device__ bf16 mwdT_h[(size_t)E * D * EF], mwdT_l[(size_t)E * D * EF];
// routing
__device__ int g_expid[2 * T];
__device__ int g_slot[2 * T];
__device__ int g_rowOf[2 * T];
__device__ float g_gate[2 * T];
__device__ int g_cnt[E];
__device__ int g_off[E];

// ---------------- small helpers ----------------
__device__ __forceinline__ void wr_hl(bf16* h, bf16* l, size_t i, float x) {
    bf16 hi = __float2bfloat16(x);
    h[i] = hi;
    l[i] = __float2bfloat16(x - __bfloat162float(hi));
}
__device__ __forceinline__ void split2(float x, unsigned short& h, unsigned short& l) {
    bf16 hi = __float2bfloat16(x);
    bf16 lo = __float2bfloat16(x - __bfloat162float(hi));
    h = *(unsigned short*)&hi;
    l = *(unsigned short*)&lo;
}
__device__ __forceinline__ float blockReduceSum(float v) {
    __shared__ float sh[32];
    int lane = threadIdx.x & 31, wid = threadIdx.x >> 5;
    #pragma unroll
    for (int o = 16; o; o >>= 1) v += __shfl_down_sync(0xffffffffu, v, o);
    if (lane == 0) sh[wid] = v;
    __syncthreads();
    int nw = (blockDim.x + 31) >> 5;
    v = (threadIdx.x < nw) ? sh[threadIdx.x] : 0.f;
    if (wid == 0) {
        #pragma unroll
        for (int o = 16; o; o >>= 1) v += __shfl_down_sync(0xffffffffu, v, o);
        if (lane == 0) sh[0] = v;
    }
    __syncthreads();
    float r = sh[0];
    __syncthreads();
    return r;
}
__device__ __forceinline__ float blockReduceMax(float v) {
    __shared__ float sh[32];
    int lane = threadIdx.x & 31, wid = threadIdx.x >> 5;
    #pragma unroll
    for (int o = 16; o; o >>= 1) v = fmaxf(v, __shfl_down_sync(0xffffffffu, v, o));
    if (lane == 0) sh[wid] = v;
    __syncthreads();
    int nw = (blockDim.x + 31) >> 5;
    v = (threadIdx.x < nw) ? sh[threadIdx.x] : -1e30f;
    if (wid == 0) {
        #pragma unroll
        for (int o = 16; o; o >>= 1) v = fmaxf(v, __shfl_down_sync(0xffffffffu, v, o));
        if (lane == 0) sh[0] = v;
    }
    __syncthreads();
    float r = sh[0];
    __syncthreads();
    return r;
}

// ---- shared GEMM inner body (XOR-swizzled 64B rows) ----
struct GemmCtx {
    uint32_t smb;
    int tid, lane, wid, warp_m, warp_n, srow0, sch, rrow, rcol;
    int a_r, a_c, b_r, b_c;  // per-lane fragment row/chunk components
};
__device__ __forceinline__ GemmCtx make_ctx(const void* sm) {
    GemmCtx c;
    c.smb = smem_to_u32(sm);
    c.tid = threadIdx.x;
    c.lane = c.tid & 31;
    c.wid = c.tid >> 5;
    c.warp_m = c.wid >> 2;
    c.warp_n = c.wid & 3;
    c.srow0 = c.tid >> 2;
    c.sch = c.tid & 3;
    c.a_r = c.lane & 15;
    c.a_c = c.lane >> 4;
    c.b_r = (c.lane & 7) + ((c.lane >> 1) & 8);
    c.b_c = (c.lane & 8) >> 3;
    c.rrow = c.lane >> 2;
    c.rcol = (c.lane & 3) * 2;
    return c;
}
__device__ __forceinline__ void stage_chunk(const GemmCtx& g, const bf16* Ah, const bf16* Al,
                                            const bf16* Bh, const bf16* Bl,
                                            int lda, int ldb, int bm, int bn,
                                            int rcA, int rcB, int k0, int buf) {
    uint32_t base = g.smb + (uint32_t)buf * 4 * TILE_BYTES;
    #pragma unroll
    for (int it = 0; it < 2; it++) {
        int row = g.srow0 + it * 64;
        uint32_t soff = swz(row, g.sch);
        bool vA = row < rcA;
        bool vB = row < rcB;
        long ga = (long)(bm + (vA ? row : 0)) * lda + k0 + g.sch * 8;
        long gb = (long)(bn + (vB ? row : 0)) * ldb + k0 + g.sch * 8;
        cp16(base + 0 * TILE_BYTES + soff, Ah + ga, vA);
        cp16(base + 1 * TILE_BYTES + soff, Al + ga, vA);
        cp16(base + 2 * TILE_BYTES + soff, Bh + gb, vB);
        cp16(base + 3 * TILE_BYTES + soff, Bl + gb, vB);
    }
}
__device__ __forceinline__ void compute_chunk(const GemmCtx& g, int buf, float acc[4][4][4]) {
    uint32_t base = g.smb + (uint32_t)buf * 4 * TILE_BYTES;
    uint32_t tAh = base, tAl = base + TILE_BYTES;
    uint32_t tBh = base + 2 * TILE_BYTES, tBl = base + 3 * TILE_BYTES;
    #pragma unroll
    for (int ks = 0; ks < 2; ks++) {
        uint32_t bh[2][4], bl[2][4];
        #pragma unroll
        for (int nf2 = 0; nf2 < 2; nf2++) {
            int r = g.warp_n * 32 + nf2 * 16 + g.b_r;
            uint32_t o = swz(r, ks * 2 + g.b_c);
            ldsm_x4(bh[nf2], tBh + o);
            ldsm_x4(bl[nf2], tBl + o);
        }
        #pragma unroll
        for (int mf = 0; mf < 4; mf++) {
            int r = g.warp_m * 64 + mf * 16 + g.a_r;
            uint32_t o = swz(r, ks * 2 + g.a_c);
            uint32_t ah[4], al[4];
            ldsm_x4(ah, tAh + o);
            ldsm_x4(al, tAl + o);
            #pragma unroll
            for (int nf = 0; nf < 4; nf++) {
                int n2 = nf >> 1, pb = (nf & 1) * 2;
                float* cc = acc[mf][nf];
                mma_bf(cc, ah, bh[n2][pb], bh[n2][pb + 1]);
                mma_bf(cc, ah, bl[n2][pb], bl[n2][pb + 1]);
                mma_bf(cc, al, bh[n2][pb], bh[n2][pb + 1]);
            }
        }
    }
}

// =======================================================================
// bf16x3 GEMM (3-stage, 2 CTA/SM) — scores (cskip)
// =======================================================================
__global__ void __launch_bounds__(256, 2)
bgemm_k(const bf16* __restrict__ Ah, const bf16* __restrict__ Al,
        const bf16* __restrict__ Bh, const bf16* __restrict__ Bl,
        float* __restrict__ C, int M, int N, int K,
        int lda, int ldb, int ldc, long sA, long sB, long sC, int cskip) {
    int z = blockIdx.z;
    Ah += (long)z * sA; Al += (long)z * sA;
    Bh += (long)z * sB; Bl += (long)z * sB;
    C += (long)z * sC;
    int bid = blockIdx.y * gridDim.x + blockIdx.x;
    int mt = gridDim.y;
    int bm = (bid % mt) * BM;
    int bn = (bid / mt) * BN;
    if (bm >= M) return;
    if (cskip && bn > bm + 127) return;
    int nch = K / BK;

    extern __shared__ bf16 sm[];
    GemmCtx g = make_ctx(sm);
    float acc[4][4][4];
    #pragma unroll
    for (int i = 0; i < 4; i++)
        #pragma unroll
        for (int j = 0; j < 4; j++)
            #pragma unroll
            for (int q = 0; q < 4; q++) acc[i][j][q] = 0.f;

    int rcA = (M - bm) < BM ? (M - bm) : BM;
    int rcB = (N - bn) < BN ? (N - bn) : BN;

    stage_chunk(g, Ah, Al, Bh, Bl, lda, ldb, bm, bn, rcA, rcB, 0, 0);
    CP_COMMIT();
    if (nch > 1) stage_chunk(g, Ah, Al, Bh, Bl, lda, ldb, bm, bn, rcA, rcB, BK, 1);
    CP_COMMIT();

    int bi = 0;
    for (int c = 0; c < nch; c++) {
        CP_WAIT1();
        __syncthreads();
        int pf = c + 2;
        int pb = bi + 2; if (pb >= 3) pb -= 3;
        if (pf < nch) stage_chunk(g, Ah, Al, Bh, Bl, lda, ldb, bm, bn, rcA, rcB, pf * BK, pb);
        CP_COMMIT();
        compute_chunk(g, bi, acc);
        bi = bi + 1 == 3 ? 0 : bi + 1;
    }

    #pragma unroll
    for (int mf = 0; mf < 4; mf++)
        #pragma unroll
        for (int nf = 0; nf < 4; nf++) {
            int m0 = bm + g.warp_m * 64 + mf * 16 + g.rrow;
            int n0 = bn + g.warp_n * 32 + nf * 8 + g.rcol;
            float* cc = acc[mf][nf];
            #pragma unroll
            for (int half = 0; half < 2; half++) {
                int mm = m0 + half * 8;
                if (mm >= M) continue;
                #pragma unroll
                for (int jj = 0; jj < 2; jj++) {
                    int nn = n0 + jj;
                    if (nn < N) C[(long)mm * ldc + nn] = cc[half * 2 + jj];
                }
            }
        }
}

// =======================================================================
// Balanced-range split GEMM (plain GEMMs)
// =======================================================================
__global__ void __launch_bounds__(256, 2)
sgemm_split_k(const bf16* __restrict__ Ah, const bf16* __restrict__ Al,
              const bf16* __restrict__ Bh, const bf16* __restrict__ Bl,
              float* __restrict__ C, int M, int N, int K,
              int lda, int ldb, int ldc, int mt, int nt) {
    int nch = K / BK;
    long U = (long)mt * nt * nch;
    int G = gridDim.x;
    long u0 = (long)blockIdx.x * U / G;
    long u1 = ((long)blockIdx.x + 1) * U / G;

    extern __shared__ bf16 sm[];
    GemmCtx g = make_ctx(sm);

    while (u0 < u1) {
        int tile = (int)(u0 / nch);
        int c0 = (int)(u0 % nch);
        long rem = u1 - (long)tile * nch;
        int c1 = rem < (long)nch ? (int)rem : nch;

        int bm = (tile % mt) * BM;
        int bn = (tile / mt) * BN;
        int rcA = (M - bm) < BM ? (M - bm) : BM;
        int rcB = (N - bn) < BN ? (N - bn) : BN;
        bool full = (c0 == 0) && (c1 == nch);

        float acc[4][4][4];
        #pragma unroll
        for (int i = 0; i < 4; i++)
            #pragma unroll
            for (int j = 0; j < 4; j++)
                #pragma unroll
                for (int q = 0; q < 4; q++) acc[i][j][q] = 0.f;

        stage_chunk(g, Ah, Al, Bh, Bl, lda, ldb, bm, bn, rcA, rcB, c0 * BK, 0);
        CP_COMMIT();
        if (c0 + 1 < c1) stage_chunk(g, Ah, Al, Bh, Bl, lda, ldb, bm, bn, rcA, rcB,
                                     (c0 + 1) * BK, 1);
        CP_COMMIT();

        int bi = 0;
        for (int c = c0; c < c1; c++) {
            CP_WAIT1();
            __syncthreads();
            int pf = c + 2;
            int pb = bi + 2; if (pb >= 3) pb -= 3;
            if (pf < c1) stage_chunk(g, Ah, Al, Bh, Bl, lda, ldb, bm, bn, rcA, rcB, pf * BK, pb);
            CP_COMMIT();
            compute_chunk(g, bi, acc);
            bi = bi + 1 == 3 ? 0 : bi + 1;
        }
        __syncthreads();  // all warps done before next segment reuses smem

        #pragma unroll
        for (int mf = 0; mf < 4; mf++)
            #pragma unroll
            for (int nf = 0; nf < 4; nf++) {
                int m0 = bm + g.warp_m * 64 + mf * 16 + g.rrow;
                int n0 = bn + g.warp_n * 32 + nf * 8 + g.rcol;
                float* cc = acc[mf][nf];
                #pragma unroll
                for (int half = 0; half < 2; half++) {
                    int mm = m0 + half * 8;
                    if (mm >= M) continue;
                    #pragma unroll
                    for (int jj = 0; jj < 2; jj++) {
                        int nn = n0 + jj;
                        if (nn >= N) continue;
                        float v = cc[half * 2 + jj];
                        if (full) C[(long)mm * ldc + nn] = v;
                        else atomicAdd(&C[(long)mm * ldc + nn], v);
                    }
                }
            }
        u0 = (long)tile * nch + c1;
    }
}

// =======================================================================
// Balanced MoE segmented GEMM
// =======================================================================
__global__ void __launch_bounds__(256, 2)
mgemm_split_k(const bf16* __restrict__ Ah, const bf16* __restrict__ Al,
              const bf16* __restrict__ Bh, const bf16* __restrict__ Bl, long sB,
              float* __restrict__ C, int N, int K, int lda, int ldc) {
    int nch = K / BK;
    int ntN = (N + BN - 1) / BN;
    long U = 0;
    #pragma unroll
    for (int e = 0; e < E; e++)
        U += (long)((g_cnt[e] + 127) >> 7) * ntN * nch;
    int G = gridDim.x;
    long u0 = (long)blockIdx.x * U / G;
    long u1 = ((long)blockIdx.x + 1) * U / G;

    extern __shared__ bf16 sm[];
    GemmCtx g = make_ctx(sm);

    while (u0 < u1) {
        long pre = 0;
        int e = 0, M = 0;
        for (; e < E; e++) {
            M = g_cnt[e];
            long ue = (long)((M + 127) >> 7) * ntN * nch;
            if (u0 < pre + ue) break;
            pre += ue;
        }
        int rs = g_off[e];
        long lu = u0 - pre;
        int tile = (int)(lu / nch);
        int c0 = (int)(lu % nch);
        long luend = u1 - pre;
        long tend = (long)(tile + 1) * nch;
        if (luend > tend) luend = tend;
        int c1 = (int)(luend - (long)tile * nch);
        bool full = (c0 == 0) && (c1 == nch);

        int mtiles = (M + 127) >> 7;
        int bm = (tile % mtiles) * BM;
        int bn = (tile / mtiles) * BN;
        int rcA = (M - bm) < BM ? (M - bm) : BM;
        int rcB = (N - bn) < BN ? (N - bn) : BN;

        const bf16* eAh = Ah + (long)rs * lda;
        const bf16* eAl = Al + (long)rs * lda;
        const bf16* eBh = Bh + (long)e * sB;
        const bf16* eBl = Bl + (long)e * sB;
        float* eC = C + (long)rs * ldc;

        float acc[4][4][4];
        #pragma unroll
        for (int i = 0; i < 4; i++)
            #pragma unroll
            for (int j = 0; j < 4; j++)
                #pragma unroll
                for (int q = 0; q < 4; q++) acc[i][j][q] = 0.f;

        stage_chunk(g, eAh, eAl, eBh, eBl, lda, K, bm, bn, rcA, rcB, c0 * BK, 0);
        CP_COMMIT();
        if (c0 + 1 < c1) stage_chunk(g, eAh, eAl, eBh, eBl, lda, K, bm, bn, rcA, rcB,
                                     (c0 + 1) * BK, 1);
        CP_COMMIT();

        int bi = 0;
        for (int c = c0; c < c1; c++) {
            CP_WAIT1();
            __syncthreads();
            int pf = c + 2;
            int pb = bi + 2; if (pb >= 3) pb -= 3;
            if (pf < c1) stage_chunk(g, eAh, eAl, eBh, eBl, lda, K, bm, bn, rcA, rcB,
                                     pf * BK, pb);
            CP_COMMIT();
            compute_chunk(g, bi, acc);
            bi = bi + 1 == 3 ? 0 : bi + 1;
        }
        __syncthreads();

        #pragma unroll
        for (int mf = 0; mf < 4; mf++)
            #pragma unroll
            for (int nf = 0; nf < 4; nf++) {
                int m0 = bm + g.warp_m * 64 + mf * 16 + g.rrow;
                int n0 = bn + g.warp_n * 32 + nf * 8 + g.rcol;
                float* cc = acc[mf][nf];
                #pragma unroll
                for (int half = 0; half < 2; half++) {
                    int mm = m0 + half * 8;
                    if (mm >= M) continue;
                    #pragma unroll
                    for (int jj = 0; jj < 2; jj++) {
                        int nn = n0 + jj;
                        if (nn >= N) continue;
                        float v = cc[half * 2 + jj];
                        if (full) eC[(long)mm * ldc + nn] = v;
                        else atomicAdd(&eC[(long)mm * ldc + nn], v);
                    }
                }
            }
        u0 = pre + (long)tile * nch + c1;
    }
}

// =======================================================================
// Balanced AV GEMM: chunks(m)=4(m+1); U=8704
// =======================================================================
__global__ void __launch_bounds__(256, 2)
av_split_k(const bf16* __restrict__ Ph, const bf16* __restrict__ Pl,
           const bf16* __restrict__ Vh, const bf16* __restrict__ Vl,
           float* __restrict__ C) {
    const long U = 8704;
    int G = gridDim.x;
    long u0 = (long)blockIdx.x * U / G;
    long u1 = ((long)blockIdx.x + 1) * U / G;

    extern __shared__ bf16 sm[];
    GemmCtx g = make_ctx(sm);

    while (u0 < u1) {
        int h = (int)(u0 / 544);
        int rem = (int)(u0 - (long)h * 544);
        int m = 0;
        while (rem >= 2 * (m + 1) * (m + 2)) m++;
        int c0 = rem - 2 * m * (m + 1);
        int nchT = 4 * (m + 1);
        long avail = u1 - u0;
        int c1 = (c0 + avail < (long)nchT) ? (int)(c0 + avail) : nchT;
        bool full = (c0 == 0) && (c1 == nchT);
        int bm = m * 128;

        const bf16* Ah = Ph + (size_t)h * T * T;
        const bf16* Al = Pl + (size_t)h * T * T;
        const bf16* Bh = Vh + (size_t)h * 128 * T;
        const bf16* Bl = Vl + (size_t)h * 128 * T;

        float acc[4][4][4];
        #pragma unroll
        for (int i = 0; i < 4; i++)
            #pragma unroll
            for (int j = 0; j < 4; j++)
                #pragma unroll
                for (int q = 0; q < 4; q++) acc[i][j][q] = 0.f;

        stage_chunk(g, Ah, Al, Bh, Bl, T, T, bm, 0, 128, 128, c0 * BK, 0);
        CP_COMMIT();
        if (c0 + 1 < c1) stage_chunk(g, Ah, Al, Bh, Bl, T, T, bm, 0, 128, 128,
                                     (c0 + 1) * BK, 1);
        CP_COMMIT();

        int bi = 0;
        for (int c = c0; c < c1; c++) {
            CP_WAIT1();
            __syncthreads();
            int pf = c + 2;
            int pb = bi + 2; if (pb >= 3) pb -= 3;
            if (pf < c1) stage_chunk(g, Ah, Al, Bh, Bl, T, T, bm, 0, 128, 128, pf * BK, pb);
            CP_COMMIT();
            compute_chunk(g, bi, acc);
            bi = bi + 1 == 3 ? 0 : bi + 1;
        }
        __syncthreads();

        #pragma unroll
        for (int mf = 0; mf < 4; mf++)
            #pragma unroll
            for (int nf = 0; nf < 4; nf++) {
                int m0 = bm + g.warp_m * 64 + mf * 16 + g.rrow;
                int n0 = h * 128 + g.warp_n * 32 + nf * 8 + g.rcol;
                float* cc = acc[mf][nf];
                #pragma unroll
                for (int half = 0; half < 2; half++) {
                    int mm = m0 + half * 8;
                    #pragma unroll
                    for (int jj = 0; jj < 2; jj++) {
                        int nn = n0 + jj;
                        float v = cc[half * 2 + jj];
                        if (full) C[(long)mm * HDV + nn] = v;
                        else atomicAdd(&C[(long)mm * HDV + nn], v);
                    }
                }
            }
        u0 += c1 - c0;
    }
}

// ---------------- vectorized weight transpose + bf16 split ----------------
__global__ void wtrans_k(const float* __restrict__ W, bf16* __restrict__ Oh,
                         bf16* __restrict__ Ol, int K, int N, long zso) {
    long z = blockIdx.z;
    W += z * (long)K * N;
    Oh += z * zso;
    Ol += z * zso;
    __shared__ float tile[64][33];
    int n0 = blockIdx.x * 32, k0 = blockIdx.y * 64;
    int tid = threadIdx.x;  // 256
    int c = tid & 31, r0 = tid >> 5;
    #pragma unroll
    for (int i = 0; i < 8; i++)
        tile[r0 + i * 8][c] = W[(long)(k0 + r0 + i * 8) * N + n0 + c];
    __syncthreads();
    int nl = tid >> 3, kc = tid & 7;
    int n = n0 + nl;
    unsigned short hi[8], lo[8];
    #pragma unroll
    for (int j = 0; j < 8; j++)
        split2(tile[kc * 8 + j][nl], hi[j], lo[j]);
    *(uint4*)(Oh + (size_t)n * K + k0 + kc * 8) = *(uint4*)hi;
    *(uint4*)(Ol + (size_t)n * K + k0 + kc * 8) = *(uint4*)lo;
}

// ---------------- elementwise / norm ----------------
__global__ void rms_hl_k(const float* __restrict__ x, const float* __restrict__ w,
                         bf16* __restrict__ oh, bf16* __restrict__ ol,
                         int cols, int ldx, int ldo) {
    long row = blockIdx.x;
    const float* xr = x + row * ldx;
    float s = 0.f;
    for (int i = threadIdx.x; i < cols; i += blockDim.x) { float v = xr[i]; s += v * v; }
    s = blockReduceSum(s);
    float sc = rsqrtf(s / cols + 1e-6f);
    for (int i = threadIdx.x; i < cols; i += blockDim.x)
        wr_hl(oh, ol, row * ldo + i, xr[i] * sc * w[i]);
}

__global__ void addnorm_hl_k(const float* __restrict__ a, const float* __restrict__ b,
                             const float* __restrict__ w, float* __restrict__ res,
                             bf16* __restrict__ oh, bf16* __restrict__ ol) {
    long row = blockIdx.x;
    const float* ar = a + row * D;
    const float* br = b + row * D;
    float* rr = res + row * D;
    float s = 0.f;
    for (int i = threadIdx.x; i < D; i += blockDim.x) {
        float v = ar[i] + br[i];
        rr[i] = v;
        s += v * v;
    }
    s = blockReduceSum(s);
    float sc = rsqrtf(s / D + 1e-6f);
    for (int i = threadIdx.x; i < D; i += blockDim.x)
        wr_hl(oh, ol, row * D + i, rr[i] * sc * w[i]);
}

__global__ void cvt_hl_k(const float* __restrict__ x, bf16* __restrict__ oh,
                         bf16* __restrict__ ol, long n) {
    long i = ((long)blockIdx.x * blockDim.x + threadIdx.x) * 8;
    if (i >= n) return;
    unsigned short hi[8], lo[8];
    #pragma unroll
    for (int j = 0; j < 8; j++) split2(x[i + j], hi[j], lo[j]);
    *(uint4*)(oh + i) = *(uint4*)hi;
    *(uint4*)(ol + i) = *(uint4*)lo;
}

__global__ void rope_cvt_q_k(const float* __restrict__ q, const int* __restrict__ pos) {
    int t = blockIdx.x;
    float fp = (float)pos[t];
    for (int e = threadIdx.x; e < QTOT; e += blockDim.x) {
        int h = e / QD, d = e % QD;
        const float* qr = q + (size_t)t * QTOT + h * QD;
        float v;
        if (d < DN) {
            v = qr[d];
        } else {
            int j = d - DN;
            int i = j & 31;
            float inv = 1.f / powf(10000.f, (float)i * (2.f / 64.f));
            float sn, cs;
            sincosf(fp * inv, &sn, &cs);
            float x1 = qr[DN + i], x2 = qr[DN + i + 32];
            v = (j < 32) ? (x1 * cs - x2 * sn) : (x2 * cs + x1 * sn);
        }
        wr_hl(qq_h, qq_l, (size_t)t * QTOT + e, v);
    }
}

__global__ void build_kh_k(const int* __restrict__ pos) {
    int t = blockIdx.x;
    __shared__ float kr[64];
    int tid = threadIdx.x;
    if (tid < 32) {
        int i = tid;
        float inv = 1.f / powf(10000.f, (float)i * (2.f / 64.f));
        float sn, cs;
        sincosf((float)pos[t] * inv, &sn, &cs);
        const float* kb = g_qkv + (size_t)t * NQKV + QL + KL;
        float x1 = kb[i], x2 = kb[i + 32];
        kr[i] = x1 * cs - x2 * sn;
        kr[i + 32] = x2 * cs + x1 * sn;
    }
    __syncthreads();
    for (int e = tid; e < QTOT; e += blockDim.x) {
        int h = e / QD, d = e % QD;
        float v = (d < DN) ? g_kvb[(size_t)t * KVBD + h * (DN + DV) + d] : kr[d - DN];
        wr_hl(kh_h, kh_l, (size_t)t * QTOT + e, v);
    }
}

// build_vt: smem-transposed, vectorized stores
__global__ void build_vt_k() {
    __shared__ float tile[64][129];
    int t0 = blockIdx.x * 64;
    int h = blockIdx.y;
    int tid = threadIdx.x;  // 256
    #pragma unroll
    for (int i = 0; i < 32; i++) {
        int idx = i * 256 + tid;
        int tt = idx >> 7, dd = idx & 127;
        tile[tt][dd] = g_kvb[(size_t)(t0 + tt) * KVBD + h * (DN + DV) + DN + dd];
    }
    __syncthreads();
    int d = tid >> 1, half = tid & 1;
    size_t obase = ((size_t)h * 128 + d) * T + t0 + half * 32;
    #pragma unroll
    for (int v = 0; v < 4; v++) {
        unsigned short hi[8], lo[8];
        #pragma unroll
        for (int j = 0; j < 8; j++)
            split2(tile[half * 32 + v * 8 + j][d], hi[j], lo[j]);
        *(uint4*)(vt_h + obase + v * 8) = *(uint4*)hi;
        *(uint4*)(vt_l + obase + v * 8) = *(uint4*)lo;
    }
}

// softmax: single global read via 8KB smem row buffer
__global__ void softmaxP_k() {
    __shared__ float buf[2048];
    int t = blockIdx.x, h = blockIdx.y;
    const float* row = g_scores + ((size_t)h * T + t) * (size_t)T;
    size_t po = ((size_t)h * T + t) * (size_t)T;
    int n = t + 1;
    const float alpha = 0.07216878364870322f;
    float m = -1e30f;
    for (int i = threadIdx.x; i < n; i += blockDim.x) {
        float v = row[i] * alpha;
        buf[i] = v;
        m = fmaxf(m, v);
    }
    m = blockReduceMax(m);
    float s = 0.f;
    for (int i = threadIdx.x; i < n; i += blockDim.x) s += expf(buf[i] - m);
    s = blockReduceSum(s);
    float inv = 1.f / s;
    for (int i = threadIdx.x; i < n; i += blockDim.x)
        wr_hl(P_h, P_l, po + i, expf(buf[i] - m) * inv);
    int fend = ((t >> 7) + 1) << 7;
    bf16 zz = __float2bfloat16(0.f);
    for (int i = n + threadIdx.x; i < fend; i += blockDim.x) { P_h[po + i] = zz; P_l[po + i] = zz; }
}

// vectorized silu*mul for dense MLP
__global__ void silumul_mlp_k() {
    long idx = ((long)blockIdx.x * blockDim.x + threadIdx.x) * 8;
    if (idx >= (long)T * FF) return;
    long r = idx / FF;
    int c = (int)(idx % FF);
    const float* gr = g_gu + r * (2 * FF);
    unsigned short hi[8], lo[8];
    #pragma unroll
    for (int j = 0; j < 8; j++) {
        float gv = gr[c + j], u = gr[FF + c + j];
        split2(gv / (1.f + expf(-gv)) * u, hi[j], lo[j]);
    }
    *(uint4*)(ff_h + idx) = *(uint4*)hi;
    *(uint4*)(ff_l + idx) = *(uint4*)lo;
}

// vectorized silu*mul for MoE
__global__ void silumul2_k() {
    long idx = ((long)blockIdx.x * blockDim.x + threadIdx.x) * 8;
    if (idx >= (long)2 * T * EF) return;
    long r = idx / EF;
    int c = (int)(idx % EF);
    const float* gr = g_mgu + r * (2 * EF);
    unsigned short hi[8], lo[8];
    #pragma unroll
    for (int j = 0; j < 8; j++) {
        float gv = gr[c + j], u = gr[EF + c + j];
        split2(gv / (1.f + expf(-gv)) * u, hi[j], lo[j]);
    }
    *(uint4*)(mh_h + idx) = *(uint4*)hi;
    *(uint4*)(mh_l + idx) = *(uint4*)lo;
}

// ---------------- MoE routing ----------------
__global__ void top2_k() {
    int t = blockIdx.x * blockDim.x + threadIdx.x;
    if (t >= T) return;
    const float* l = g_logits + (size_t)t * E;
    int i0 = 0;
    float v0 = l[0];
    for (int i = 1; i < E; i++)
        if (l[i] > v0) { v0 = l[i]; i0 = i; }
    int i1 = -1;
    float v1 = -1e30f;
    for (int i = 0; i < E; i++)
        if (i != i0 && l[i] > v1) { v1 = l[i]; i1 = i; }
    float e = expf(v1 - v0);
    g_expid[2 * t] = i0;
    g_expid[2 * t + 1] = i1;
    g_gate[2 * t] = 1.f / (1.f + e);
    g_gate[2 * t + 1] = e / (1.f + e);
}
__global__ void zero_cnt_k() { if (threadIdx.x < E) g_cnt[threadIdx.x] = 0; }
__global__ void count_k() {
    int p = blockIdx.x * blockDim.x + threadIdx.x;
    if (p < 2 * T) g_slot[p] = atomicAdd(&g_cnt[g_expid[p]], 1);
}
__global__ void scan_k() {
    if (threadIdx.x == 0) {
        int o = 0;
        for (int e = 0; e < E; e++) { g_off[e] = o; o += g_cnt[e]; }
    }
}
__global__ void gather_k() {
    int p = blockIdx.x;
    int row = g_off[g_expid[p]] + g_slot[p];
    if (threadIdx.x == 0) g_rowOf[p] = row;
    size_t src = (size_t)(p >> 1) * D, dst = (size_t)row * D;
    for (int i = threadIdx.x; i < D; i += blockDim.x) {
        mx_h[dst + i] = x_h[src + i];
        mx_l[dst + i] = x_l[src + i];
    }
}
__global__ void moecomb_k() {
    long idx = (long)blockIdx.x * blockDim.x + threadIdx.x;
    if (idx >= (long)T * D) return;
    long t = idx / D;
    int d = (int)(idx % D);
    g_moe[idx] = g_gate[2 * t] * g_my[(size_t)g_rowOf[2 * t] * D + d] +
                 g_gate[2 * t + 1] * g_my[(size_t)g_rowOf[2 * t + 1] * D + d];
}
__global__ void add_k(const float* __restrict__ a, const float* __restrict__ b,
                      float* __restrict__ o, long n) {
    long idx = (long)blockIdx.x * blockDim.x + threadIdx.x;
    if (idx < n) o[idx] = a[idx] + b[idx];
}

// ---------------- host side ----------------
static void bgemm_f(const bf16* Ah, const bf16* Al, const bf16* Bh, const bf16* Bl,
                    float* C, int M, int N, int K, int lda, int ldb, int ldc,
                    long sA, long sB, long sC, int batch, int cskip) {
    dim3 g((N + BN - 1) / BN, (M + BM - 1) / BM, batch);
    bgemm_k<<<g, 256, GSMEM>>>(Ah, Al, Bh, Bl, C, M, N, K, lda, ldb, ldc, sA, sB, sC, cskip);
}
static void sgemm_split(const bf16* Ah, const bf16* Al, const bf16* Bh, const bf16* Bl,
                        float* C, int M, int N, int K, int lda, int ldb, int ldc) {
    cudaMemsetAsync(C, 0, (size_t)M * ldc * sizeof(float));
    int mt = (M + BM - 1) / BM, nt = (N + BN - 1) / BN;
    long U = (long)mt * nt * (K / BK);
    int G = U < GPERS ? (int)U : GPERS;
    sgemm_split_k<<<G, 256, GSMEM>>>(Ah, Al, Bh, Bl, C, M, N, K, lda, ldb, ldc, mt, nt);
}
static void mgemm_split(const bf16* Ah, const bf16* Al, const bf16* Bh, const bf16* Bl,
                        long sB, float* C, int N, int K, int lda, int ldc, size_t csize) {
    cudaMemsetAsync(C, 0, csize);
    mgemm_split_k<<<GPERS, 256, GSMEM>>>(Ah, Al, Bh, Bl, sB, C, N, K, lda, ldc);
}

extern "C" void kernel_launch(void* const* d_in, const int* in_sizes, int n_in,
                              void* d_out, int out_size) {
    const float* hidden = (const float*)d_in[0];
    const int* pos = (const int*)d_in[1];
    const float* ln_in = (const float*)d_in[2];
    const float* ln_post = (const float*)d_in[3];
    const float* wqa = (const float*)d_in[4];
    const float* qnorm = (const float*)d_in[5];
    const float* wqb = (const float*)d_in[6];
    const float* wkva = (const float*)d_in[7];
    const float* kvnorm = (const float*)d_in[8];
    const float* wkvb = (const float*)d_in[9];
    const float* wo = (const float*)d_in[10];
    const float* wgu = (const float*)d_in[11];
    const float* wd = (const float*)d_in[12];
    const float* rw = (const float*)d_in[13];
    const float* mwg = (const float*)d_in[14];
    const float* mwu = (const float*)d_in[15];
    const float* mwd = (const float*)d_in[16];
    float* out = (float*)d_out;

    cudaFuncSetAttribute(bgemm_k, cudaFuncAttributeMaxDynamicSharedMemorySize, GSMEM);
    cudaFuncSetAttribute(sgemm_split_k, cudaFuncAttributeMaxDynamicSharedMemorySize, GSMEM);
    cudaFuncSetAttribute(mgemm_split_k, cudaFuncAttributeMaxDynamicSharedMemorySize, GSMEM);
    cudaFuncSetAttribute(av_split_k, cudaFuncAttributeMaxDynamicSharedMemorySize, GSMEM);

    void* p;
#define SYMF(name) cudaGetSymbolAddress(&p, name); float* p_##name = (float*)p;
#define SYMB(name) cudaGetSymbolAddress(&p, name); bf16* p_##name = (bf16*)p;
#define SYMI(name) cudaGetSymbolAddress(&p, name); int* p_##name = (int*)p;
    SYMF(g_res) SYMF(g_h) SYMF(g_moe) SYMF(g_qkv) SYMF(g_q) SYMF(g_kvb) SYMF(g_attno)
    SYMF(g_scores) SYMF(g_gu) SYMF(g_mgu) SYMF(g_my) SYMF(g_logits)
    SYMB(x_h) SYMB(x_l) SYMB(qln_h) SYMB(qln_l) SYMB(qq_h) SYMB(qq_l)
    SYMB(kvcn_h) SYMB(kvcn_l) SYMB(kh_h) SYMB(kh_l) SYMB(vt_h) SYMB(vt_l)
    SYMB(P_h) SYMB(P_l) SYMB(ao_h) SYMB(ao_l) SYMB(ff_h) SYMB(ff_l)
    SYMB(mx_h) SYMB(mx_l) SYMB(mh_h) SYMB(mh_l)
    SYMB(wqkvT_h) SYMB(wqkvT_l) SYMB(wqbT_h) SYMB(wqbT_l)
    SYMB(wkvbT_h) SYMB(wkvbT_l) SYMB(woT_h) SYMB(woT_l) SYMB(wguT_h) SYMB(wguT_l)
    SYMB(wdT_h) SYMB(wdT_l) SYMB(rwT_h) SYMB(rwT_l)
    SYMB(mwguT_h) SYMB(mwguT_l) SYMB(mwdT_h) SYMB(mwdT_l)
    SYMI(g_cnt) SYMI(g_off)
#undef SYMF
#undef SYMB
#undef SYMI

    long zqkv = (long)NQKV * D;

    // kernels: rms(0), wtrans(1), wtrans(2), sgemm_split(3) <- ncu target
    rms_hl_k<<<T, 256>>>(hidden, ln_in, p_x_h, p_x_l, D, D, D);
    wtrans_k<<<dim3(QL / 32, D / 64, 2), 256>>>(wqa, p_wqkvT_h, p_wqkvT_l, D, QL, zqkv);
    wtrans_k<<<dim3(KVD / 32, D / 64, 2), 256>>>(wkva, p_wqkvT_h + (size_t)QL * D,
                                                 p_wqkvT_l + (size_t)QL * D, D, KVD, zqkv);
    sgemm_split(p_x_h, p_x_l, p_wqkvT_h, p_wqkvT_l, p_g_qkv, T, NQKV, D, D, D, NQKV);
    // remaining weight preps
    wtrans_k<<<dim3(QTOT / 32, QL / 64, 2), 256>>>(wqb, p_wqbT_h, p_wqbT_l, QL, QTOT,
                                                   (long)QTOT * QL);
    wtrans_k<<<dim3(KVBD / 32, KL / 64, 2), 256>>>(wkvb, p_wkvbT_h, p_wkvbT_l, KL, KVBD,
                                                   (long)KVBD * KL);
    wtrans_k<<<dim3(D / 32, HDV / 64, 2), 256>>>(wo, p_woT_h, p_woT_l, HDV, D, (long)D * D);
    wtrans_k<<<dim3(2 * FF / 32, D / 64, 2), 256>>>(wgu, p_wguT_h, p_wguT_l, D, 2 * FF,
                                                    (long)2 * FF * D);
    wtrans_k<<<dim3(D / 32, FF / 64, 2), 256>>>(wd, p_wdT_h, p_wdT_l, FF, D, (long)D * FF);
    wtrans_k<<<dim3(E / 32, D / 64, 1), 256>>>(rw, p_rwT_h, p_rwT_l, D, E, 0);
    wtrans_k<<<dim3(EF / 32, D / 64, E), 256>>>(mwg, p_mwguT_h, p_mwguT_l, D, EF,
                                                (long)2 * EF * D);
    wtrans_k<<<dim3(EF / 32, D / 64, E), 256>>>(mwu, p_mwguT_h + (size_t)EF * D,
                                                p_mwguT_l + (size_t)EF * D, D, EF,
                                                (long)2 * EF * D);
    wtrans_k<<<dim3(D / 32, EF / 64, E), 256>>>(mwd, p_mwdT_h, p_mwdT_l, EF, D, (long)D * EF);

    auto mla = [&](int l, float* outbuf, bool qkv_done) {
        if (!qkv_done)
            sgemm_split(p_x_h, p_x_l, p_wqkvT_h + (size_t)l * zqkv, p_wqkvT_l + (size_t)l * zqkv,
                        p_g_qkv, T, NQKV, D, D, D, NQKV);
        rms_hl_k<<<T, 256>>>(p_g_qkv, qnorm + (size_t)l * QL, p_qln_h, p_qln_l, QL, NQKV, QL);
        sgemm_split(p_qln_h, p_qln_l, p_wqbT_h + (size_t)l * QTOT * QL,
                    p_wqbT_l + (size_t)l * QTOT * QL, p_g_q, T, QTOT, QL, QL, QL, QTOT);
        rms_hl_k<<<T, 256>>>(p_g_qkv + QL, kvnorm + (size_t)l * KL, p_kvcn_h, p_kvcn_l,
                             KL, NQKV, KL);
        sgemm_split(p_kvcn_h, p_kvcn_l, p_wkvbT_h + (size_t)l * KVBD * KL,
                    p_wkvbT_l + (size_t)l * KVBD * KL, p_g_kvb, T, KVBD, KL, KL, KL, KVBD);
        rope_cvt_q_k<<<T, 256>>>(p_g_q, pos);
        build_kh_k<<<T, 256>>>(pos);
        build_vt_k<<<dim3(T / 64, H), 256>>>();
        bgemm_f(p_qq_h, p_qq_l, p_kh_h, p_kh_l, p_g_scores, T, T, QD,
                QTOT, QTOT, T, QD, QD, (long)T * T, H, 1);
        softmaxP_k<<<dim3(T, H), 256>>>();
        cudaMemsetAsync(p_g_attno, 0, (size_t)T * HDV * sizeof(float));
        av_split_k<<<GPERS, 256, GSMEM>>>(p_P_h, p_P_l, p_vt_h, p_vt_l, p_g_attno);
        cvt_hl_k<<<(int)(((long)T * HDV / 8 + 255) / 256), 256>>>(p_g_attno, p_ao_h, p_ao_l,
                                                                  (long)T * HDV);
        sgemm_split(p_ao_h, p_ao_l, p_woT_h + (size_t)l * D * D, p_woT_l + (size_t)l * D * D,
                    outbuf, T, D, HDV, HDV, HDV, D);
    };

    auto mlp = [&](int l, float* outbuf) {
        sgemm_split(p_x_h, p_x_l, p_wguT_h + (size_t)l * 2 * FF * D,
                    p_wguT_l + (size_t)l * 2 * FF * D, p_g_gu, T, 2 * FF, D, D, D, 2 * FF);
        silumul_mlp_k<<<(int)(((long)T * FF / 8 + 255) / 256), 256>>>();
        sgemm_split(p_ff_h, p_ff_l, p_wdT_h + (size_t)l * D * FF, p_wdT_l + (size_t)l * D * FF,
                    outbuf, T, D, FF, FF, FF, D);
    };

    // ================= forward =================
    mla(0, p_g_h, true);
    addnorm_hl_k<<<T, 256>>>(p_g_h, hidden, ln_post, p_g_res, p_x_h, p_x_l);

    // ---- MoE ----
    sgemm_split(p_x_h, p_x_l, p_rwT_h, p_rwT_l, p_g_logits, T, E, D, D, D, E);
    top2_k<<<(T + 255) / 256, 256>>>();
    zero_cnt_k<<<1, 32>>>();
    count_k<<<(2 * T + 255) / 256, 256>>>();
    scan_k<<<1, 32>>>();
    gather_k<<<2 * T, 256>>>();
    mgemm_split(p_mx_h, p_mx_l, p_mwguT_h, p_mwguT_l, (long)2 * EF * D,
                p_g_mgu, 2 * EF, D, D, 2 * EF, (size_t)2 * T * 2 * EF * sizeof(float));
    silumul2_k<<<(int)(((long)2 * T * EF / 8 + 255) / 256), 256>>>();
    mgemm_split(p_mh_h, p_mh_l, p_mwdT_h, p_mwdT_l, (long)D * EF,
                p_g_my, D, EF, EF, D, (size_t)2 * T * D * sizeof(float));
    moecomb_k<<<(int)(((long)T * D + 255) / 256), 256>>>();

    // ---- MLP layer 0 ----
    mlp(0, p_g_h);
    addnorm_hl_k<<<T, 256>>>(p_g_h, p_g_res, ln_in + D, p_g_res, p_x_h, p_x_l);

    // ---- layer 1 ----
    mla(1, p_g_h, false);
    addnorm_hl_k<<<T, 256>>>(p_g_h, p_g_res, ln_post + D, p_g_res, p_x_h, p_x_l);
    mlp(1, p_g_h);

    add_k<<<(int)(((long)T * D + 255) / 256), 256>>>(p_g_h, p_g_moe, out, (long)T * D);
}